// round 1
// baseline (speedup 1.0000x reference)
#include <cuda_runtime.h>
#include <math.h>

#define SEQ 2048
#define DM 512
#define NH 8
#define DH 64
#define DFF 2048
#define BATCH 4
#define ROWS (BATCH * SEQ)   // 8192

// Scratch (device globals — no allocation allowed)
__device__ float g_qkv[(size_t)ROWS * 3 * DM];   // 48 MB
__device__ float g_o[(size_t)ROWS * DM];         // 16 MB
__device__ float g_h[(size_t)ROWS * DFF];        // 64 MB

// ---------------------------------------------------------------------------
// GEMM: Y[M,N] = X[M,K] @ W[N,K]^T + bias[N]  (optional ReLU)
// 64x64 tile, BK=16, 256 threads, 4x4 accum per thread.
// Requires M%64==0, N%64==0, K%16==0 (true for all shapes here).
// ---------------------------------------------------------------------------
template<int RELU>
__global__ void gemm64(const float* __restrict__ X, const float* __restrict__ W,
                       const float* __restrict__ bias, float* __restrict__ Y,
                       int M, int N, int K) {
    __shared__ float Xs[16][65];
    __shared__ float Ws[16][65];
    const int tx = threadIdx.x, ty = threadIdx.y;
    const int tid = ty * 16 + tx;
    const int m0 = blockIdx.y * 64, n0 = blockIdx.x * 64;

    float acc[4][4] = {};

    const int lm = tid >> 2;          // 0..63 : tile row
    const int lk = (tid & 3) * 4;     // 0,4,8,12 : k offset (float4)
    const float* Xg = X + (long)(m0 + lm) * K + lk;
    const float* Wg = W + (long)(n0 + lm) * K + lk;

    for (int k0 = 0; k0 < K; k0 += 16) {
        float4 xv = *(const float4*)(Xg + k0);
        float4 wv = *(const float4*)(Wg + k0);
        Xs[lk + 0][lm] = xv.x; Xs[lk + 1][lm] = xv.y;
        Xs[lk + 2][lm] = xv.z; Xs[lk + 3][lm] = xv.w;
        Ws[lk + 0][lm] = wv.x; Ws[lk + 1][lm] = wv.y;
        Ws[lk + 2][lm] = wv.z; Ws[lk + 3][lm] = wv.w;
        __syncthreads();
        #pragma unroll
        for (int k = 0; k < 16; k++) {
            float a[4], b[4];
            #pragma unroll
            for (int i = 0; i < 4; i++) a[i] = Xs[k][ty * 4 + i];
            #pragma unroll
            for (int j = 0; j < 4; j++) b[j] = Ws[k][tx * 4 + j];
            #pragma unroll
            for (int i = 0; i < 4; i++)
                #pragma unroll
                for (int j = 0; j < 4; j++)
                    acc[i][j] += a[i] * b[j];
        }
        __syncthreads();
    }

    #pragma unroll
    for (int i = 0; i < 4; i++) {
        const int m = m0 + ty * 4 + i;
        #pragma unroll
        for (int j = 0; j < 4; j++) {
            const int n = n0 + tx * 4 + j;
            float v = acc[i][j] + bias[n];
            if (RELU) v = fmaxf(v, 0.f);
            Y[(long)m * N + n] = v;
        }
    }
}

// ---------------------------------------------------------------------------
// Log-sparse attention. One block (64 threads) per (b, h, query i).
// Allowed keys: j with d=i-j in [0,64], plus d in {128,256,512,1024} if d<=i.
// qkv layout: [B*S, 3*DM]; q cols [h*64, h*64+64), k cols [512+h*64,...),
// v cols [1024+h*64,...). Output o: [B*S, DM].
// ---------------------------------------------------------------------------
__global__ void attn_kernel(const float* __restrict__ qkv, float* __restrict__ o) {
    const int idx = blockIdx.x;
    const int i = idx & (SEQ - 1);
    const int h = (idx >> 11) & (NH - 1);
    const int b = idx >> 14;
    const int t = threadIdx.x;   // 0..63

    __shared__ float qs[DH];
    __shared__ float sc[72];
    __shared__ int   kj[72];
    __shared__ float red[64];

    const long rowq = (long)(b * SEQ + i);
    qs[t] = qkv[rowq * (3 * DM) + h * DH + t];

    const int lo = (i > 64) ? (i - 64) : 0;
    const int nwin = i - lo + 1;                                  // <= 65
    const int ne = (i >= 128) + (i >= 256) + (i >= 512) + (i >= 1024);
    const int n = nwin + ne;                                      // <= 69
    __syncthreads();

    // scores
    float pmax = -INFINITY;
    for (int kk = t; kk < n; kk += 64) {
        const int j = (kk < nwin) ? (lo + kk) : (i - (128 << (kk - nwin)));
        kj[kk] = j;
        const float* kp = qkv + (long)(b * SEQ + j) * (3 * DM) + DM + h * DH;
        float dot = 0.f;
        #pragma unroll
        for (int d = 0; d < DH; d++) dot += qs[d] * kp[d];
        dot *= 0.125f;   // 1/sqrt(64)
        sc[kk] = dot;
        pmax = fmaxf(pmax, dot);
    }
    red[t] = pmax; __syncthreads();
    #pragma unroll
    for (int s2 = 32; s2 > 0; s2 >>= 1) {
        if (t < s2) red[t] = fmaxf(red[t], red[t + s2]);
        __syncthreads();
    }
    const float mx = red[0];
    __syncthreads();

    // exp + sum
    float psum = 0.f;
    for (int kk = t; kk < n; kk += 64) {
        const float e = expf(sc[kk] - mx);
        sc[kk] = e;
        psum += e;
    }
    red[t] = psum; __syncthreads();
    #pragma unroll
    for (int s2 = 32; s2 > 0; s2 >>= 1) {
        if (t < s2) red[t] += red[t + s2];
        __syncthreads();
    }
    const float inv = 1.f / red[0];
    __syncthreads();

    // weighted sum of V: thread t owns dim t (coalesced across block)
    float acc = 0.f;
    for (int kk = 0; kk < n; kk++) {
        const float* vp = qkv + (long)(b * SEQ + kj[kk]) * (3 * DM) + 2 * DM + h * DH;
        acc += sc[kk] * vp[t];
    }
    o[rowq * DM + h * DH + t] = acc * inv;
}

// ---------------------------------------------------------------------------
// x = LayerNorm(x + o) * scale + bias, in place over x. One block per row.
// ---------------------------------------------------------------------------
__global__ void add_ln_kernel(float* __restrict__ x, const float* __restrict__ o,
                              const float* __restrict__ sc, const float* __restrict__ bi) {
    const int row = blockIdx.x;
    const int t = threadIdx.x;    // 256
    const long base = (long)row * DM;

    const float v0 = x[base + t]       + o[base + t];
    const float v1 = x[base + t + 256] + o[base + t + 256];
    float s = v0 + v1, sq = v0 * v0 + v1 * v1;
    #pragma unroll
    for (int off = 16; off; off >>= 1) {
        s  += __shfl_xor_sync(0xffffffffu, s, off);
        sq += __shfl_xor_sync(0xffffffffu, sq, off);
    }
    __shared__ float ss[8], sqs[8];
    __shared__ float mean_s, rstd_s;
    const int w = t >> 5;
    if ((t & 31) == 0) { ss[w] = s; sqs[w] = sq; }
    __syncthreads();
    if (t == 0) {
        float s1 = 0.f, s2 = 0.f;
        #pragma unroll
        for (int k = 0; k < 8; k++) { s1 += ss[k]; s2 += sqs[k]; }
        const float m = s1 / (float)DM;
        const float var = s2 / (float)DM - m * m;
        mean_s = m;
        rstd_s = rsqrtf(var + 1e-5f);
    }
    __syncthreads();
    const float m = mean_s, r = rstd_s;
    x[base + t]       = (v0 - m) * r * sc[t]       + bi[t];
    x[base + t + 256] = (v1 - m) * r * sc[t + 256] + bi[t + 256];
}

// ---------------------------------------------------------------------------
extern "C" void kernel_launch(void* const* d_in, const int* in_sizes, int n_in,
                              void* d_out, int out_size) {
    const float* src   = (const float*)d_in[0];
    // d_in[1] = mask (ignored; computed analytically)
    const float* qkv_w = (const float*)d_in[2];
    const float* qkv_b = (const float*)d_in[3];
    const float* out_w = (const float*)d_in[4];
    const float* out_b = (const float*)d_in[5];
    const float* ln1_s = (const float*)d_in[6];
    const float* ln1_b = (const float*)d_in[7];
    const float* w1    = (const float*)d_in[8];
    const float* b1    = (const float*)d_in[9];
    const float* w2    = (const float*)d_in[10];
    const float* b2    = (const float*)d_in[11];
    const float* ln2_s = (const float*)d_in[12];
    const float* ln2_b = (const float*)d_in[13];

    float* x = (float*)d_out;   // running activation buffer lives in d_out

    float *qkv, *obuf, *hbuf;
    cudaGetSymbolAddress((void**)&qkv,  g_qkv);
    cudaGetSymbolAddress((void**)&obuf, g_o);
    cudaGetSymbolAddress((void**)&hbuf, g_h);

    cudaMemcpyAsync(x, src, sizeof(float) * (size_t)ROWS * DM,
                    cudaMemcpyDeviceToDevice);

    const dim3 thr(16, 16);
    for (int l = 0; l < 2; l++) {
        // QKV projection: [8192,512] @ [1536,512]^T -> [8192,1536]
        gemm64<0><<<dim3(3 * DM / 64, ROWS / 64), thr>>>(
            x, qkv_w + (long)l * 3 * DM * DM, qkv_b + (long)l * 3 * DM,
            qkv, ROWS, 3 * DM, DM);

        // Log-sparse attention
        attn_kernel<<<BATCH * NH * SEQ, 64>>>(qkv, obuf);

        // Output projection -> hbuf (reused as temp)
        gemm64<0><<<dim3(DM / 64, ROWS / 64), thr>>>(
            obuf, out_w + (long)l * DM * DM, out_b + (long)l * DM,
            hbuf, ROWS, DM, DM);

        // x = LN(x + attn_proj)
        add_ln_kernel<<<ROWS, 256>>>(x, hbuf, ln1_s + l * DM, ln1_b + l * DM);

        // FFN up + ReLU: [8192,512] -> [8192,2048]
        gemm64<1><<<dim3(DFF / 64, ROWS / 64), thr>>>(
            x, w1 + (long)l * DFF * DM, b1 + (long)l * DFF,
            hbuf, ROWS, DFF, DM);

        // FFN down: [8192,2048] -> [8192,512]
        gemm64<0><<<dim3(DM / 64, ROWS / 64), thr>>>(
            hbuf, w2 + (long)l * DM * DFF, b2 + (long)l * DM,
            obuf, ROWS, DM, DFF);

        // x = LN(x + ffn)
        add_ln_kernel<<<ROWS, 256>>>(x, obuf, ln2_s + l * DM, ln2_b + l * DM);
    }
}

// round 2
// speedup vs baseline: 1.4292x; 1.4292x over previous
#include <cuda_runtime.h>
#include <math.h>
#include <stdint.h>

#define SEQ 2048
#define DM 512
#define NH 8
#define DH 64
#define DFF 2048
#define BATCH 4
#define ROWS (BATCH * SEQ)   // 8192

// Scratch (device globals - no allocation allowed)
__device__ float g_qkv[(size_t)ROWS * 3 * DM];
__device__ float g_o[(size_t)ROWS * DM];
__device__ float g_h[(size_t)ROWS * DFF];

// ---------------------------------------------------------------------------
// Tensor-core GEMM (tf32 x3 for fp32 accuracy)
// Y[M,N] = X[M,K] @ W[N,K]^T + bias  (optional ReLU)
// 128x128 block tile, BK=32, 256 threads (8 warps: 2m x 4n, 64x32 each).
// ---------------------------------------------------------------------------
#define TPAD 36                      // floats per smem row (16B-aligned, conflict-free ldmatrix)
#define TILE_F (128 * TPAD)          // 4608 floats per tile
#define BUF_B (2 * TILE_F * 4)       // bytes per buffer (A+B) = 36864
#define SMEM_BYTES (2 * BUF_B)       // 73728

__device__ __forceinline__ void cp16(uint32_t saddr, const void* g) {
    asm volatile("cp.async.cg.shared.global [%0], [%1], 16;" :: "r"(saddr), "l"(g));
}
__device__ __forceinline__ void ldsm_x4(uint32_t* r, uint32_t a) {
    asm volatile("ldmatrix.sync.aligned.m8n8.x4.shared.b16 {%0,%1,%2,%3}, [%4];"
                 : "=r"(r[0]), "=r"(r[1]), "=r"(r[2]), "=r"(r[3]) : "r"(a));
}
__device__ __forceinline__ void ldsm_x2(uint32_t* r, uint32_t a) {
    asm volatile("ldmatrix.sync.aligned.m8n8.x2.shared.b16 {%0,%1}, [%2];"
                 : "=r"(r[0]), "=r"(r[1]) : "r"(a));
}
__device__ __forceinline__ void split_tf32(uint32_t raw, uint32_t& hi, uint32_t& lo) {
    float f = __uint_as_float(raw);
    asm("cvt.rna.tf32.f32 %0, %1;" : "=r"(hi) : "f"(f));
    float l = f - __uint_as_float(hi);
    asm("cvt.rna.tf32.f32 %0, %1;" : "=r"(lo) : "f"(l));
}
__device__ __forceinline__ void mma_tf32(float* d, const uint32_t* a, const uint32_t* b) {
    asm volatile("mma.sync.aligned.m16n8k8.row.col.f32.tf32.tf32.f32 "
                 "{%0,%1,%2,%3}, {%4,%5,%6,%7}, {%8,%9}, {%0,%1,%2,%3};"
                 : "+f"(d[0]), "+f"(d[1]), "+f"(d[2]), "+f"(d[3])
                 : "r"(a[0]), "r"(a[1]), "r"(a[2]), "r"(a[3]), "r"(b[0]), "r"(b[1]));
}

template<int RELU>
__global__ __launch_bounds__(256, 1)
void gemm_tc(const float* __restrict__ X, const float* __restrict__ W,
             const float* __restrict__ bias, float* __restrict__ Y,
             int M, int N, int K) {
    extern __shared__ float sm[];
    const uint32_t smem_u32 = (uint32_t)__cvta_generic_to_shared(sm);

    const int tid = threadIdx.x;
    const int lane = tid & 31, warp = tid >> 5;
    const int wm = warp & 1, wn = warp >> 1;
    const int m0 = blockIdx.y * 128, n0 = blockIdx.x * 128;

    // ldmatrix per-lane offsets
    const int a_m = lane & 15;
    const int a_k = (lane >> 4) << 2;
    const int l16 = lane & 15;
    const int b_n = l16 & 7;
    const int b_k = (l16 >> 3) << 2;

    float acc[4][4][4] = {};

    const int KT = K >> 5;

    // prologue: load tile 0 into buf 0
    #pragma unroll
    for (int r = 0; r < 4; r++) {
        const int e = r * 256 + tid;
        const int row = e >> 3, c4 = (e & 7) << 2;
        const uint32_t so = (uint32_t)((row * TPAD + c4) << 2);
        cp16(smem_u32 + so, X + (size_t)(m0 + row) * K + c4);
        cp16(smem_u32 + (TILE_F << 2) + so, W + (size_t)(n0 + row) * K + c4);
    }
    asm volatile("cp.async.commit_group;");

    int buf = 0;
    for (int kt = 0; kt < KT; kt++) {
        asm volatile("cp.async.wait_group 0;");
        __syncthreads();

        if (kt + 1 < KT) {
            const int k0 = (kt + 1) << 5;
            const uint32_t sbase = smem_u32 + (buf ^ 1) * BUF_B;
            #pragma unroll
            for (int r = 0; r < 4; r++) {
                const int e = r * 256 + tid;
                const int row = e >> 3, c4 = (e & 7) << 2;
                const uint32_t so = (uint32_t)((row * TPAD + c4) << 2);
                cp16(sbase + so, X + (size_t)(m0 + row) * K + k0 + c4);
                cp16(sbase + (TILE_F << 2) + so, W + (size_t)(n0 + row) * K + k0 + c4);
            }
            asm volatile("cp.async.commit_group;");
        }

        const uint32_t Abase = smem_u32 + buf * BUF_B +
                               (uint32_t)(((wm * 64 + a_m) * TPAD + a_k) << 2);
        const uint32_t Bbase = smem_u32 + buf * BUF_B + (TILE_F << 2) +
                               (uint32_t)(((wn * 32 + b_n) * TPAD + b_k) << 2);

        #pragma unroll
        for (int ks = 0; ks < 4; ks++) {
            uint32_t ah[4][4], al[4][4], bh[4][2], bl[4][2];
            #pragma unroll
            for (int i = 0; i < 4; i++) {
                uint32_t raw[4];
                ldsm_x4(raw, Abase + (uint32_t)(((i * 16 * TPAD) + ks * 8) << 2));
                #pragma unroll
                for (int r = 0; r < 4; r++) split_tf32(raw[r], ah[i][r], al[i][r]);
            }
            #pragma unroll
            for (int j = 0; j < 4; j++) {
                uint32_t raw[2];
                ldsm_x2(raw, Bbase + (uint32_t)(((j * 8 * TPAD) + ks * 8) << 2));
                #pragma unroll
                for (int r = 0; r < 2; r++) split_tf32(raw[r], bh[j][r], bl[j][r]);
            }
            #pragma unroll
            for (int i = 0; i < 4; i++)
                #pragma unroll
                for (int j = 0; j < 4; j++) {
                    mma_tf32(acc[i][j], ah[i], bh[j]);
                    mma_tf32(acc[i][j], ah[i], bl[j]);
                    mma_tf32(acc[i][j], al[i], bh[j]);
                }
        }
        buf ^= 1;
    }

    // epilogue
    const int g = lane >> 2, tig = lane & 3;
    #pragma unroll
    for (int i = 0; i < 4; i++) {
        const int row0 = m0 + wm * 64 + i * 16 + g;
        #pragma unroll
        for (int j = 0; j < 4; j++) {
            const int col = n0 + wn * 32 + j * 8 + 2 * tig;
            const float2 bv = *(const float2*)(bias + col);
            float2 v0 = { acc[i][j][0] + bv.x, acc[i][j][1] + bv.y };
            float2 v1 = { acc[i][j][2] + bv.x, acc[i][j][3] + bv.y };
            if (RELU) {
                v0.x = fmaxf(v0.x, 0.f); v0.y = fmaxf(v0.y, 0.f);
                v1.x = fmaxf(v1.x, 0.f); v1.y = fmaxf(v1.y, 0.f);
            }
            *(float2*)(Y + (size_t)row0 * N + col) = v0;
            *(float2*)(Y + (size_t)(row0 + 8) * N + col) = v1;
        }
    }
}

// ---------------------------------------------------------------------------
// Log-sparse attention: one block (64 threads) per (b, h, query i).
// ---------------------------------------------------------------------------
__global__ void attn_kernel(const float* __restrict__ qkv, float* __restrict__ o) {
    const int idx = blockIdx.x;
    const int i = idx & (SEQ - 1);
    const int h = (idx >> 11) & (NH - 1);
    const int b = idx >> 14;
    const int t = threadIdx.x;

    __shared__ float qs[DH];
    __shared__ float sc[72];
    __shared__ int   kj[72];
    __shared__ float red[64];

    const long rowq = (long)(b * SEQ + i);
    qs[t] = qkv[rowq * (3 * DM) + h * DH + t];

    const int lo = (i > 64) ? (i - 64) : 0;
    const int nwin = i - lo + 1;
    const int ne = (i >= 128) + (i >= 256) + (i >= 512) + (i >= 1024);
    const int n = nwin + ne;
    __syncthreads();

    float pmax = -INFINITY;
    for (int kk = t; kk < n; kk += 64) {
        const int j = (kk < nwin) ? (lo + kk) : (i - (128 << (kk - nwin)));
        kj[kk] = j;
        const float* kp = qkv + (long)(b * SEQ + j) * (3 * DM) + DM + h * DH;
        float dot = 0.f;
        #pragma unroll
        for (int d = 0; d < DH; d++) dot += qs[d] * kp[d];
        dot *= 0.125f;
        sc[kk] = dot;
        pmax = fmaxf(pmax, dot);
    }
    red[t] = pmax; __syncthreads();
    #pragma unroll
    for (int s2 = 32; s2 > 0; s2 >>= 1) {
        if (t < s2) red[t] = fmaxf(red[t], red[t + s2]);
        __syncthreads();
    }
    const float mx = red[0];
    __syncthreads();

    float psum = 0.f;
    for (int kk = t; kk < n; kk += 64) {
        const float e = expf(sc[kk] - mx);
        sc[kk] = e;
        psum += e;
    }
    red[t] = psum; __syncthreads();
    #pragma unroll
    for (int s2 = 32; s2 > 0; s2 >>= 1) {
        if (t < s2) red[t] += red[t + s2];
        __syncthreads();
    }
    const float inv = 1.f / red[0];
    __syncthreads();

    float acc = 0.f;
    for (int kk = 0; kk < n; kk++) {
        const float* vp = qkv + (long)(b * SEQ + kj[kk]) * (3 * DM) + 2 * DM + h * DH;
        acc += sc[kk] * vp[t];
    }
    o[rowq * DM + h * DH + t] = acc * inv;
}

// ---------------------------------------------------------------------------
// x = LayerNorm(x + o) * scale + bias, in place over x.
// ---------------------------------------------------------------------------
__global__ void add_ln_kernel(float* __restrict__ x, const float* __restrict__ o,
                              const float* __restrict__ sc, const float* __restrict__ bi) {
    const int row = blockIdx.x;
    const int t = threadIdx.x;
    const long base = (long)row * DM;

    const float v0 = x[base + t]       + o[base + t];
    const float v1 = x[base + t + 256] + o[base + t + 256];
    float s = v0 + v1, sq = v0 * v0 + v1 * v1;
    #pragma unroll
    for (int off = 16; off; off >>= 1) {
        s  += __shfl_xor_sync(0xffffffffu, s, off);
        sq += __shfl_xor_sync(0xffffffffu, sq, off);
    }
    __shared__ float ss[8], sqs[8];
    __shared__ float mean_s, rstd_s;
    const int w = t >> 5;
    if ((t & 31) == 0) { ss[w] = s; sqs[w] = sq; }
    __syncthreads();
    if (t == 0) {
        float s1 = 0.f, s2 = 0.f;
        #pragma unroll
        for (int k = 0; k < 8; k++) { s1 += ss[k]; s2 += sqs[k]; }
        const float m = s1 / (float)DM;
        mean_s = m;
        rstd_s = rsqrtf(s2 / (float)DM - m * m + 1e-5f);
    }
    __syncthreads();
    const float m = mean_s, r = rstd_s;
    x[base + t]       = (v0 - m) * r * sc[t]       + bi[t];
    x[base + t + 256] = (v1 - m) * r * sc[t + 256] + bi[t + 256];
}

// ---------------------------------------------------------------------------
extern "C" void kernel_launch(void* const* d_in, const int* in_sizes, int n_in,
                              void* d_out, int out_size) {
    const float* src   = (const float*)d_in[0];
    const float* qkv_w = (const float*)d_in[2];
    const float* qkv_b = (const float*)d_in[3];
    const float* out_w = (const float*)d_in[4];
    const float* out_b = (const float*)d_in[5];
    const float* ln1_s = (const float*)d_in[6];
    const float* ln1_b = (const float*)d_in[7];
    const float* w1    = (const float*)d_in[8];
    const float* b1    = (const float*)d_in[9];
    const float* w2    = (const float*)d_in[10];
    const float* b2    = (const float*)d_in[11];
    const float* ln2_s = (const float*)d_in[12];
    const float* ln2_b = (const float*)d_in[13];

    float* x = (float*)d_out;

    float *qkv, *obuf, *hbuf;
    cudaGetSymbolAddress((void**)&qkv,  g_qkv);
    cudaGetSymbolAddress((void**)&obuf, g_o);
    cudaGetSymbolAddress((void**)&hbuf, g_h);

    cudaFuncSetAttribute(gemm_tc<0>, cudaFuncAttributeMaxDynamicSharedMemorySize, SMEM_BYTES);
    cudaFuncSetAttribute(gemm_tc<1>, cudaFuncAttributeMaxDynamicSharedMemorySize, SMEM_BYTES);

    cudaMemcpyAsync(x, src, sizeof(float) * (size_t)ROWS * DM,
                    cudaMemcpyDeviceToDevice);

    for (int l = 0; l < 2; l++) {
        // QKV projection: [8192,512] x [1536,512]^T
        gemm_tc<0><<<dim3(3 * DM / 128, ROWS / 128), 256, SMEM_BYTES>>>(
            x, qkv_w + (size_t)l * 3 * DM * DM, qkv_b + (size_t)l * 3 * DM,
            qkv, ROWS, 3 * DM, DM);

        attn_kernel<<<BATCH * NH * SEQ, 64>>>(qkv, obuf);

        // Output projection
        gemm_tc<0><<<dim3(DM / 128, ROWS / 128), 256, SMEM_BYTES>>>(
            obuf, out_w + (size_t)l * DM * DM, out_b + (size_t)l * DM,
            hbuf, ROWS, DM, DM);

        add_ln_kernel<<<ROWS, 256>>>(x, hbuf, ln1_s + l * DM, ln1_b + l * DM);

        // FFN up + ReLU
        gemm_tc<1><<<dim3(DFF / 128, ROWS / 128), 256, SMEM_BYTES>>>(
            x, w1 + (size_t)l * DFF * DM, b1 + (size_t)l * DFF,
            hbuf, ROWS, DFF, DM);

        // FFN down
        gemm_tc<0><<<dim3(DM / 128, ROWS / 128), 256, SMEM_BYTES>>>(
            hbuf, w2 + (size_t)l * DM * DFF, b2 + (size_t)l * DM,
            obuf, ROWS, DM, DFF);

        add_ln_kernel<<<ROWS, 256>>>(x, obuf, ln2_s + l * DM, ln2_b + l * DM);
    }
}

// round 3
// speedup vs baseline: 2.8884x; 2.0209x over previous
#include <cuda_runtime.h>
#include <cuda_bf16.h>
#include <math.h>
#include <stdint.h>

#define SEQ 2048
#define DM 512
#define NH 8
#define DH 64
#define DFF 2048
#define BATCH 4
#define ROWS (BATCH * SEQ)   // 8192

// Scratch (device globals - no allocation allowed)
__device__ float g_qkv[(size_t)ROWS * 3 * DM];
__device__ float g_o[(size_t)ROWS * DM];
__device__ float g_h[(size_t)ROWS * DFF];

// ---------------------------------------------------------------------------
// Tensor-core GEMM: bf16 2-way split, 3 MMAs (hi*hi + hi*lo + lo*hi).
// Y[M,N] = X[M,K] @ W[N,K]^T + bias  (optional ReLU)
// 128x128 block tile, BK=32, 256 threads (8 warps: 2m x 4n, 64x32 each).
// ---------------------------------------------------------------------------
#define TPAD 36
#define TILE_F (128 * TPAD)
#define BUF_B (2 * TILE_F * 4)
#define SMEM_BYTES (2 * BUF_B)

__device__ __forceinline__ void cp16(uint32_t saddr, const void* g) {
    asm volatile("cp.async.cg.shared.global [%0], [%1], 16;" :: "r"(saddr), "l"(g));
}
__device__ __forceinline__ void split2(float2 f, uint32_t& hi, uint32_t& lo) {
    __nv_bfloat162 h = __floats2bfloat162_rn(f.x, f.y);
    float rx = f.x - __bfloat162float(h.x);
    float ry = f.y - __bfloat162float(h.y);
    __nv_bfloat162 l = __floats2bfloat162_rn(rx, ry);
    hi = *(uint32_t*)&h;
    lo = *(uint32_t*)&l;
}
__device__ __forceinline__ void mma_bf16(float* d, const uint32_t* a, const uint32_t* b) {
    asm volatile("mma.sync.aligned.m16n8k16.row.col.f32.bf16.bf16.f32 "
                 "{%0,%1,%2,%3}, {%4,%5,%6,%7}, {%8,%9}, {%0,%1,%2,%3};"
                 : "+f"(d[0]), "+f"(d[1]), "+f"(d[2]), "+f"(d[3])
                 : "r"(a[0]), "r"(a[1]), "r"(a[2]), "r"(a[3]), "r"(b[0]), "r"(b[1]));
}

template<int RELU>
__global__ __launch_bounds__(256, 1)
void gemm_tc(const float* __restrict__ X, const float* __restrict__ W,
             const float* __restrict__ bias, float* __restrict__ Y,
             int M, int N, int K) {
    extern __shared__ float sm[];
    const uint32_t smem_u32 = (uint32_t)__cvta_generic_to_shared(sm);

    const int tid = threadIdx.x;
    const int lane = tid & 31, warp = tid >> 5;
    const int wm = warp & 1, wn = warp >> 1;
    const int g = lane >> 2, tig = lane & 3;
    const int m0 = blockIdx.y * 128, n0 = blockIdx.x * 128;

    float acc[4][4][4] = {};
    const int KT = K >> 5;

    // prologue: tile 0 -> buf 0
    #pragma unroll
    for (int r = 0; r < 4; r++) {
        const int e = r * 256 + tid;
        const int row = e >> 3, c4 = (e & 7) << 2;
        const uint32_t so = (uint32_t)((row * TPAD + c4) << 2);
        cp16(smem_u32 + so, X + (size_t)(m0 + row) * K + c4);
        cp16(smem_u32 + (TILE_F << 2) + so, W + (size_t)(n0 + row) * K + c4);
    }
    asm volatile("cp.async.commit_group;");

    int buf = 0;
    for (int kt = 0; kt < KT; kt++) {
        asm volatile("cp.async.wait_group 0;");
        __syncthreads();

        if (kt + 1 < KT) {
            const int k0 = (kt + 1) << 5;
            const uint32_t sbase = smem_u32 + (buf ^ 1) * BUF_B;
            #pragma unroll
            for (int r = 0; r < 4; r++) {
                const int e = r * 256 + tid;
                const int row = e >> 3, c4 = (e & 7) << 2;
                const uint32_t so = (uint32_t)((row * TPAD + c4) << 2);
                cp16(sbase + so, X + (size_t)(m0 + row) * K + k0 + c4);
                cp16(sbase + (TILE_F << 2) + so, W + (size_t)(n0 + row) * K + k0 + c4);
            }
            asm volatile("cp.async.commit_group;");
        }

        const float* As = sm + buf * (2 * TILE_F);
        const float* Bs = As + TILE_F;

        #pragma unroll
        for (int ks = 0; ks < 2; ks++) {
            const int c = ks * 16 + 2 * tig;
            uint32_t ah[4][4], al[4][4], bh[4][2], bl[4][2];
            #pragma unroll
            for (int i = 0; i < 4; i++) {
                const int r0 = wm * 64 + i * 16 + g;
                float2 f00 = *(const float2*)&As[r0 * TPAD + c];
                float2 f10 = *(const float2*)&As[(r0 + 8) * TPAD + c];
                float2 f01 = *(const float2*)&As[r0 * TPAD + c + 8];
                float2 f11 = *(const float2*)&As[(r0 + 8) * TPAD + c + 8];
                split2(f00, ah[i][0], al[i][0]);
                split2(f10, ah[i][1], al[i][1]);
                split2(f01, ah[i][2], al[i][2]);
                split2(f11, ah[i][3], al[i][3]);
            }
            #pragma unroll
            for (int j = 0; j < 4; j++) {
                const int nr = wn * 32 + j * 8 + g;
                float2 fb0 = *(const float2*)&Bs[nr * TPAD + c];
                float2 fb1 = *(const float2*)&Bs[nr * TPAD + c + 8];
                split2(fb0, bh[j][0], bl[j][0]);
                split2(fb1, bh[j][1], bl[j][1]);
            }
            #pragma unroll
            for (int i = 0; i < 4; i++)
                #pragma unroll
                for (int j = 0; j < 4; j++) {
                    mma_bf16(acc[i][j], ah[i], bh[j]);
                    mma_bf16(acc[i][j], ah[i], bl[j]);
                    mma_bf16(acc[i][j], al[i], bh[j]);
                }
        }
        buf ^= 1;
    }

    // epilogue: d0,d1 -> (row g, cols 2tig,2tig+1); d2,d3 -> row g+8
    #pragma unroll
    for (int i = 0; i < 4; i++) {
        const int row0 = m0 + wm * 64 + i * 16 + g;
        #pragma unroll
        for (int j = 0; j < 4; j++) {
            const int col = n0 + wn * 32 + j * 8 + 2 * tig;
            const float2 bv = *(const float2*)(bias + col);
            float2 v0 = { acc[i][j][0] + bv.x, acc[i][j][1] + bv.y };
            float2 v1 = { acc[i][j][2] + bv.x, acc[i][j][3] + bv.y };
            if (RELU) {
                v0.x = fmaxf(v0.x, 0.f); v0.y = fmaxf(v0.y, 0.f);
                v1.x = fmaxf(v1.x, 0.f); v1.y = fmaxf(v1.y, 0.f);
            }
            *(float2*)(Y + (size_t)row0 * N + col) = v0;
            *(float2*)(Y + (size_t)(row0 + 8) * N + col) = v1;
        }
    }
}

// ---------------------------------------------------------------------------
// Log-sparse attention, 16 queries per block (128 threads = 4 warps).
// K/V window rows [q0-64, q0+15] staged in smem; log-strided keys from gmem.
// ---------------------------------------------------------------------------
#define QT 16
__global__ __launch_bounds__(128)
void attn_tile(const float* __restrict__ qkv, float* __restrict__ o) {
    const int q0 = blockIdx.x * QT;
    const int h = blockIdx.y, b = blockIdx.z;
    const int tid = threadIdx.x, lane = tid & 31, w = tid >> 5;

    __shared__ float Ks[80][64];
    __shared__ float Vs[80][64];
    __shared__ float Qs[QT][64];
    __shared__ float P[QT][72];

    const float* base = qkv + (size_t)(b * SEQ) * 1536;

    // stage K/V rows j = q0-64 .. q0+15 (zero if j<0; never read then)
    for (int e = tid; e < 80 * 16; e += 128) {
        const int r = e >> 4, c4 = (e & 15) << 2;
        const int j = q0 - 64 + r;
        float4 kv = {0.f, 0.f, 0.f, 0.f}, vv = {0.f, 0.f, 0.f, 0.f};
        if (j >= 0) {
            kv = *(const float4*)(base + (size_t)j * 1536 + 512 + h * 64 + c4);
            vv = *(const float4*)(base + (size_t)j * 1536 + 1024 + h * 64 + c4);
        }
        *(float4*)(&Ks[r][c4]) = kv;
        *(float4*)(&Vs[r][c4]) = vv;
    }
    for (int e = tid; e < QT * 16; e += 128) {
        const int r = e >> 4, c4 = (e & 15) << 2;
        *(float4*)(&Qs[r][c4]) =
            *(const float4*)(base + (size_t)(q0 + r) * 1536 + h * 64 + c4);
    }
    __syncthreads();

    float inv[4];
    // phase A: scores + softmax weights (each warp owns 4 queries)
    #pragma unroll
    for (int c = 0; c < 4; c++) {
        const int qi = w * 4 + c;
        const int i = q0 + qi;
        const int lo = (i > 64) ? (i - 64) : 0;
        const int nwin = i - lo + 1;
        const int ne = (i >= 128) + (i >= 256) + (i >= 512) + (i >= 1024);
        const int n = nwin + ne;
        const float qv0 = Qs[qi][lane], qv1 = Qs[qi][lane + 32];

        float mx = -INFINITY;
        for (int kk = 0; kk < n; kk++) {
            float p;
            if (kk < nwin) {
                const int r = lo + kk - (q0 - 64);
                p = qv0 * Ks[r][lane] + qv1 * Ks[r][lane + 32];
            } else {
                const int j = i - (128 << (kk - nwin));
                const float* kp = base + (size_t)j * 1536 + 512 + h * 64;
                p = qv0 * kp[lane] + qv1 * kp[lane + 32];
            }
            #pragma unroll
            for (int o2 = 16; o2; o2 >>= 1) p += __shfl_xor_sync(~0u, p, o2);
            p *= 0.125f;
            P[qi][kk] = p;
            mx = fmaxf(mx, p);
        }
        float s = 0.f;
        for (int kk = lane; kk < n; kk += 32) {
            const float e = expf(P[qi][kk] - mx);
            P[qi][kk] = e;
            s += e;
        }
        #pragma unroll
        for (int o2 = 16; o2; o2 >>= 1) s += __shfl_xor_sync(~0u, s, o2);
        inv[c] = 1.f / s;
    }
    __syncwarp();

    // phase B: weighted V sums, dims across lanes
    #pragma unroll
    for (int c = 0; c < 4; c++) {
        const int qi = w * 4 + c;
        const int i = q0 + qi;
        const int lo = (i > 64) ? (i - 64) : 0;
        const int nwin = i - lo + 1;
        const int ne = (i >= 128) + (i >= 256) + (i >= 512) + (i >= 1024);
        const int n = nwin + ne;

        float a0 = 0.f, a1 = 0.f;
        for (int kk = 0; kk < n; kk++) {
            const float p = P[qi][kk];
            if (kk < nwin) {
                const int r = lo + kk - (q0 - 64);
                a0 += p * Vs[r][lane];
                a1 += p * Vs[r][lane + 32];
            } else {
                const int j = i - (128 << (kk - nwin));
                const float* vp = base + (size_t)j * 1536 + 1024 + h * 64;
                a0 += p * vp[lane];
                a1 += p * vp[lane + 32];
            }
        }
        float* op = o + (size_t)(b * SEQ + i) * DM + h * 64;
        op[lane]      = a0 * inv[c];
        op[lane + 32] = a1 * inv[c];
    }
}

// ---------------------------------------------------------------------------
// x = LayerNorm(x + o) * scale + bias, in place over x.
// ---------------------------------------------------------------------------
__global__ void add_ln_kernel(float* __restrict__ x, const float* __restrict__ o,
                              const float* __restrict__ sc, const float* __restrict__ bi) {
    const int row = blockIdx.x;
    const int t = threadIdx.x;
    const long base = (long)row * DM;

    const float v0 = x[base + t]       + o[base + t];
    const float v1 = x[base + t + 256] + o[base + t + 256];
    float s = v0 + v1, sq = v0 * v0 + v1 * v1;
    #pragma unroll
    for (int off = 16; off; off >>= 1) {
        s  += __shfl_xor_sync(0xffffffffu, s, off);
        sq += __shfl_xor_sync(0xffffffffu, sq, off);
    }
    __shared__ float ss[8], sqs[8];
    __shared__ float mean_s, rstd_s;
    const int w = t >> 5;
    if ((t & 31) == 0) { ss[w] = s; sqs[w] = sq; }
    __syncthreads();
    if (t == 0) {
        float s1 = 0.f, s2 = 0.f;
        #pragma unroll
        for (int k = 0; k < 8; k++) { s1 += ss[k]; s2 += sqs[k]; }
        const float m = s1 / (float)DM;
        mean_s = m;
        rstd_s = rsqrtf(s2 / (float)DM - m * m + 1e-5f);
    }
    __syncthreads();
    const float m = mean_s, r = rstd_s;
    x[base + t]       = (v0 - m) * r * sc[t]       + bi[t];
    x[base + t + 256] = (v1 - m) * r * sc[t + 256] + bi[t + 256];
}

// ---------------------------------------------------------------------------
extern "C" void kernel_launch(void* const* d_in, const int* in_sizes, int n_in,
                              void* d_out, int out_size) {
    const float* src   = (const float*)d_in[0];
    const float* qkv_w = (const float*)d_in[2];
    const float* qkv_b = (const float*)d_in[3];
    const float* out_w = (const float*)d_in[4];
    const float* out_b = (const float*)d_in[5];
    const float* ln1_s = (const float*)d_in[6];
    const float* ln1_b = (const float*)d_in[7];
    const float* w1    = (const float*)d_in[8];
    const float* b1    = (const float*)d_in[9];
    const float* w2    = (const float*)d_in[10];
    const float* b2    = (const float*)d_in[11];
    const float* ln2_s = (const float*)d_in[12];
    const float* ln2_b = (const float*)d_in[13];

    float* x = (float*)d_out;

    float *qkv, *obuf, *hbuf;
    cudaGetSymbolAddress((void**)&qkv,  g_qkv);
    cudaGetSymbolAddress((void**)&obuf, g_o);
    cudaGetSymbolAddress((void**)&hbuf, g_h);

    cudaFuncSetAttribute(gemm_tc<0>, cudaFuncAttributeMaxDynamicSharedMemorySize, SMEM_BYTES);
    cudaFuncSetAttribute(gemm_tc<1>, cudaFuncAttributeMaxDynamicSharedMemorySize, SMEM_BYTES);

    cudaMemcpyAsync(x, src, sizeof(float) * (size_t)ROWS * DM,
                    cudaMemcpyDeviceToDevice);

    for (int l = 0; l < 2; l++) {
        gemm_tc<0><<<dim3(3 * DM / 128, ROWS / 128), 256, SMEM_BYTES>>>(
            x, qkv_w + (size_t)l * 3 * DM * DM, qkv_b + (size_t)l * 3 * DM,
            qkv, ROWS, 3 * DM, DM);

        attn_tile<<<dim3(SEQ / QT, NH, BATCH), 128>>>(qkv, obuf);

        gemm_tc<0><<<dim3(DM / 128, ROWS / 128), 256, SMEM_BYTES>>>(
            obuf, out_w + (size_t)l * DM * DM, out_b + (size_t)l * DM,
            hbuf, ROWS, DM, DM);

        add_ln_kernel<<<ROWS, 256>>>(x, hbuf, ln1_s + l * DM, ln1_b + l * DM);

        gemm_tc<1><<<dim3(DFF / 128, ROWS / 128), 256, SMEM_BYTES>>>(
            x, w1 + (size_t)l * DFF * DM, b1 + (size_t)l * DFF,
            hbuf, ROWS, DFF, DM);

        gemm_tc<0><<<dim3(DM / 128, ROWS / 128), 256, SMEM_BYTES>>>(
            hbuf, w2 + (size_t)l * DM * DFF, b2 + (size_t)l * DM,
            obuf, ROWS, DM, DFF);

        add_ln_kernel<<<ROWS, 256>>>(x, obuf, ln2_s + l * DM, ln2_b + l * DM);
    }
}

// round 4
// speedup vs baseline: 3.1609x; 1.0944x over previous
#include <cuda_runtime.h>
#include <cuda_bf16.h>
#include <math.h>
#include <stdint.h>

#define SEQ 2048
#define DM 512
#define NH 8
#define DH 64
#define DFF 2048
#define BATCH 4
#define ROWS (BATCH * SEQ)   // 8192

// ---------------- device scratch (no allocation allowed) -------------------
__device__ float g_qkv[(size_t)ROWS * 3 * DM];           // 48 MB fp32
__device__ float g_d[(size_t)ROWS * DM];                 // delta buffer fp32
__device__ __nv_bfloat16 g_xhi[(size_t)ROWS * DM];
__device__ __nv_bfloat16 g_xlo[(size_t)ROWS * DM];
__device__ __nv_bfloat16 g_ohi[(size_t)ROWS * DM];
__device__ __nv_bfloat16 g_olo[(size_t)ROWS * DM];
__device__ __nv_bfloat16 g_hhi[(size_t)ROWS * DFF];
__device__ __nv_bfloat16 g_hlo[(size_t)ROWS * DFF];
#define W_TOTAL 6291456   // 2*(1536*512 + 512*512 + 2048*512 + 512*2048)
__device__ __nv_bfloat16 g_whi[W_TOTAL];
__device__ __nv_bfloat16 g_wlo[W_TOTAL];
// segment offsets inside g_whi/g_wlo
#define OFF_QKV 0
#define OFF_OUT (2 * 1536 * 512)                  // 1572864
#define OFF_W1  (OFF_OUT + 2 * 512 * 512)         // 2097152
#define OFF_W2  (OFF_W1 + 2 * 2048 * 512)         // 4194304

// ---------------------------------------------------------------------------
// helpers
// ---------------------------------------------------------------------------
__device__ __forceinline__ void cp16(uint32_t saddr, const void* g) {
    asm volatile("cp.async.cg.shared.global [%0], [%1], 16;" :: "r"(saddr), "l"(g));
}
__device__ __forceinline__ void ldsm_x4(uint32_t* r, uint32_t a) {
    asm volatile("ldmatrix.sync.aligned.m8n8.x4.shared.b16 {%0,%1,%2,%3}, [%4];"
                 : "=r"(r[0]), "=r"(r[1]), "=r"(r[2]), "=r"(r[3]) : "r"(a));
}
__device__ __forceinline__ void mma_bf16(float* d, const uint32_t* a, const uint32_t* b) {
    asm volatile("mma.sync.aligned.m16n8k16.row.col.f32.bf16.bf16.f32 "
                 "{%0,%1,%2,%3}, {%4,%5,%6,%7}, {%8,%9}, {%0,%1,%2,%3};"
                 : "+f"(d[0]), "+f"(d[1]), "+f"(d[2]), "+f"(d[3])
                 : "r"(a[0]), "r"(a[1]), "r"(a[2]), "r"(a[3]), "r"(b[0]), "r"(b[1]));
}
__device__ __forceinline__ void split1(float v, __nv_bfloat16& h, __nv_bfloat16& l) {
    h = __float2bfloat16_rn(v);
    l = __float2bfloat16_rn(v - __bfloat162float(h));
}

// ---------------------------------------------------------------------------
// one-shot fp32 -> (hi, lo) bf16 split
// ---------------------------------------------------------------------------
__global__ void split_arr(const float* __restrict__ src, __nv_bfloat16* __restrict__ hi,
                          __nv_bfloat16* __restrict__ lo, int n4) {
    const int i = blockIdx.x * blockDim.x + threadIdx.x;
    if (i >= n4) return;
    const float4 v = ((const float4*)src)[i];
    __nv_bfloat162 h0 = __floats2bfloat162_rn(v.x, v.y);
    __nv_bfloat162 h1 = __floats2bfloat162_rn(v.z, v.w);
    __nv_bfloat162 l0 = __floats2bfloat162_rn(v.x - __bfloat162float(h0.x),
                                              v.y - __bfloat162float(h0.y));
    __nv_bfloat162 l1 = __floats2bfloat162_rn(v.z - __bfloat162float(h1.x),
                                              v.w - __bfloat162float(h1.y));
    ((__nv_bfloat162*)hi)[2 * i]     = h0;
    ((__nv_bfloat162*)hi)[2 * i + 1] = h1;
    ((__nv_bfloat162*)lo)[2 * i]     = l0;
    ((__nv_bfloat162*)lo)[2 * i + 1] = l1;
}

// src -> x copy + split
__global__ void copy_split(const float* __restrict__ src, float* __restrict__ x,
                           __nv_bfloat16* __restrict__ hi, __nv_bfloat16* __restrict__ lo,
                           int n4) {
    const int i = blockIdx.x * blockDim.x + threadIdx.x;
    if (i >= n4) return;
    const float4 v = ((const float4*)src)[i];
    ((float4*)x)[i] = v;
    __nv_bfloat162 h0 = __floats2bfloat162_rn(v.x, v.y);
    __nv_bfloat162 h1 = __floats2bfloat162_rn(v.z, v.w);
    __nv_bfloat162 l0 = __floats2bfloat162_rn(v.x - __bfloat162float(h0.x),
                                              v.y - __bfloat162float(h0.y));
    __nv_bfloat162 l1 = __floats2bfloat162_rn(v.z - __bfloat162float(h1.x),
                                              v.w - __bfloat162float(h1.y));
    ((__nv_bfloat162*)hi)[2 * i]     = h0;
    ((__nv_bfloat162*)hi)[2 * i + 1] = h1;
    ((__nv_bfloat162*)lo)[2 * i]     = l0;
    ((__nv_bfloat162*)lo)[2 * i + 1] = l1;
}

// ---------------------------------------------------------------------------
// GEMM: Y[M,N] = X[M,K] @ W[N,K]^T + bias, inputs pre-split bf16 hi/lo.
// 3-MMA scheme (hh + hl + lh). 128x128 tile, BK=32, 256 thr (8 warps 2x4).
// SPLIT_OUT: write Yhi/Ylo bf16 instead of fp32.
// ---------------------------------------------------------------------------
#define PITCH 40                         // bf16 per smem row (80B, conflict-free)
#define PLANE_B (128 * PITCH * 2)        // 10240 bytes
#define BUFB (4 * PLANE_B)               // 40960 bytes (Ahi,Alo,Bhi,Blo)
#define SMEMB (2 * BUFB)                 // 81920

template<int RELU, int SPLIT_OUT>
__global__ __launch_bounds__(256)
void gemm_tc(const __nv_bfloat16* __restrict__ Xhi, const __nv_bfloat16* __restrict__ Xlo,
             const __nv_bfloat16* __restrict__ Whi, const __nv_bfloat16* __restrict__ Wlo,
             const float* __restrict__ bias, float* __restrict__ Yf,
             __nv_bfloat16* __restrict__ Yhi, __nv_bfloat16* __restrict__ Ylo,
             int M, int N, int K) {
    extern __shared__ __align__(16) char smc[];
    const uint32_t smem_u32 = (uint32_t)__cvta_generic_to_shared(smc);

    const int tid = threadIdx.x;
    const int lane = tid & 31, warp = tid >> 5;
    const int wm = warp & 1, wn = warp >> 1;
    const int g = lane >> 2, tig = lane & 3;
    const int m0 = blockIdx.y * 128, n0 = blockIdx.x * 128;

    float acc[4][4][4] = {};
    const int KT = K >> 5;

    // staging: 8 chunks of 16B per thread per k-tile (plane = r>>1)
    const __nv_bfloat16* gp[4] = { Xhi, Xlo, Whi, Wlo };
    const int rb[4] = { m0, m0, n0, n0 };

    {   // prologue
        #pragma unroll
        for (int r = 0; r < 8; r++) {
            const int plane = r >> 1;
            const int c = ((r & 1) << 8) + tid;      // 0..511
            const int row = c >> 2, c8 = (c & 3) << 3;
            cp16(smem_u32 + plane * PLANE_B + (row * PITCH + c8) * 2,
                 gp[plane] + (size_t)(rb[plane] + row) * K + c8);
        }
        asm volatile("cp.async.commit_group;");
    }

    int buf = 0;
    for (int kt = 0; kt < KT; kt++) {
        asm volatile("cp.async.wait_group 0;");
        __syncthreads();

        if (kt + 1 < KT) {
            const int k0 = (kt + 1) << 5;
            const uint32_t sb = smem_u32 + (buf ^ 1) * BUFB;
            #pragma unroll
            for (int r = 0; r < 8; r++) {
                const int plane = r >> 1;
                const int c = ((r & 1) << 8) + tid;
                const int row = c >> 2, c8 = (c & 3) << 3;
                cp16(sb + plane * PLANE_B + (row * PITCH + c8) * 2,
                     gp[plane] + (size_t)(rb[plane] + row) * K + k0 + c8);
            }
            asm volatile("cp.async.commit_group;");
        }

        const uint32_t bb = smem_u32 + buf * BUFB;
        const int lrow = lane & 15;
        const int lcol8 = (lane >> 4) << 3;

        #pragma unroll
        for (int ks = 0; ks < 2; ks++) {
            const int acol = ks * 16 + lcol8;
            uint32_t ah[4][4], al[4][4], bh[4][2], bl[4][2];
            #pragma unroll
            for (int i = 0; i < 4; i++) {
                const uint32_t off = (uint32_t)(((wm * 64 + i * 16 + lrow) * PITCH + acol) * 2);
                ldsm_x4(ah[i], bb + off);                 // Ahi plane
                ldsm_x4(al[i], bb + PLANE_B + off);       // Alo plane
            }
            #pragma unroll
            for (int jp = 0; jp < 2; jp++) {
                const uint32_t off = (uint32_t)(((wn * 32 + jp * 16 + lrow) * PITCH + acol) * 2);
                uint32_t th[4], tl[4];
                ldsm_x4(th, bb + 2 * PLANE_B + off);      // Bhi
                ldsm_x4(tl, bb + 3 * PLANE_B + off);      // Blo
                bh[jp * 2][0] = th[0]; bh[jp * 2 + 1][0] = th[1];
                bh[jp * 2][1] = th[2]; bh[jp * 2 + 1][1] = th[3];
                bl[jp * 2][0] = tl[0]; bl[jp * 2 + 1][0] = tl[1];
                bl[jp * 2][1] = tl[2]; bl[jp * 2 + 1][1] = tl[3];
            }
            #pragma unroll
            for (int i = 0; i < 4; i++)
                #pragma unroll
                for (int j = 0; j < 4; j++) {
                    mma_bf16(acc[i][j], ah[i], bh[j]);
                    mma_bf16(acc[i][j], ah[i], bl[j]);
                    mma_bf16(acc[i][j], al[i], bh[j]);
                }
        }
        buf ^= 1;
    }

    // epilogue
    #pragma unroll
    for (int i = 0; i < 4; i++) {
        const int row0 = m0 + wm * 64 + i * 16 + g;
        #pragma unroll
        for (int j = 0; j < 4; j++) {
            const int col = n0 + wn * 32 + j * 8 + 2 * tig;
            const float2 bv = *(const float2*)(bias + col);
            float2 v0 = { acc[i][j][0] + bv.x, acc[i][j][1] + bv.y };
            float2 v1 = { acc[i][j][2] + bv.x, acc[i][j][3] + bv.y };
            if (RELU) {
                v0.x = fmaxf(v0.x, 0.f); v0.y = fmaxf(v0.y, 0.f);
                v1.x = fmaxf(v1.x, 0.f); v1.y = fmaxf(v1.y, 0.f);
            }
            if (SPLIT_OUT) {
                __nv_bfloat162 h0 = __floats2bfloat162_rn(v0.x, v0.y);
                __nv_bfloat162 h1 = __floats2bfloat162_rn(v1.x, v1.y);
                __nv_bfloat162 l0 = __floats2bfloat162_rn(v0.x - __bfloat162float(h0.x),
                                                          v0.y - __bfloat162float(h0.y));
                __nv_bfloat162 l1 = __floats2bfloat162_rn(v1.x - __bfloat162float(h1.x),
                                                          v1.y - __bfloat162float(h1.y));
                *(__nv_bfloat162*)(Yhi + (size_t)row0 * N + col) = h0;
                *(__nv_bfloat162*)(Yhi + (size_t)(row0 + 8) * N + col) = h1;
                *(__nv_bfloat162*)(Ylo + (size_t)row0 * N + col) = l0;
                *(__nv_bfloat162*)(Ylo + (size_t)(row0 + 8) * N + col) = l1;
            } else {
                *(float2*)(Yf + (size_t)row0 * N + col) = v0;
                *(float2*)(Yf + (size_t)(row0 + 8) * N + col) = v1;
            }
        }
    }
}

// ---------------------------------------------------------------------------
// Log-sparse attention, 16 queries per block; writes split bf16 output.
// ---------------------------------------------------------------------------
#define QT 16
__global__ __launch_bounds__(128)
void attn_tile(const float* __restrict__ qkv,
               __nv_bfloat16* __restrict__ ohi, __nv_bfloat16* __restrict__ olo) {
    const int q0 = blockIdx.x * QT;
    const int h = blockIdx.y, b = blockIdx.z;
    const int tid = threadIdx.x, lane = tid & 31, w = tid >> 5;

    __shared__ float Ks[80][64];
    __shared__ float Vs[80][64];
    __shared__ float Qs[QT][64];
    __shared__ float P[QT][72];

    const float* base = qkv + (size_t)(b * SEQ) * 1536;

    for (int e = tid; e < 80 * 16; e += 128) {
        const int r = e >> 4, c4 = (e & 15) << 2;
        const int j = q0 - 64 + r;
        float4 kv = {0.f, 0.f, 0.f, 0.f}, vv = {0.f, 0.f, 0.f, 0.f};
        if (j >= 0) {
            kv = *(const float4*)(base + (size_t)j * 1536 + 512 + h * 64 + c4);
            vv = *(const float4*)(base + (size_t)j * 1536 + 1024 + h * 64 + c4);
        }
        *(float4*)(&Ks[r][c4]) = kv;
        *(float4*)(&Vs[r][c4]) = vv;
    }
    for (int e = tid; e < QT * 16; e += 128) {
        const int r = e >> 4, c4 = (e & 15) << 2;
        *(float4*)(&Qs[r][c4]) =
            *(const float4*)(base + (size_t)(q0 + r) * 1536 + h * 64 + c4);
    }
    __syncthreads();

    float inv[4];
    #pragma unroll
    for (int c = 0; c < 4; c++) {
        const int qi = w * 4 + c;
        const int i = q0 + qi;
        const int lo = (i > 64) ? (i - 64) : 0;
        const int nwin = i - lo + 1;
        const int ne = (i >= 128) + (i >= 256) + (i >= 512) + (i >= 1024);
        const int n = nwin + ne;
        const float qv0 = Qs[qi][lane], qv1 = Qs[qi][lane + 32];

        float mx = -INFINITY;
        for (int kk = 0; kk < n; kk++) {
            float p;
            if (kk < nwin) {
                const int r = lo + kk - (q0 - 64);
                p = qv0 * Ks[r][lane] + qv1 * Ks[r][lane + 32];
            } else {
                const int j = i - (128 << (kk - nwin));
                const float* kp = base + (size_t)j * 1536 + 512 + h * 64;
                p = qv0 * kp[lane] + qv1 * kp[lane + 32];
            }
            #pragma unroll
            for (int o2 = 16; o2; o2 >>= 1) p += __shfl_xor_sync(~0u, p, o2);
            p *= 0.125f;
            P[qi][kk] = p;
            mx = fmaxf(mx, p);
        }
        float s = 0.f;
        for (int kk = lane; kk < n; kk += 32) {
            const float e = expf(P[qi][kk] - mx);
            P[qi][kk] = e;
            s += e;
        }
        #pragma unroll
        for (int o2 = 16; o2; o2 >>= 1) s += __shfl_xor_sync(~0u, s, o2);
        inv[c] = 1.f / s;
    }
    __syncwarp();

    #pragma unroll
    for (int c = 0; c < 4; c++) {
        const int qi = w * 4 + c;
        const int i = q0 + qi;
        const int lo = (i > 64) ? (i - 64) : 0;
        const int nwin = i - lo + 1;
        const int ne = (i >= 128) + (i >= 256) + (i >= 512) + (i >= 1024);
        const int n = nwin + ne;

        float a0 = 0.f, a1 = 0.f;
        for (int kk = 0; kk < n; kk++) {
            const float p = P[qi][kk];
            if (kk < nwin) {
                const int r = lo + kk - (q0 - 64);
                a0 += p * Vs[r][lane];
                a1 += p * Vs[r][lane + 32];
            } else {
                const int j = i - (128 << (kk - nwin));
                const float* vp = base + (size_t)j * 1536 + 1024 + h * 64;
                a0 += p * vp[lane];
                a1 += p * vp[lane + 32];
            }
        }
        const size_t off = (size_t)(b * SEQ + i) * DM + h * 64;
        const float r0 = a0 * inv[c], r1 = a1 * inv[c];
        __nv_bfloat16 h0, l0, h1, l1;
        split1(r0, h0, l0);
        split1(r1, h1, l1);
        ohi[off + lane] = h0;      olo[off + lane] = l0;
        ohi[off + lane + 32] = h1; olo[off + lane + 32] = l1;
    }
}

// ---------------------------------------------------------------------------
// x = LayerNorm(x + d) * scale + bias, also emits split bf16 of result.
// ---------------------------------------------------------------------------
__global__ void add_ln_kernel(float* __restrict__ x, const float* __restrict__ o,
                              const float* __restrict__ sc, const float* __restrict__ bi,
                              __nv_bfloat16* __restrict__ xhi, __nv_bfloat16* __restrict__ xlo) {
    const int row = blockIdx.x;
    const int t = threadIdx.x;
    const long base = (long)row * DM;

    const float v0 = x[base + t]       + o[base + t];
    const float v1 = x[base + t + 256] + o[base + t + 256];
    float s = v0 + v1, sq = v0 * v0 + v1 * v1;
    #pragma unroll
    for (int off = 16; off; off >>= 1) {
        s  += __shfl_xor_sync(0xffffffffu, s, off);
        sq += __shfl_xor_sync(0xffffffffu, sq, off);
    }
    __shared__ float ss[8], sqs[8];
    __shared__ float mean_s, rstd_s;
    const int w = t >> 5;
    if ((t & 31) == 0) { ss[w] = s; sqs[w] = sq; }
    __syncthreads();
    if (t == 0) {
        float s1 = 0.f, s2 = 0.f;
        #pragma unroll
        for (int k = 0; k < 8; k++) { s1 += ss[k]; s2 += sqs[k]; }
        const float m = s1 / (float)DM;
        mean_s = m;
        rstd_s = rsqrtf(s2 / (float)DM - m * m + 1e-5f);
    }
    __syncthreads();
    const float m = mean_s, r = rstd_s;
    const float y0 = (v0 - m) * r * sc[t]       + bi[t];
    const float y1 = (v1 - m) * r * sc[t + 256] + bi[t + 256];
    x[base + t]       = y0;
    x[base + t + 256] = y1;
    __nv_bfloat16 h0, l0, h1, l1;
    split1(y0, h0, l0);
    split1(y1, h1, l1);
    xhi[base + t] = h0;       xlo[base + t] = l0;
    xhi[base + t + 256] = h1; xlo[base + t + 256] = l1;
}

// ---------------------------------------------------------------------------
extern "C" void kernel_launch(void* const* d_in, const int* in_sizes, int n_in,
                              void* d_out, int out_size) {
    const float* src   = (const float*)d_in[0];
    const float* qkv_w = (const float*)d_in[2];
    const float* qkv_b = (const float*)d_in[3];
    const float* out_w = (const float*)d_in[4];
    const float* out_b = (const float*)d_in[5];
    const float* ln1_s = (const float*)d_in[6];
    const float* ln1_b = (const float*)d_in[7];
    const float* w1    = (const float*)d_in[8];
    const float* b1    = (const float*)d_in[9];
    const float* w2    = (const float*)d_in[10];
    const float* b2    = (const float*)d_in[11];
    const float* ln2_s = (const float*)d_in[12];
    const float* ln2_b = (const float*)d_in[13];

    float* x = (float*)d_out;

    float *qkv, *dbuf;
    __nv_bfloat16 *xhi, *xlo, *ohi, *olo, *hhi, *hlo, *whi, *wlo;
    cudaGetSymbolAddress((void**)&qkv, g_qkv);
    cudaGetSymbolAddress((void**)&dbuf, g_d);
    cudaGetSymbolAddress((void**)&xhi, g_xhi);
    cudaGetSymbolAddress((void**)&xlo, g_xlo);
    cudaGetSymbolAddress((void**)&ohi, g_ohi);
    cudaGetSymbolAddress((void**)&olo, g_olo);
    cudaGetSymbolAddress((void**)&hhi, g_hhi);
    cudaGetSymbolAddress((void**)&hlo, g_hlo);
    cudaGetSymbolAddress((void**)&whi, g_whi);
    cudaGetSymbolAddress((void**)&wlo, g_wlo);

    cudaFuncSetAttribute(gemm_tc<0,0>, cudaFuncAttributeMaxDynamicSharedMemorySize, SMEMB);
    cudaFuncSetAttribute(gemm_tc<1,1>, cudaFuncAttributeMaxDynamicSharedMemorySize, SMEMB);

    // weight splits (once per launch; cheap)
    split_arr<<<(2*1536*512/4 + 255)/256, 256>>>(qkv_w, whi + OFF_QKV, wlo + OFF_QKV, 2*1536*512/4);
    split_arr<<<(2*512*512/4  + 255)/256, 256>>>(out_w, whi + OFF_OUT, wlo + OFF_OUT, 2*512*512/4);
    split_arr<<<(2*2048*512/4 + 255)/256, 256>>>(w1,    whi + OFF_W1,  wlo + OFF_W1,  2*2048*512/4);
    split_arr<<<(2*512*2048/4 + 255)/256, 256>>>(w2,    whi + OFF_W2,  wlo + OFF_W2,  2*512*2048/4);
    copy_split<<<(ROWS*DM/4 + 255)/256, 256>>>(src, x, xhi, xlo, ROWS*DM/4);

    for (int l = 0; l < 2; l++) {
        // QKV projection
        gemm_tc<0,0><<<dim3(12, 64), 256, SMEMB>>>(
            xhi, xlo, whi + OFF_QKV + (size_t)l*1536*512, wlo + OFF_QKV + (size_t)l*1536*512,
            qkv_b + (size_t)l*1536, qkv, nullptr, nullptr, ROWS, 1536, 512);

        attn_tile<<<dim3(SEQ/QT, NH, BATCH), 128>>>(qkv, ohi, olo);

        // output projection -> dbuf (fp32)
        gemm_tc<0,0><<<dim3(4, 64), 256, SMEMB>>>(
            ohi, olo, whi + OFF_OUT + (size_t)l*512*512, wlo + OFF_OUT + (size_t)l*512*512,
            out_b + (size_t)l*512, dbuf, nullptr, nullptr, ROWS, 512, 512);

        add_ln_kernel<<<ROWS, 256>>>(x, dbuf, ln1_s + l*DM, ln1_b + l*DM, xhi, xlo);

        // FFN up + ReLU -> split bf16 directly
        gemm_tc<1,1><<<dim3(16, 64), 256, SMEMB>>>(
            xhi, xlo, whi + OFF_W1 + (size_t)l*2048*512, wlo + OFF_W1 + (size_t)l*2048*512,
            b1 + (size_t)l*2048, nullptr, hhi, hlo, ROWS, 2048, 512);

        // FFN down -> dbuf (fp32)
        gemm_tc<0,0><<<dim3(4, 64), 256, SMEMB>>>(
            hhi, hlo, whi + OFF_W2 + (size_t)l*512*2048, wlo + OFF_W2 + (size_t)l*512*2048,
            b2 + (size_t)l*512, dbuf, nullptr, nullptr, ROWS, 512, 2048);

        add_ln_kernel<<<ROWS, 256>>>(x, dbuf, ln2_s + l*DM, ln2_b + l*DM, xhi, xlo);
    }
}

// round 6
// speedup vs baseline: 3.3892x; 1.0722x over previous
#include <cuda_runtime.h>
#include <cuda_bf16.h>
#include <math.h>
#include <stdint.h>

#define SEQ 2048
#define DM 512
#define NH 8
#define DH 64
#define DFF 2048
#define BATCH 4
#define ROWS (BATCH * SEQ)   // 8192

// ---------------- device scratch (no allocation allowed) -------------------
__device__ float g_qkv[(size_t)ROWS * 3 * DM];
__device__ float g_d[(size_t)ROWS * DM];
__device__ __nv_bfloat16 g_xhi[(size_t)ROWS * DM];
__device__ __nv_bfloat16 g_xlo[(size_t)ROWS * DM];
__device__ __nv_bfloat16 g_ohi[(size_t)ROWS * DM];
__device__ __nv_bfloat16 g_olo[(size_t)ROWS * DM];
__device__ __nv_bfloat16 g_hhi[(size_t)ROWS * DFF];
__device__ __nv_bfloat16 g_hlo[(size_t)ROWS * DFF];
#define W_TOTAL 6291456
__device__ __nv_bfloat16 g_whi[W_TOTAL];
__device__ __nv_bfloat16 g_wlo[W_TOTAL];
#define OFF_QKV 0
#define OFF_OUT (2 * 1536 * 512)
#define OFF_W1  (OFF_OUT + 2 * 512 * 512)
#define OFF_W2  (OFF_W1 + 2 * 2048 * 512)

// ---------------------------------------------------------------------------
// helpers
// ---------------------------------------------------------------------------
__device__ __forceinline__ void cp16(uint32_t saddr, const void* g) {
    asm volatile("cp.async.cg.shared.global [%0], [%1], 16;" :: "r"(saddr), "l"(g));
}
__device__ __forceinline__ void ldsm_x4(uint32_t* r, uint32_t a) {
    asm volatile("ldmatrix.sync.aligned.m8n8.x4.shared.b16 {%0,%1,%2,%3}, [%4];"
                 : "=r"(r[0]), "=r"(r[1]), "=r"(r[2]), "=r"(r[3]) : "r"(a));
}
__device__ __forceinline__ void mma_bf16(float* d, const uint32_t* a, const uint32_t* b) {
    asm volatile("mma.sync.aligned.m16n8k16.row.col.f32.bf16.bf16.f32 "
                 "{%0,%1,%2,%3}, {%4,%5,%6,%7}, {%8,%9}, {%0,%1,%2,%3};"
                 : "+f"(d[0]), "+f"(d[1]), "+f"(d[2]), "+f"(d[3])
                 : "r"(a[0]), "r"(a[1]), "r"(a[2]), "r"(a[3]), "r"(b[0]), "r"(b[1]));
}
__device__ __forceinline__ void split1(float v, __nv_bfloat16& h, __nv_bfloat16& l) {
    h = __float2bfloat16_rn(v);
    l = __float2bfloat16_rn(v - __bfloat162float(h));
}
#define SWZ(bo) ((bo) ^ (((bo) >> 3) & 0x70))

// ---------------------------------------------------------------------------
// one-shot fp32 -> (hi, lo) bf16 split kernels
// ---------------------------------------------------------------------------
__global__ void split_arr(const float* __restrict__ src, __nv_bfloat16* __restrict__ hi,
                          __nv_bfloat16* __restrict__ lo, int n4) {
    const int i = blockIdx.x * blockDim.x + threadIdx.x;
    if (i >= n4) return;
    const float4 v = ((const float4*)src)[i];
    __nv_bfloat162 h0 = __floats2bfloat162_rn(v.x, v.y);
    __nv_bfloat162 h1 = __floats2bfloat162_rn(v.z, v.w);
    __nv_bfloat162 l0 = __floats2bfloat162_rn(v.x - __bfloat162float(h0.x),
                                              v.y - __bfloat162float(h0.y));
    __nv_bfloat162 l1 = __floats2bfloat162_rn(v.z - __bfloat162float(h1.x),
                                              v.w - __bfloat162float(h1.y));
    ((__nv_bfloat162*)hi)[2 * i]     = h0;
    ((__nv_bfloat162*)hi)[2 * i + 1] = h1;
    ((__nv_bfloat162*)lo)[2 * i]     = l0;
    ((__nv_bfloat162*)lo)[2 * i + 1] = l1;
}

__global__ void copy_split(const float* __restrict__ src, float* __restrict__ x,
                           __nv_bfloat16* __restrict__ hi, __nv_bfloat16* __restrict__ lo,
                           int n4) {
    const int i = blockIdx.x * blockDim.x + threadIdx.x;
    if (i >= n4) return;
    const float4 v = ((const float4*)src)[i];
    ((float4*)x)[i] = v;
    __nv_bfloat162 h0 = __floats2bfloat162_rn(v.x, v.y);
    __nv_bfloat162 h1 = __floats2bfloat162_rn(v.z, v.w);
    __nv_bfloat162 l0 = __floats2bfloat162_rn(v.x - __bfloat162float(h0.x),
                                              v.y - __bfloat162float(h0.y));
    __nv_bfloat162 l1 = __floats2bfloat162_rn(v.z - __bfloat162float(h1.x),
                                              v.w - __bfloat162float(h1.y));
    ((__nv_bfloat162*)hi)[2 * i]     = h0;
    ((__nv_bfloat162*)hi)[2 * i + 1] = h1;
    ((__nv_bfloat162*)lo)[2 * i]     = l0;
    ((__nv_bfloat162*)lo)[2 * i + 1] = l1;
}

// ---------------------------------------------------------------------------
// GEMM: Y[M,N] = X[M,K] @ W[N,K]^T + bias, bf16 hi/lo split (3 MMAs, mma.sync).
// 128x128 tile, BK=64, SW128-swizzled smem (conflict-free cp.async + ldmatrix),
// double-buffered. 256 threads (8 warps: 2m x 4n, 64x32 each).
// ---------------------------------------------------------------------------
#define PLANEB 16384                  // 128 rows x 128B
#define BUFB (4 * PLANEB)             // Ahi,Alo,Bhi,Blo = 64 KB
#define SMEMB (2 * BUFB)              // 128 KB

#define STAGE_TILE(BUFADDR, KOF) do {                                          \
    _Pragma("unroll")                                                          \
    for (int r_ = 0; r_ < 16; r_++) {                                          \
        const int idx_ = r_ * 256 + tid;                                       \
        const int p_ = idx_ >> 10;                                             \
        const int c_ = idx_ & 1023;                                            \
        const int row_ = c_ >> 3, ch_ = c_ & 7;                                \
        const uint32_t bo_ = (uint32_t)(row_ * 128 + ch_ * 16);                \
        cp16((BUFADDR) + p_ * PLANEB + SWZ(bo_),                               \
             gp[p_] + (size_t)(rb[p_] + row_) * K + (KOF) + ch_ * 8);          \
    }                                                                          \
    asm volatile("cp.async.commit_group;");                                    \
} while (0)

template<int RELU, int SPLIT_OUT>
__global__ __launch_bounds__(256)
void gemm_tc(const __nv_bfloat16* __restrict__ Xhi, const __nv_bfloat16* __restrict__ Xlo,
             const __nv_bfloat16* __restrict__ Whi, const __nv_bfloat16* __restrict__ Wlo,
             const float* __restrict__ bias, float* __restrict__ Yf,
             __nv_bfloat16* __restrict__ Yhi, __nv_bfloat16* __restrict__ Ylo,
             int M, int N, int K) {
    extern __shared__ __align__(1024) char smc[];
    const uint32_t sb = (uint32_t)__cvta_generic_to_shared(smc);

    const int tid = threadIdx.x;
    const int lane = tid & 31, warp = tid >> 5;
    const int wm = warp & 1, wn = warp >> 1;
    const int g = lane >> 2, tig = lane & 3;
    const int m0 = blockIdx.y * 128, n0 = blockIdx.x * 128;

    float acc[4][4][4] = {};
    const int KT = K >> 6;

    const __nv_bfloat16* gp[4] = { Xhi, Xlo, Whi, Wlo };
    const int rb[4] = { m0, m0, n0, n0 };

    // ldmatrix lane addressing (within a 128B-row swizzled plane)
    const int lrow = lane & 15;
    const int lseg = (lane >> 4) << 4;    // 0 or 16 bytes (col +8 bf16)

    STAGE_TILE(sb, 0);   // prologue: tile 0 -> buf 0

    for (int kt = 0; kt < KT; kt++) {
        const int b = kt & 1;
        asm volatile("cp.async.wait_group 0;");
        __syncthreads();

        if (kt + 1 < KT) {
            const uint32_t bufn = sb + (b ^ 1) * BUFB;
            const int kof = (kt + 1) << 6;
            STAGE_TILE(bufn, kof);
        }

        const uint32_t bufb = sb + b * BUFB;
        #pragma unroll
        for (int ks = 0; ks < 4; ks++) {
            const uint32_t kbyte = (uint32_t)(ks * 32 + lseg);
            uint32_t ah[4][4], al[4][4], bh[4][2], bl[4][2];
            #pragma unroll
            for (int i = 0; i < 4; i++) {
                const uint32_t bo = (uint32_t)((wm * 64 + i * 16 + lrow) * 128) + kbyte;
                const uint32_t sw = SWZ(bo);
                ldsm_x4(ah[i], bufb + sw);
                ldsm_x4(al[i], bufb + PLANEB + sw);
            }
            #pragma unroll
            for (int jp = 0; jp < 2; jp++) {
                const uint32_t bo = (uint32_t)((wn * 32 + jp * 16 + lrow) * 128) + kbyte;
                const uint32_t sw = SWZ(bo);
                uint32_t th[4], tl[4];
                ldsm_x4(th, bufb + 2 * PLANEB + sw);
                ldsm_x4(tl, bufb + 3 * PLANEB + sw);
                bh[jp * 2][0] = th[0]; bh[jp * 2 + 1][0] = th[1];
                bh[jp * 2][1] = th[2]; bh[jp * 2 + 1][1] = th[3];
                bl[jp * 2][0] = tl[0]; bl[jp * 2 + 1][0] = tl[1];
                bl[jp * 2][1] = tl[2]; bl[jp * 2 + 1][1] = tl[3];
            }
            #pragma unroll
            for (int i = 0; i < 4; i++)
                #pragma unroll
                for (int j = 0; j < 4; j++) {
                    mma_bf16(acc[i][j], ah[i], bh[j]);
                    mma_bf16(acc[i][j], ah[i], bl[j]);
                    mma_bf16(acc[i][j], al[i], bh[j]);
                }
        }
    }

    // epilogue: d0,d1 -> (row g, cols 2tig..); d2,d3 -> row g+8
    #pragma unroll
    for (int i = 0; i < 4; i++) {
        const int row0 = m0 + wm * 64 + i * 16 + g;
        #pragma unroll
        for (int j = 0; j < 4; j++) {
            const int col = n0 + wn * 32 + j * 8 + 2 * tig;
            const float2 bv = *(const float2*)(bias + col);
            float2 v0 = { acc[i][j][0] + bv.x, acc[i][j][1] + bv.y };
            float2 v1 = { acc[i][j][2] + bv.x, acc[i][j][3] + bv.y };
            if (RELU) {
                v0.x = fmaxf(v0.x, 0.f); v0.y = fmaxf(v0.y, 0.f);
                v1.x = fmaxf(v1.x, 0.f); v1.y = fmaxf(v1.y, 0.f);
            }
            if (SPLIT_OUT) {
                __nv_bfloat162 h0 = __floats2bfloat162_rn(v0.x, v0.y);
                __nv_bfloat162 h1 = __floats2bfloat162_rn(v1.x, v1.y);
                __nv_bfloat162 l0 = __floats2bfloat162_rn(v0.x - __bfloat162float(h0.x),
                                                          v0.y - __bfloat162float(h0.y));
                __nv_bfloat162 l1 = __floats2bfloat162_rn(v1.x - __bfloat162float(h1.x),
                                                          v1.y - __bfloat162float(h1.y));
                *(__nv_bfloat162*)(Yhi + (size_t)row0 * N + col) = h0;
                *(__nv_bfloat162*)(Yhi + (size_t)(row0 + 8) * N + col) = h1;
                *(__nv_bfloat162*)(Ylo + (size_t)row0 * N + col) = l0;
                *(__nv_bfloat162*)(Ylo + (size_t)(row0 + 8) * N + col) = l1;
            } else {
                *(float2*)(Yf + (size_t)row0 * N + col) = v0;
                *(float2*)(Yf + (size_t)(row0 + 8) * N + col) = v1;
            }
        }
    }
}

// ---------------------------------------------------------------------------
// Log-sparse attention, 16 queries per block; writes split bf16 output.
// ---------------------------------------------------------------------------
#define QT 16
__global__ __launch_bounds__(128)
void attn_tile(const float* __restrict__ qkv,
               __nv_bfloat16* __restrict__ ohi, __nv_bfloat16* __restrict__ olo) {
    const int q0 = blockIdx.x * QT;
    const int h = blockIdx.y, b = blockIdx.z;
    const int tid = threadIdx.x, lane = tid & 31, w = tid >> 5;

    __shared__ float Ks[80][64];
    __shared__ float Vs[80][64];
    __shared__ float Qs[QT][64];
    __shared__ float P[QT][72];

    const float* base = qkv + (size_t)(b * SEQ) * 1536;

    for (int e = tid; e < 80 * 16; e += 128) {
        const int r = e >> 4, c4 = (e & 15) << 2;
        const int j = q0 - 64 + r;
        float4 kv = {0.f, 0.f, 0.f, 0.f}, vv = {0.f, 0.f, 0.f, 0.f};
        if (j >= 0) {
            kv = *(const float4*)(base + (size_t)j * 1536 + 512 + h * 64 + c4);
            vv = *(const float4*)(base + (size_t)j * 1536 + 1024 + h * 64 + c4);
        }
        *(float4*)(&Ks[r][c4]) = kv;
        *(float4*)(&Vs[r][c4]) = vv;
    }
    for (int e = tid; e < QT * 16; e += 128) {
        const int r = e >> 4, c4 = (e & 15) << 2;
        *(float4*)(&Qs[r][c4]) =
            *(const float4*)(base + (size_t)(q0 + r) * 1536 + h * 64 + c4);
    }
    __syncthreads();

    float inv[4];
    #pragma unroll
    for (int c = 0; c < 4; c++) {
        const int qi = w * 4 + c;
        const int i = q0 + qi;
        const int lo = (i > 64) ? (i - 64) : 0;
        const int nwin = i - lo + 1;
        const int ne = (i >= 128) + (i >= 256) + (i >= 512) + (i >= 1024);
        const int n = nwin + ne;
        const float qv0 = Qs[qi][lane], qv1 = Qs[qi][lane + 32];

        float mx = -INFINITY;
        for (int kk = 0; kk < n; kk++) {
            float p;
            if (kk < nwin) {
                const int r = lo + kk - (q0 - 64);
                p = qv0 * Ks[r][lane] + qv1 * Ks[r][lane + 32];
            } else {
                const int j = i - (128 << (kk - nwin));
                const float* kp = base + (size_t)j * 1536 + 512 + h * 64;
                p = qv0 * kp[lane] + qv1 * kp[lane + 32];
            }
            #pragma unroll
            for (int o2 = 16; o2; o2 >>= 1) p += __shfl_xor_sync(~0u, p, o2);
            p *= 0.125f;
            P[qi][kk] = p;
            mx = fmaxf(mx, p);
        }
        float s = 0.f;
        for (int kk = lane; kk < n; kk += 32) {
            const float e = expf(P[qi][kk] - mx);
            P[qi][kk] = e;
            s += e;
        }
        #pragma unroll
        for (int o2 = 16; o2; o2 >>= 1) s += __shfl_xor_sync(~0u, s, o2);
        inv[c] = 1.f / s;
    }
    __syncwarp();

    #pragma unroll
    for (int c = 0; c < 4; c++) {
        const int qi = w * 4 + c;
        const int i = q0 + qi;
        const int lo = (i > 64) ? (i - 64) : 0;
        const int nwin = i - lo + 1;
        const int ne = (i >= 128) + (i >= 256) + (i >= 512) + (i >= 1024);
        const int n = nwin + ne;

        float a0 = 0.f, a1 = 0.f;
        for (int kk = 0; kk < n; kk++) {
            const float p = P[qi][kk];
            if (kk < nwin) {
                const int r = lo + kk - (q0 - 64);
                a0 += p * Vs[r][lane];
                a1 += p * Vs[r][lane + 32];
            } else {
                const int j = i - (128 << (kk - nwin));
                const float* vp = base + (size_t)j * 1536 + 1024 + h * 64;
                a0 += p * vp[lane];
                a1 += p * vp[lane + 32];
            }
        }
        const size_t off = (size_t)(b * SEQ + i) * DM + h * 64;
        const float r0 = a0 * inv[c], r1 = a1 * inv[c];
        __nv_bfloat16 h0, l0, h1, l1;
        split1(r0, h0, l0);
        split1(r1, h1, l1);
        ohi[off + lane] = h0;      olo[off + lane] = l0;
        ohi[off + lane + 32] = h1; olo[off + lane + 32] = l1;
    }
}

// ---------------------------------------------------------------------------
// x = LayerNorm(x + d) * scale + bias, also emits split bf16 of result.
// ---------------------------------------------------------------------------
__global__ void add_ln_kernel(float* __restrict__ x, const float* __restrict__ o,
                              const float* __restrict__ sc, const float* __restrict__ bi,
                              __nv_bfloat16* __restrict__ xhi, __nv_bfloat16* __restrict__ xlo) {
    const int row = blockIdx.x;
    const int t = threadIdx.x;
    const long base = (long)row * DM;

    const float v0 = x[base + t]       + o[base + t];
    const float v1 = x[base + t + 256] + o[base + t + 256];
    float s = v0 + v1, sq = v0 * v0 + v1 * v1;
    #pragma unroll
    for (int off = 16; off; off >>= 1) {
        s  += __shfl_xor_sync(0xffffffffu, s, off);
        sq += __shfl_xor_sync(0xffffffffu, sq, off);
    }
    __shared__ float ss[8], sqs[8];
    __shared__ float mean_s, rstd_s;
    const int w = t >> 5;
    if ((t & 31) == 0) { ss[w] = s; sqs[w] = sq; }
    __syncthreads();
    if (t == 0) {
        float s1 = 0.f, s2 = 0.f;
        #pragma unroll
        for (int k = 0; k < 8; k++) { s1 += ss[k]; s2 += sqs[k]; }
        const float m = s1 / (float)DM;
        mean_s = m;
        rstd_s = rsqrtf(s2 / (float)DM - m * m + 1e-5f);
    }
    __syncthreads();
    const float m = mean_s, r = rstd_s;
    const float y0 = (v0 - m) * r * sc[t]       + bi[t];
    const float y1 = (v1 - m) * r * sc[t + 256] + bi[t + 256];
    x[base + t]       = y0;
    x[base + t + 256] = y1;
    __nv_bfloat16 h0, l0, h1, l1;
    split1(y0, h0, l0);
    split1(y1, h1, l1);
    xhi[base + t] = h0;       xlo[base + t] = l0;
    xhi[base + t + 256] = h1; xlo[base + t + 256] = l1;
}

// ---------------------------------------------------------------------------
extern "C" void kernel_launch(void* const* d_in, const int* in_sizes, int n_in,
                              void* d_out, int out_size) {
    const float* src   = (const float*)d_in[0];
    const float* qkv_w = (const float*)d_in[2];
    const float* qkv_b = (const float*)d_in[3];
    const float* out_w = (const float*)d_in[4];
    const float* out_b = (const float*)d_in[5];
    const float* ln1_s = (const float*)d_in[6];
    const float* ln1_b = (const float*)d_in[7];
    const float* w1    = (const float*)d_in[8];
    const float* b1    = (const float*)d_in[9];
    const float* w2    = (const float*)d_in[10];
    const float* b2    = (const float*)d_in[11];
    const float* ln2_s = (const float*)d_in[12];
    const float* ln2_b = (const float*)d_in[13];

    float* x = (float*)d_out;

    float *qkv, *dbuf;
    __nv_bfloat16 *xhi, *xlo, *ohi, *olo, *hhi, *hlo, *whi, *wlo;
    cudaGetSymbolAddress((void**)&qkv, g_qkv);
    cudaGetSymbolAddress((void**)&dbuf, g_d);
    cudaGetSymbolAddress((void**)&xhi, g_xhi);
    cudaGetSymbolAddress((void**)&xlo, g_xlo);
    cudaGetSymbolAddress((void**)&ohi, g_ohi);
    cudaGetSymbolAddress((void**)&olo, g_olo);
    cudaGetSymbolAddress((void**)&hhi, g_hhi);
    cudaGetSymbolAddress((void**)&hlo, g_hlo);
    cudaGetSymbolAddress((void**)&whi, g_whi);
    cudaGetSymbolAddress((void**)&wlo, g_wlo);

    cudaFuncSetAttribute(gemm_tc<0,0>, cudaFuncAttributeMaxDynamicSharedMemorySize, SMEMB);
    cudaFuncSetAttribute(gemm_tc<1,1>, cudaFuncAttributeMaxDynamicSharedMemorySize, SMEMB);

    split_arr<<<(2*1536*512/4 + 255)/256, 256>>>(qkv_w, whi + OFF_QKV, wlo + OFF_QKV, 2*1536*512/4);
    split_arr<<<(2*512*512/4  + 255)/256, 256>>>(out_w, whi + OFF_OUT, wlo + OFF_OUT, 2*512*512/4);
    split_arr<<<(2*2048*512/4 + 255)/256, 256>>>(w1,    whi + OFF_W1,  wlo + OFF_W1,  2*2048*512/4);
    split_arr<<<(2*512*2048/4 + 255)/256, 256>>>(w2,    whi + OFF_W2,  wlo + OFF_W2,  2*512*2048/4);
    copy_split<<<(ROWS*DM/4 + 255)/256, 256>>>(src, x, xhi, xlo, ROWS*DM/4);

    for (int l = 0; l < 2; l++) {
        // QKV projection -> fp32 qkv
        gemm_tc<0,0><<<dim3(12, 64), 256, SMEMB>>>(
            xhi, xlo, whi + OFF_QKV + (size_t)l*1536*512, wlo + OFF_QKV + (size_t)l*1536*512,
            qkv_b + (size_t)l*1536, qkv, nullptr, nullptr, ROWS, 1536, 512);

        attn_tile<<<dim3(SEQ/QT, NH, BATCH), 128>>>(qkv, ohi, olo);

        // output projection -> dbuf (fp32)
        gemm_tc<0,0><<<dim3(4, 64), 256, SMEMB>>>(
            ohi, olo, whi + OFF_OUT + (size_t)l*512*512, wlo + OFF_OUT + (size_t)l*512*512,
            out_b + (size_t)l*512, dbuf, nullptr, nullptr, ROWS, 512, 512);

        add_ln_kernel<<<ROWS, 256>>>(x, dbuf, ln1_s + l*DM, ln1_b + l*DM, xhi, xlo);

        // FFN up + ReLU -> split bf16
        gemm_tc<1,1><<<dim3(16, 64), 256, SMEMB>>>(
            xhi, xlo, whi + OFF_W1 + (size_t)l*2048*512, wlo + OFF_W1 + (size_t)l*2048*512,
            b1 + (size_t)l*2048, nullptr, hhi, hlo, ROWS, 2048, 512);

        // FFN down -> dbuf (fp32)
        gemm_tc<0,0><<<dim3(4, 64), 256, SMEMB>>>(
            hhi, hlo, whi + OFF_W2 + (size_t)l*512*2048, wlo + OFF_W2 + (size_t)l*512*2048,
            b2 + (size_t)l*512, dbuf, nullptr, nullptr, ROWS, 512, 2048);

        add_ln_kernel<<<ROWS, 256>>>(x, dbuf, ln2_s + l*DM, ln2_b + l*DM, xhi, xlo);
    }
}

// round 7
// speedup vs baseline: 4.1694x; 1.2302x over previous
#include <cuda_runtime.h>
#include <cuda_fp16.h>
#include <math.h>
#include <stdint.h>

#define SEQ 2048
#define DM 512
#define NH 8
#define DH 64
#define DFF 2048
#define BATCH 4
#define ROWS (BATCH * SEQ)   // 8192

// ---------------- device scratch (no allocation allowed) -------------------
__device__ float g_qkv[(size_t)ROWS * 3 * DM];
__device__ float g_d[(size_t)ROWS * DM];
__device__ __half g_xhi[(size_t)ROWS * DM];
__device__ __half g_xlo[(size_t)ROWS * DM];
__device__ __half g_ohi[(size_t)ROWS * DM];
__device__ __half g_olo[(size_t)ROWS * DM];
__device__ __half g_hhi[(size_t)ROWS * DFF];
__device__ __half g_hlo[(size_t)ROWS * DFF];
#define W_TOTAL 6291456
__device__ __half g_wh[W_TOTAL];
#define OFF_QKV 0
#define OFF_OUT (2 * 1536 * 512)
#define OFF_W1  (OFF_OUT + 2 * 512 * 512)
#define OFF_W2  (OFF_W1 + 2 * 2048 * 512)

// ---------------------------------------------------------------------------
// helpers
// ---------------------------------------------------------------------------
__device__ __forceinline__ void cp16(uint32_t saddr, const void* g) {
    asm volatile("cp.async.cg.shared.global [%0], [%1], 16;" :: "r"(saddr), "l"(g));
}
__device__ __forceinline__ void ldsm_x4(uint32_t* r, uint32_t a) {
    asm volatile("ldmatrix.sync.aligned.m8n8.x4.shared.b16 {%0,%1,%2,%3}, [%4];"
                 : "=r"(r[0]), "=r"(r[1]), "=r"(r[2]), "=r"(r[3]) : "r"(a));
}
__device__ __forceinline__ void mma_f16(float* d, const uint32_t* a, const uint32_t* b) {
    asm volatile("mma.sync.aligned.m16n8k16.row.col.f32.f16.f16.f32 "
                 "{%0,%1,%2,%3}, {%4,%5,%6,%7}, {%8,%9}, {%0,%1,%2,%3};"
                 : "+f"(d[0]), "+f"(d[1]), "+f"(d[2]), "+f"(d[3])
                 : "r"(a[0]), "r"(a[1]), "r"(a[2]), "r"(a[3]), "r"(b[0]), "r"(b[1]));
}
__device__ __forceinline__ void split1h(float v, __half& h, __half& l) {
    h = __float2half_rn(v);
    l = __float2half_rn(v - __half2float(h));
}
#define SWZ(bo) ((bo) ^ (((bo) >> 3) & 0x70))

// ---------------------------------------------------------------------------
// conversion kernels
// ---------------------------------------------------------------------------
// weights: fp32 -> fp16 (single plane)
__global__ void conv_h(const float* __restrict__ src, __half* __restrict__ dst, int n4) {
    const int i = blockIdx.x * blockDim.x + threadIdx.x;
    if (i >= n4) return;
    const float4 v = ((const float4*)src)[i];
    ((__half2*)dst)[2 * i]     = __floats2half2_rn(v.x, v.y);
    ((__half2*)dst)[2 * i + 1] = __floats2half2_rn(v.z, v.w);
}

// src -> x copy + fp16 hi/lo split
__global__ void copy_split(const float* __restrict__ src, float* __restrict__ x,
                           __half* __restrict__ hi, __half* __restrict__ lo, int n4) {
    const int i = blockIdx.x * blockDim.x + threadIdx.x;
    if (i >= n4) return;
    const float4 v = ((const float4*)src)[i];
    ((float4*)x)[i] = v;
    __half2 h0 = __floats2half2_rn(v.x, v.y);
    __half2 h1 = __floats2half2_rn(v.z, v.w);
    __half2 l0 = __floats2half2_rn(v.x - __low2float(h0), v.y - __high2float(h0));
    __half2 l1 = __floats2half2_rn(v.z - __low2float(h1), v.w - __high2float(h1));
    ((__half2*)hi)[2 * i]     = h0;
    ((__half2*)hi)[2 * i + 1] = h1;
    ((__half2*)lo)[2 * i]     = l0;
    ((__half2*)lo)[2 * i + 1] = l1;
}

// ---------------------------------------------------------------------------
// GEMM: Y[M,N] = X[M,K] @ W[N,K]^T + bias.
// X pre-split fp16 hi/lo; W plain fp16. 2 MMAs per k16 (Ahi*B + Alo*B).
// 128x128 tile, BK=64, SW128-swizzled smem, double-buffered, 256 threads.
// ---------------------------------------------------------------------------
#define PLANEB 16384                  // 128 rows x 128B
#define BUFB (3 * PLANEB)             // Ahi, Alo, B = 48 KB
#define SMEMB (2 * BUFB)              // 96 KB

#define STAGE_TILE(BUFADDR, KOF) do {                                          \
    _Pragma("unroll")                                                          \
    for (int r_ = 0; r_ < 12; r_++) {                                          \
        const int idx_ = r_ * 256 + tid;                                       \
        const int p_ = idx_ >> 10;                                             \
        const int c_ = idx_ & 1023;                                            \
        const int row_ = c_ >> 3, ch_ = c_ & 7;                                \
        const uint32_t bo_ = (uint32_t)(row_ * 128 + ch_ * 16);                \
        cp16((BUFADDR) + p_ * PLANEB + SWZ(bo_),                               \
             gp[p_] + (size_t)(rb[p_] + row_) * K + (KOF) + ch_ * 8);          \
    }                                                                          \
    asm volatile("cp.async.commit_group;");                                    \
} while (0)

template<int RELU, int SPLIT_OUT>
__global__ __launch_bounds__(256)
void gemm_tc(const __half* __restrict__ Xhi, const __half* __restrict__ Xlo,
             const __half* __restrict__ Wh,
             const float* __restrict__ bias, float* __restrict__ Yf,
             __half* __restrict__ Yhi, __half* __restrict__ Ylo,
             int M, int N, int K) {
    extern __shared__ __align__(1024) char smc[];
    const uint32_t sb = (uint32_t)__cvta_generic_to_shared(smc);

    const int tid = threadIdx.x;
    const int lane = tid & 31, warp = tid >> 5;
    const int wm = warp & 1, wn = warp >> 1;
    const int g = lane >> 2, tig = lane & 3;
    const int m0 = blockIdx.y * 128, n0 = blockIdx.x * 128;

    float acc[4][4][4] = {};
    const int KT = K >> 6;

    const __half* gp[3] = { Xhi, Xlo, Wh };
    const int rb[3] = { m0, m0, n0 };

    const int lrow = lane & 15;
    const int lseg = (lane >> 4) << 4;    // 0 or 16 bytes

    STAGE_TILE(sb, 0);   // prologue: tile 0 -> buf 0

    for (int kt = 0; kt < KT; kt++) {
        const int b = kt & 1;
        asm volatile("cp.async.wait_group 0;");
        __syncthreads();

        if (kt + 1 < KT) {
            const uint32_t bufn = sb + (b ^ 1) * BUFB;
            const int kof = (kt + 1) << 6;
            STAGE_TILE(bufn, kof);
        }

        const uint32_t bufb = sb + b * BUFB;
        #pragma unroll
        for (int ks = 0; ks < 4; ks++) {
            const uint32_t kbyte = (uint32_t)(ks * 32 + lseg);
            uint32_t ah[4][4], al[4][4], bh[4][2];
            #pragma unroll
            for (int i = 0; i < 4; i++) {
                const uint32_t bo = (uint32_t)((wm * 64 + i * 16 + lrow) * 128) + kbyte;
                const uint32_t sw = SWZ(bo);
                ldsm_x4(ah[i], bufb + sw);
                ldsm_x4(al[i], bufb + PLANEB + sw);
            }
            #pragma unroll
            for (int jp = 0; jp < 2; jp++) {
                const uint32_t bo = (uint32_t)((wn * 32 + jp * 16 + lrow) * 128) + kbyte;
                uint32_t th[4];
                ldsm_x4(th, bufb + 2 * PLANEB + SWZ(bo));
                bh[jp * 2][0] = th[0]; bh[jp * 2 + 1][0] = th[1];
                bh[jp * 2][1] = th[2]; bh[jp * 2 + 1][1] = th[3];
            }
            #pragma unroll
            for (int i = 0; i < 4; i++)
                #pragma unroll
                for (int j = 0; j < 4; j++) {
                    mma_f16(acc[i][j], ah[i], bh[j]);
                    mma_f16(acc[i][j], al[i], bh[j]);
                }
        }
    }

    // epilogue
    #pragma unroll
    for (int i = 0; i < 4; i++) {
        const int row0 = m0 + wm * 64 + i * 16 + g;
        #pragma unroll
        for (int j = 0; j < 4; j++) {
            const int col = n0 + wn * 32 + j * 8 + 2 * tig;
            const float2 bv = *(const float2*)(bias + col);
            float2 v0 = { acc[i][j][0] + bv.x, acc[i][j][1] + bv.y };
            float2 v1 = { acc[i][j][2] + bv.x, acc[i][j][3] + bv.y };
            if (RELU) {
                v0.x = fmaxf(v0.x, 0.f); v0.y = fmaxf(v0.y, 0.f);
                v1.x = fmaxf(v1.x, 0.f); v1.y = fmaxf(v1.y, 0.f);
            }
            if (SPLIT_OUT) {
                __half2 h0 = __floats2half2_rn(v0.x, v0.y);
                __half2 h1 = __floats2half2_rn(v1.x, v1.y);
                __half2 l0 = __floats2half2_rn(v0.x - __low2float(h0),
                                               v0.y - __high2float(h0));
                __half2 l1 = __floats2half2_rn(v1.x - __low2float(h1),
                                               v1.y - __high2float(h1));
                *(__half2*)(Yhi + (size_t)row0 * N + col) = h0;
                *(__half2*)(Yhi + (size_t)(row0 + 8) * N + col) = h1;
                *(__half2*)(Ylo + (size_t)row0 * N + col) = l0;
                *(__half2*)(Ylo + (size_t)(row0 + 8) * N + col) = l1;
            } else {
                *(float2*)(Yf + (size_t)row0 * N + col) = v0;
                *(float2*)(Yf + (size_t)(row0 + 8) * N + col) = v1;
            }
        }
    }
}

// ---------------------------------------------------------------------------
// Log-sparse attention, 16 queries per block; writes fp16 hi/lo output.
// ---------------------------------------------------------------------------
#define QT 16
__global__ __launch_bounds__(128)
void attn_tile(const float* __restrict__ qkv,
               __half* __restrict__ ohi, __half* __restrict__ olo) {
    const int q0 = blockIdx.x * QT;
    const int h = blockIdx.y, b = blockIdx.z;
    const int tid = threadIdx.x, lane = tid & 31, w = tid >> 5;

    __shared__ float Ks[80][64];
    __shared__ float Vs[80][64];
    __shared__ float Qs[QT][64];
    __shared__ float P[QT][72];

    const float* base = qkv + (size_t)(b * SEQ) * 1536;

    for (int e = tid; e < 80 * 16; e += 128) {
        const int r = e >> 4, c4 = (e & 15) << 2;
        const int j = q0 - 64 + r;
        float4 kv = {0.f, 0.f, 0.f, 0.f}, vv = {0.f, 0.f, 0.f, 0.f};
        if (j >= 0) {
            kv = *(const float4*)(base + (size_t)j * 1536 + 512 + h * 64 + c4);
            vv = *(const float4*)(base + (size_t)j * 1536 + 1024 + h * 64 + c4);
        }
        *(float4*)(&Ks[r][c4]) = kv;
        *(float4*)(&Vs[r][c4]) = vv;
    }
    for (int e = tid; e < QT * 16; e += 128) {
        const int r = e >> 4, c4 = (e & 15) << 2;
        *(float4*)(&Qs[r][c4]) =
            *(const float4*)(base + (size_t)(q0 + r) * 1536 + h * 64 + c4);
    }
    __syncthreads();

    float inv[4];
    #pragma unroll
    for (int c = 0; c < 4; c++) {
        const int qi = w * 4 + c;
        const int i = q0 + qi;
        const int lo = (i > 64) ? (i - 64) : 0;
        const int nwin = i - lo + 1;
        const int ne = (i >= 128) + (i >= 256) + (i >= 512) + (i >= 1024);
        const int n = nwin + ne;
        const float qv0 = Qs[qi][lane], qv1 = Qs[qi][lane + 32];

        float mx = -INFINITY;
        for (int kk = 0; kk < n; kk++) {
            float p;
            if (kk < nwin) {
                const int r = lo + kk - (q0 - 64);
                p = qv0 * Ks[r][lane] + qv1 * Ks[r][lane + 32];
            } else {
                const int j = i - (128 << (kk - nwin));
                const float* kp = base + (size_t)j * 1536 + 512 + h * 64;
                p = qv0 * kp[lane] + qv1 * kp[lane + 32];
            }
            #pragma unroll
            for (int o2 = 16; o2; o2 >>= 1) p += __shfl_xor_sync(~0u, p, o2);
            p *= 0.125f;
            P[qi][kk] = p;
            mx = fmaxf(mx, p);
        }
        float s = 0.f;
        for (int kk = lane; kk < n; kk += 32) {
            const float e = expf(P[qi][kk] - mx);
            P[qi][kk] = e;
            s += e;
        }
        #pragma unroll
        for (int o2 = 16; o2; o2 >>= 1) s += __shfl_xor_sync(~0u, s, o2);
        inv[c] = 1.f / s;
    }
    __syncwarp();

    #pragma unroll
    for (int c = 0; c < 4; c++) {
        const int qi = w * 4 + c;
        const int i = q0 + qi;
        const int lo = (i > 64) ? (i - 64) : 0;
        const int nwin = i - lo + 1;
        const int ne = (i >= 128) + (i >= 256) + (i >= 512) + (i >= 1024);
        const int n = nwin + ne;

        float a0 = 0.f, a1 = 0.f;
        for (int kk = 0; kk < n; kk++) {
            const float p = P[qi][kk];
            if (kk < nwin) {
                const int r = lo + kk - (q0 - 64);
                a0 += p * Vs[r][lane];
                a1 += p * Vs[r][lane + 32];
            } else {
                const int j = i - (128 << (kk - nwin));
                const float* vp = base + (size_t)j * 1536 + 1024 + h * 64;
                a0 += p * vp[lane];
                a1 += p * vp[lane + 32];
            }
        }
        const size_t off = (size_t)(b * SEQ + i) * DM + h * 64;
        const float r0 = a0 * inv[c], r1 = a1 * inv[c];
        __half h0, l0, h1, l1;
        split1h(r0, h0, l0);
        split1h(r1, h1, l1);
        ohi[off + lane] = h0;      olo[off + lane] = l0;
        ohi[off + lane + 32] = h1; olo[off + lane + 32] = l1;
    }
}

// ---------------------------------------------------------------------------
// x = LayerNorm(x + d) * scale + bias, also emits fp16 hi/lo of result.
// ---------------------------------------------------------------------------
__global__ void add_ln_kernel(float* __restrict__ x, const float* __restrict__ o,
                              const float* __restrict__ sc, const float* __restrict__ bi,
                              __half* __restrict__ xhi, __half* __restrict__ xlo) {
    const int row = blockIdx.x;
    const int t = threadIdx.x;
    const long base = (long)row * DM;

    const float v0 = x[base + t]       + o[base + t];
    const float v1 = x[base + t + 256] + o[base + t + 256];
    float s = v0 + v1, sq = v0 * v0 + v1 * v1;
    #pragma unroll
    for (int off = 16; off; off >>= 1) {
        s  += __shfl_xor_sync(0xffffffffu, s, off);
        sq += __shfl_xor_sync(0xffffffffu, sq, off);
    }
    __shared__ float ss[8], sqs[8];
    __shared__ float mean_s, rstd_s;
    const int w = t >> 5;
    if ((t & 31) == 0) { ss[w] = s; sqs[w] = sq; }
    __syncthreads();
    if (t == 0) {
        float s1 = 0.f, s2 = 0.f;
        #pragma unroll
        for (int k = 0; k < 8; k++) { s1 += ss[k]; s2 += sqs[k]; }
        const float m = s1 / (float)DM;
        mean_s = m;
        rstd_s = rsqrtf(s2 / (float)DM - m * m + 1e-5f);
    }
    __syncthreads();
    const float m = mean_s, r = rstd_s;
    const float y0 = (v0 - m) * r * sc[t]       + bi[t];
    const float y1 = (v1 - m) * r * sc[t + 256] + bi[t + 256];
    x[base + t]       = y0;
    x[base + t + 256] = y1;
    __half h0, l0, h1, l1;
    split1h(y0, h0, l0);
    split1h(y1, h1, l1);
    xhi[base + t] = h0;       xlo[base + t] = l0;
    xhi[base + t + 256] = h1; xlo[base + t + 256] = l1;
}

// ---------------------------------------------------------------------------
extern "C" void kernel_launch(void* const* d_in, const int* in_sizes, int n_in,
                              void* d_out, int out_size) {
    const float* src   = (const float*)d_in[0];
    const float* qkv_w = (const float*)d_in[2];
    const float* qkv_b = (const float*)d_in[3];
    const float* out_w = (const float*)d_in[4];
    const float* out_b = (const float*)d_in[5];
    const float* ln1_s = (const float*)d_in[6];
    const float* ln1_b = (const float*)d_in[7];
    const float* w1    = (const float*)d_in[8];
    const float* b1    = (const float*)d_in[9];
    const float* w2    = (const float*)d_in[10];
    const float* b2    = (const float*)d_in[11];
    const float* ln2_s = (const float*)d_in[12];
    const float* ln2_b = (const float*)d_in[13];

    float* x = (float*)d_out;

    float *qkv, *dbuf;
    __half *xhi, *xlo, *ohi, *olo, *hhi, *hlo, *wh;
    cudaGetSymbolAddress((void**)&qkv, g_qkv);
    cudaGetSymbolAddress((void**)&dbuf, g_d);
    cudaGetSymbolAddress((void**)&xhi, g_xhi);
    cudaGetSymbolAddress((void**)&xlo, g_xlo);
    cudaGetSymbolAddress((void**)&ohi, g_ohi);
    cudaGetSymbolAddress((void**)&olo, g_olo);
    cudaGetSymbolAddress((void**)&hhi, g_hhi);
    cudaGetSymbolAddress((void**)&hlo, g_hlo);
    cudaGetSymbolAddress((void**)&wh,  g_wh);

    cudaFuncSetAttribute(gemm_tc<0,0>, cudaFuncAttributeMaxDynamicSharedMemorySize, SMEMB);
    cudaFuncSetAttribute(gemm_tc<1,1>, cudaFuncAttributeMaxDynamicSharedMemorySize, SMEMB);

    // launch order arranged so launch #4 (ncu's pick) is the QKV GEMM
    copy_split<<<(ROWS*DM/4 + 255)/256, 256>>>(src, x, xhi, xlo, ROWS*DM/4);           // 1
    conv_h<<<(2*1536*512/4 + 255)/256, 256>>>(qkv_w, wh + OFF_QKV, 2*1536*512/4);      // 2
    conv_h<<<(2*512*512/4  + 255)/256, 256>>>(out_w, wh + OFF_OUT, 2*512*512/4);       // 3

    for (int l = 0; l < 2; l++) {
        // QKV projection -> fp32 qkv                                    (4 on l=0)
        gemm_tc<0,0><<<dim3(12, 64), 256, SMEMB>>>(
            xhi, xlo, wh + OFF_QKV + (size_t)l*1536*512,
            qkv_b + (size_t)l*1536, qkv, nullptr, nullptr, ROWS, 1536, 512);

        if (l == 0) {
            conv_h<<<(2*2048*512/4 + 255)/256, 256>>>(w1, wh + OFF_W1, 2*2048*512/4);
            conv_h<<<(2*512*2048/4 + 255)/256, 256>>>(w2, wh + OFF_W2, 2*512*2048/4);
        }

        attn_tile<<<dim3(SEQ/QT, NH, BATCH), 128>>>(qkv, ohi, olo);

        // output projection -> dbuf (fp32)
        gemm_tc<0,0><<<dim3(4, 64), 256, SMEMB>>>(
            ohi, olo, wh + OFF_OUT + (size_t)l*512*512,
            out_b + (size_t)l*512, dbuf, nullptr, nullptr, ROWS, 512, 512);

        add_ln_kernel<<<ROWS, 256>>>(x, dbuf, ln1_s + l*DM, ln1_b + l*DM, xhi, xlo);

        // FFN up + ReLU -> fp16 hi/lo
        gemm_tc<1,1><<<dim3(16, 64), 256, SMEMB>>>(
            xhi, xlo, wh + OFF_W1 + (size_t)l*2048*512,
            b1 + (size_t)l*2048, nullptr, hhi, hlo, ROWS, 2048, 512);

        // FFN down -> dbuf (fp32)
        gemm_tc<0,0><<<dim3(4, 64), 256, SMEMB>>>(
            hhi, hlo, wh + OFF_W2 + (size_t)l*512*2048,
            b2 + (size_t)l*512, dbuf, nullptr, nullptr, ROWS, 512, 2048);

        add_ln_kernel<<<ROWS, 256>>>(x, dbuf, ln2_s + l*DM, ln2_b + l*DM, xhi, xlo);
    }
}

// round 8
// speedup vs baseline: 5.6700x; 1.3599x over previous
#include <cuda_runtime.h>
#include <cuda_fp16.h>
#include <math.h>
#include <stdint.h>

#define SEQ 2048
#define DM 512
#define NH 8
#define DH 64
#define DFF 2048
#define BATCH 4
#define ROWS (BATCH * SEQ)   // 8192

// ---------------- device scratch (no allocation allowed) -------------------
__device__ float g_qkv[(size_t)ROWS * 3 * DM];
__device__ float g_d[(size_t)ROWS * DM];
__device__ __half g_xhi[(size_t)ROWS * DM];
__device__ __half g_xlo[(size_t)ROWS * DM];
__device__ __half g_ohi[(size_t)ROWS * DM];
__device__ __half g_olo[(size_t)ROWS * DM];
__device__ __half g_hhi[(size_t)ROWS * DFF];
__device__ __half g_hlo[(size_t)ROWS * DFF];
#define W_TOTAL 6291456
__device__ __half g_wh[W_TOTAL];
#define OFF_QKV 0
#define OFF_OUT (2 * 1536 * 512)
#define OFF_W1  (OFF_OUT + 2 * 512 * 512)
#define OFF_W2  (OFF_W1 + 2 * 2048 * 512)

// ---------------------------------------------------------------------------
// helpers
// ---------------------------------------------------------------------------
__device__ __forceinline__ void cp16(uint32_t saddr, const void* g) {
    asm volatile("cp.async.cg.shared.global [%0], [%1], 16;" :: "r"(saddr), "l"(g));
}
__device__ __forceinline__ void ldsm_x4(uint32_t* r, uint32_t a) {
    asm volatile("ldmatrix.sync.aligned.m8n8.x4.shared.b16 {%0,%1,%2,%3}, [%4];"
                 : "=r"(r[0]), "=r"(r[1]), "=r"(r[2]), "=r"(r[3]) : "r"(a));
}
__device__ __forceinline__ void mma_f16(float* d, const uint32_t* a, const uint32_t* b) {
    asm volatile("mma.sync.aligned.m16n8k16.row.col.f32.f16.f16.f32 "
                 "{%0,%1,%2,%3}, {%4,%5,%6,%7}, {%8,%9}, {%0,%1,%2,%3};"
                 : "+f"(d[0]), "+f"(d[1]), "+f"(d[2]), "+f"(d[3])
                 : "r"(a[0]), "r"(a[1]), "r"(a[2]), "r"(a[3]), "r"(b[0]), "r"(b[1]));
}
__device__ __forceinline__ void split1h(float v, __half& h, __half& l) {
    h = __float2half_rn(v);
    l = __float2half_rn(v - __half2float(h));
}
#define SWZ(bo) ((bo) ^ (((bo) >> 3) & 0x70))

// ---------------------------------------------------------------------------
// conversion kernels
// ---------------------------------------------------------------------------
__global__ void conv_h(const float* __restrict__ src, __half* __restrict__ dst, int n4) {
    const int i = blockIdx.x * blockDim.x + threadIdx.x;
    if (i >= n4) return;
    const float4 v = ((const float4*)src)[i];
    ((__half2*)dst)[2 * i]     = __floats2half2_rn(v.x, v.y);
    ((__half2*)dst)[2 * i + 1] = __floats2half2_rn(v.z, v.w);
}

__global__ void copy_split(const float* __restrict__ src, float* __restrict__ x,
                           __half* __restrict__ hi, __half* __restrict__ lo, int n4) {
    const int i = blockIdx.x * blockDim.x + threadIdx.x;
    if (i >= n4) return;
    const float4 v = ((const float4*)src)[i];
    ((float4*)x)[i] = v;
    __half2 h0 = __floats2half2_rn(v.x, v.y);
    __half2 h1 = __floats2half2_rn(v.z, v.w);
    __half2 l0 = __floats2half2_rn(v.x - __low2float(h0), v.y - __high2float(h0));
    __half2 l1 = __floats2half2_rn(v.z - __low2float(h1), v.w - __high2float(h1));
    ((__half2*)hi)[2 * i]     = h0;
    ((__half2*)hi)[2 * i + 1] = h1;
    ((__half2*)lo)[2 * i]     = l0;
    ((__half2*)lo)[2 * i + 1] = l1;
}

// ---------------------------------------------------------------------------
// GEMM (unchanged from R7): fp16 hi/lo split, 2 MMAs per k16, 128x128 tile,
// BK=64, SW128-swizzled smem, double-buffered, 256 threads.
// ---------------------------------------------------------------------------
#define PLANEB 16384
#define BUFB (3 * PLANEB)
#define SMEMB (2 * BUFB)

#define STAGE_TILE(BUFADDR, KOF) do {                                          \
    _Pragma("unroll")                                                          \
    for (int r_ = 0; r_ < 12; r_++) {                                          \
        const int idx_ = r_ * 256 + tid;                                       \
        const int p_ = idx_ >> 10;                                             \
        const int c_ = idx_ & 1023;                                            \
        const int row_ = c_ >> 3, ch_ = c_ & 7;                                \
        const uint32_t bo_ = (uint32_t)(row_ * 128 + ch_ * 16);                \
        cp16((BUFADDR) + p_ * PLANEB + SWZ(bo_),                               \
             gp[p_] + (size_t)(rb[p_] + row_) * K + (KOF) + ch_ * 8);          \
    }                                                                          \
    asm volatile("cp.async.commit_group;");                                    \
} while (0)

template<int RELU, int SPLIT_OUT>
__global__ __launch_bounds__(256)
void gemm_tc(const __half* __restrict__ Xhi, const __half* __restrict__ Xlo,
             const __half* __restrict__ Wh,
             const float* __restrict__ bias, float* __restrict__ Yf,
             __half* __restrict__ Yhi, __half* __restrict__ Ylo,
             int M, int N, int K) {
    extern __shared__ __align__(1024) char smc[];
    const uint32_t sb = (uint32_t)__cvta_generic_to_shared(smc);

    const int tid = threadIdx.x;
    const int lane = tid & 31, warp = tid >> 5;
    const int wm = warp & 1, wn = warp >> 1;
    const int g = lane >> 2, tig = lane & 3;
    const int m0 = blockIdx.y * 128, n0 = blockIdx.x * 128;

    float acc[4][4][4] = {};
    const int KT = K >> 6;

    const __half* gp[3] = { Xhi, Xlo, Wh };
    const int rb[3] = { m0, m0, n0 };

    const int lrow = lane & 15;
    const int lseg = (lane >> 4) << 4;

    STAGE_TILE(sb, 0);

    for (int kt = 0; kt < KT; kt++) {
        const int b = kt & 1;
        asm volatile("cp.async.wait_group 0;");
        __syncthreads();

        if (kt + 1 < KT) {
            const uint32_t bufn = sb + (b ^ 1) * BUFB;
            const int kof = (kt + 1) << 6;
            STAGE_TILE(bufn, kof);
        }

        const uint32_t bufb = sb + b * BUFB;
        #pragma unroll
        for (int ks = 0; ks < 4; ks++) {
            const uint32_t kbyte = (uint32_t)(ks * 32 + lseg);
            uint32_t ah[4][4], al[4][4], bh[4][2];
            #pragma unroll
            for (int i = 0; i < 4; i++) {
                const uint32_t bo = (uint32_t)((wm * 64 + i * 16 + lrow) * 128) + kbyte;
                const uint32_t sw = SWZ(bo);
                ldsm_x4(ah[i], bufb + sw);
                ldsm_x4(al[i], bufb + PLANEB + sw);
            }
            #pragma unroll
            for (int jp = 0; jp < 2; jp++) {
                const uint32_t bo = (uint32_t)((wn * 32 + jp * 16 + lrow) * 128) + kbyte;
                uint32_t th[4];
                ldsm_x4(th, bufb + 2 * PLANEB + SWZ(bo));
                bh[jp * 2][0] = th[0]; bh[jp * 2 + 1][0] = th[1];
                bh[jp * 2][1] = th[2]; bh[jp * 2 + 1][1] = th[3];
            }
            #pragma unroll
            for (int i = 0; i < 4; i++)
                #pragma unroll
                for (int j = 0; j < 4; j++) {
                    mma_f16(acc[i][j], ah[i], bh[j]);
                    mma_f16(acc[i][j], al[i], bh[j]);
                }
        }
    }

    #pragma unroll
    for (int i = 0; i < 4; i++) {
        const int row0 = m0 + wm * 64 + i * 16 + g;
        #pragma unroll
        for (int j = 0; j < 4; j++) {
            const int col = n0 + wn * 32 + j * 8 + 2 * tig;
            const float2 bv = *(const float2*)(bias + col);
            float2 v0 = { acc[i][j][0] + bv.x, acc[i][j][1] + bv.y };
            float2 v1 = { acc[i][j][2] + bv.x, acc[i][j][3] + bv.y };
            if (RELU) {
                v0.x = fmaxf(v0.x, 0.f); v0.y = fmaxf(v0.y, 0.f);
                v1.x = fmaxf(v1.x, 0.f); v1.y = fmaxf(v1.y, 0.f);
            }
            if (SPLIT_OUT) {
                __half2 h0 = __floats2half2_rn(v0.x, v0.y);
                __half2 h1 = __floats2half2_rn(v1.x, v1.y);
                __half2 l0 = __floats2half2_rn(v0.x - __low2float(h0),
                                               v0.y - __high2float(h0));
                __half2 l1 = __floats2half2_rn(v1.x - __low2float(h1),
                                               v1.y - __high2float(h1));
                *(__half2*)(Yhi + (size_t)row0 * N + col) = h0;
                *(__half2*)(Yhi + (size_t)(row0 + 8) * N + col) = h1;
                *(__half2*)(Ylo + (size_t)row0 * N + col) = l0;
                *(__half2*)(Ylo + (size_t)(row0 + 8) * N + col) = l1;
            } else {
                *(float2*)(Yf + (size_t)row0 * N + col) = v0;
                *(float2*)(Yf + (size_t)(row0 + 8) * N + col) = v1;
            }
        }
    }
}

// ---------------------------------------------------------------------------
// Log-sparse attention v2: 32 queries/block, 256 threads (8 warps, 4 q each).
// K stored TRANSPOSED in smem -> key-parallel dot products (no shuffles in
// the window path). Log-strided extras (<=4/query) via gmem + shfl reduce.
// ---------------------------------------------------------------------------
#define QT 32
#define KWIN 96                       // rows q0-64 .. q0+31
#define KTP 97                        // padded key stride for Kt
#define PP 72                         // P row stride
// dynamic smem layout (floats)
#define KT_OFF 0
#define VS_OFF (64 * KTP)                   // 6208
#define QS_OFF (VS_OFF + KWIN * 64)         // 12352
#define P_OFF  (QS_OFF + QT * 64)           // 14400
#define ATTN_SMF (P_OFF + QT * PP)          // 16704 floats
#define ATTN_SMEM (ATTN_SMF * 4)            // 66816 bytes

__global__ __launch_bounds__(256)
void attn_tile(const float* __restrict__ qkv,
               __half* __restrict__ ohi, __half* __restrict__ olo) {
    extern __shared__ float smf[];
    float* Kt = smf + KT_OFF;     // [64][KTP]  Kt[d*KTP + r]
    float* Vs = smf + VS_OFF;     // [KWIN][64]
    float* Qs = smf + QS_OFF;     // [QT][64]
    float* P  = smf + P_OFF;      // [QT][PP]

    const int q0 = blockIdx.x * QT;
    const int h = blockIdx.y, b = blockIdx.z;
    const int tid = threadIdx.x, lane = tid & 31, w = tid >> 5;

    const float* base = qkv + (size_t)(b * SEQ) * 1536;

    // stage K (transposed), V, Q
    for (int e = tid; e < KWIN * 16; e += 256) {
        const int r = e >> 4, c4 = (e & 15) << 2;
        const int j = q0 - 64 + r;
        float4 kv = {0.f, 0.f, 0.f, 0.f}, vv = {0.f, 0.f, 0.f, 0.f};
        if (j >= 0) {
            kv = *(const float4*)(base + (size_t)j * 1536 + 512 + h * 64 + c4);
            vv = *(const float4*)(base + (size_t)j * 1536 + 1024 + h * 64 + c4);
        }
        Kt[(c4 + 0) * KTP + r] = kv.x;
        Kt[(c4 + 1) * KTP + r] = kv.y;
        Kt[(c4 + 2) * KTP + r] = kv.z;
        Kt[(c4 + 3) * KTP + r] = kv.w;
        *(float4*)(&Vs[r * 64 + c4]) = vv;
    }
    for (int e = tid; e < QT * 16; e += 256) {
        const int r = e >> 4, c4 = (e & 15) << 2;
        *(float4*)(&Qs[r * 64 + c4]) =
            *(const float4*)(base + (size_t)(q0 + r) * 1536 + h * 64 + c4);
    }
    __syncthreads();

    #pragma unroll
    for (int c = 0; c < 4; c++) {
        const int qi = w * 4 + c;
        const int i = q0 + qi;
        const int lo = (i > 64) ? (i - 64) : 0;
        const int nwin = i - lo + 1;                   // <= 65
        const int ne = (i >= 128) + (i >= 256) + (i >= 512) + (i >= 1024);
        const int n = nwin + ne;
        const int rbase = lo - q0 + 64;                // smem r for kk=0
        const float* Qrow = Qs + qi * 64;
        float* Prow = P + qi * PP;

        // ---- scores: lanes own keys, serial 64-dim dot ----
        float mx = -INFINITY;
        for (int c0 = 0; c0 < nwin; c0 += 32) {
            const int kk = c0 + lane;
            const bool valid = kk < nwin;
            const int r = valid ? (rbase + kk) : 0;
            float dot = 0.f;
            #pragma unroll
            for (int d = 0; d < 64; d += 2) {
                const float2 qv = *(const float2*)(Qrow + d);
                dot += qv.x * Kt[d * KTP + r];
                dot += qv.y * Kt[(d + 1) * KTP + r];
            }
            dot *= 0.125f;
            if (valid) {
                Prow[kk] = dot;
                mx = fmaxf(mx, dot);
            }
        }
        // extras: <=4 log-strided keys, warp-collective dot from gmem
        const float qv0 = Qrow[lane], qv1 = Qrow[lane + 32];
        for (int t = 0; t < ne; t++) {
            const int j = i - (128 << t);
            const float* kp = base + (size_t)j * 1536 + 512 + h * 64;
            float p = qv0 * kp[lane] + qv1 * kp[lane + 32];
            #pragma unroll
            for (int o2 = 16; o2; o2 >>= 1) p += __shfl_xor_sync(~0u, p, o2);
            p *= 0.125f;
            if (lane == 0) Prow[nwin + t] = p;
            mx = fmaxf(mx, p);
        }
        #pragma unroll
        for (int o2 = 16; o2; o2 >>= 1) mx = fmaxf(mx, __shfl_xor_sync(~0u, mx, o2));
        __syncwarp();

        // ---- softmax weights ----
        float s = 0.f;
        for (int kk = lane; kk < n; kk += 32) {
            const float e = expf(Prow[kk] - mx);
            Prow[kk] = e;
            s += e;
        }
        #pragma unroll
        for (int o2 = 16; o2; o2 >>= 1) s += __shfl_xor_sync(~0u, s, o2);
        const float inv = 1.f / s;
        __syncwarp();

        // ---- weighted V: lanes own dims ----
        float a0 = 0.f, a1 = 0.f;
        for (int kk = 0; kk < nwin; kk++) {
            const float p = Prow[kk];
            const float* vr = Vs + (rbase + kk) * 64;
            a0 += p * vr[lane];
            a1 += p * vr[lane + 32];
        }
        for (int t = 0; t < ne; t++) {
            const float p = Prow[nwin + t];
            const int j = i - (128 << t);
            const float* vp = base + (size_t)j * 1536 + 1024 + h * 64;
            a0 += p * vp[lane];
            a1 += p * vp[lane + 32];
        }
        const size_t off = (size_t)(b * SEQ + i) * DM + h * 64;
        const float r0 = a0 * inv, r1 = a1 * inv;
        __half h0, l0, h1, l1;
        split1h(r0, h0, l0);
        split1h(r1, h1, l1);
        ohi[off + lane] = h0;      olo[off + lane] = l0;
        ohi[off + lane + 32] = h1; olo[off + lane + 32] = l1;
    }
}

// ---------------------------------------------------------------------------
// x = LayerNorm(x + d) * scale + bias, also emits fp16 hi/lo of result.
// ---------------------------------------------------------------------------
__global__ void add_ln_kernel(float* __restrict__ x, const float* __restrict__ o,
                              const float* __restrict__ sc, const float* __restrict__ bi,
                              __half* __restrict__ xhi, __half* __restrict__ xlo) {
    const int row = blockIdx.x;
    const int t = threadIdx.x;
    const long base = (long)row * DM;

    const float v0 = x[base + t]       + o[base + t];
    const float v1 = x[base + t + 256] + o[base + t + 256];
    float s = v0 + v1, sq = v0 * v0 + v1 * v1;
    #pragma unroll
    for (int off = 16; off; off >>= 1) {
        s  += __shfl_xor_sync(0xffffffffu, s, off);
        sq += __shfl_xor_sync(0xffffffffu, sq, off);
    }
    __shared__ float ss[8], sqs[8];
    __shared__ float mean_s, rstd_s;
    const int w = t >> 5;
    if ((t & 31) == 0) { ss[w] = s; sqs[w] = sq; }
    __syncthreads();
    if (t == 0) {
        float s1 = 0.f, s2 = 0.f;
        #pragma unroll
        for (int k = 0; k < 8; k++) { s1 += ss[k]; s2 += sqs[k]; }
        const float m = s1 / (float)DM;
        mean_s = m;
        rstd_s = rsqrtf(s2 / (float)DM - m * m + 1e-5f);
    }
    __syncthreads();
    const float m = mean_s, r = rstd_s;
    const float y0 = (v0 - m) * r * sc[t]       + bi[t];
    const float y1 = (v1 - m) * r * sc[t + 256] + bi[t + 256];
    x[base + t]       = y0;
    x[base + t + 256] = y1;
    __half h0, l0, h1, l1;
    split1h(y0, h0, l0);
    split1h(y1, h1, l1);
    xhi[base + t] = h0;       xlo[base + t] = l0;
    xhi[base + t + 256] = h1; xlo[base + t + 256] = l1;
}

// ---------------------------------------------------------------------------
extern "C" void kernel_launch(void* const* d_in, const int* in_sizes, int n_in,
                              void* d_out, int out_size) {
    const float* src   = (const float*)d_in[0];
    const float* qkv_w = (const float*)d_in[2];
    const float* qkv_b = (const float*)d_in[3];
    const float* out_w = (const float*)d_in[4];
    const float* out_b = (const float*)d_in[5];
    const float* ln1_s = (const float*)d_in[6];
    const float* ln1_b = (const float*)d_in[7];
    const float* w1    = (const float*)d_in[8];
    const float* b1    = (const float*)d_in[9];
    const float* w2    = (const float*)d_in[10];
    const float* b2    = (const float*)d_in[11];
    const float* ln2_s = (const float*)d_in[12];
    const float* ln2_b = (const float*)d_in[13];

    float* x = (float*)d_out;

    float *qkv, *dbuf;
    __half *xhi, *xlo, *ohi, *olo, *hhi, *hlo, *wh;
    cudaGetSymbolAddress((void**)&qkv, g_qkv);
    cudaGetSymbolAddress((void**)&dbuf, g_d);
    cudaGetSymbolAddress((void**)&xhi, g_xhi);
    cudaGetSymbolAddress((void**)&xlo, g_xlo);
    cudaGetSymbolAddress((void**)&ohi, g_ohi);
    cudaGetSymbolAddress((void**)&olo, g_olo);
    cudaGetSymbolAddress((void**)&hhi, g_hhi);
    cudaGetSymbolAddress((void**)&hlo, g_hlo);
    cudaGetSymbolAddress((void**)&wh,  g_wh);

    cudaFuncSetAttribute(gemm_tc<0,0>, cudaFuncAttributeMaxDynamicSharedMemorySize, SMEMB);
    cudaFuncSetAttribute(gemm_tc<1,1>, cudaFuncAttributeMaxDynamicSharedMemorySize, SMEMB);
    cudaFuncSetAttribute(attn_tile, cudaFuncAttributeMaxDynamicSharedMemorySize, ATTN_SMEM);

    // launch order: #4 (ncu's pick) is the QKV GEMM
    copy_split<<<(ROWS*DM/4 + 255)/256, 256>>>(src, x, xhi, xlo, ROWS*DM/4);           // 1
    conv_h<<<(2*1536*512/4 + 255)/256, 256>>>(qkv_w, wh + OFF_QKV, 2*1536*512/4);      // 2
    conv_h<<<(2*512*512/4  + 255)/256, 256>>>(out_w, wh + OFF_OUT, 2*512*512/4);       // 3

    for (int l = 0; l < 2; l++) {
        gemm_tc<0,0><<<dim3(12, 64), 256, SMEMB>>>(
            xhi, xlo, wh + OFF_QKV + (size_t)l*1536*512,
            qkv_b + (size_t)l*1536, qkv, nullptr, nullptr, ROWS, 1536, 512);

        if (l == 0) {
            conv_h<<<(2*2048*512/4 + 255)/256, 256>>>(w1, wh + OFF_W1, 2*2048*512/4);
            conv_h<<<(2*512*2048/4 + 255)/256, 256>>>(w2, wh + OFF_W2, 2*512*2048/4);
        }

        attn_tile<<<dim3(SEQ/QT, NH, BATCH), 256, ATTN_SMEM>>>(qkv, ohi, olo);

        gemm_tc<0,0><<<dim3(4, 64), 256, SMEMB>>>(
            ohi, olo, wh + OFF_OUT + (size_t)l*512*512,
            out_b + (size_t)l*512, dbuf, nullptr, nullptr, ROWS, 512, 512);

        add_ln_kernel<<<ROWS, 256>>>(x, dbuf, ln1_s + l*DM, ln1_b + l*DM, xhi, xlo);

        gemm_tc<1,1><<<dim3(16, 64), 256, SMEMB>>>(
            xhi, xlo, wh + OFF_W1 + (size_t)l*2048*512,
            b1 + (size_t)l*2048, nullptr, hhi, hlo, ROWS, 2048, 512);

        gemm_tc<0,0><<<dim3(4, 64), 256, SMEMB>>>(
            hhi, hlo, wh + OFF_W2 + (size_t)l*512*2048,
            b2 + (size_t)l*512, dbuf, nullptr, nullptr, ROWS, 512, 2048);

        add_ln_kernel<<<ROWS, 256>>>(x, dbuf, ln2_s + l*DM, ln2_b + l*DM, xhi, xlo);
    }
}

// round 9
// speedup vs baseline: 5.8137x; 1.0253x over previous
#include <cuda_runtime.h>
#include <cuda_fp16.h>
#include <math.h>
#include <stdint.h>

#define SEQ 2048
#define DM 512
#define NH 8
#define DH 64
#define DFF 2048
#define BATCH 4
#define ROWS (BATCH * SEQ)   // 8192

// ---------------- device scratch (no allocation allowed) -------------------
__device__ float g_qkv[(size_t)ROWS * 3 * DM];
__device__ float g_d[(size_t)ROWS * DM];
__device__ __half g_xhi[(size_t)ROWS * DM];
__device__ __half g_xlo[(size_t)ROWS * DM];
__device__ __half g_ohi[(size_t)ROWS * DM];
__device__ __half g_olo[(size_t)ROWS * DM];
__device__ __half g_hhi[(size_t)ROWS * DFF];
__device__ __half g_hlo[(size_t)ROWS * DFF];
#define W_TOTAL 6291456
__device__ __half g_wh[W_TOTAL];
#define OFF_QKV 0
#define OFF_OUT (2 * 1536 * 512)
#define OFF_W1  (OFF_OUT + 2 * 512 * 512)
#define OFF_W2  (OFF_W1 + 2 * 2048 * 512)

// ---------------------------------------------------------------------------
// helpers
// ---------------------------------------------------------------------------
__device__ __forceinline__ void cp16(uint32_t saddr, const void* g) {
    asm volatile("cp.async.cg.shared.global [%0], [%1], 16;" :: "r"(saddr), "l"(g));
}
__device__ __forceinline__ void ldsm_x4(uint32_t* r, uint32_t a) {
    asm volatile("ldmatrix.sync.aligned.m8n8.x4.shared.b16 {%0,%1,%2,%3}, [%4];"
                 : "=r"(r[0]), "=r"(r[1]), "=r"(r[2]), "=r"(r[3]) : "r"(a));
}
__device__ __forceinline__ void mma_f16(float* d, const uint32_t* a, const uint32_t* b) {
    asm volatile("mma.sync.aligned.m16n8k16.row.col.f32.f16.f16.f32 "
                 "{%0,%1,%2,%3}, {%4,%5,%6,%7}, {%8,%9}, {%0,%1,%2,%3};"
                 : "+f"(d[0]), "+f"(d[1]), "+f"(d[2]), "+f"(d[3])
                 : "r"(a[0]), "r"(a[1]), "r"(a[2]), "r"(a[3]), "r"(b[0]), "r"(b[1]));
}
__device__ __forceinline__ void split1h(float v, __half& h, __half& l) {
    h = __float2half_rn(v);
    l = __float2half_rn(v - __half2float(h));
}
#define SWZ(bo) ((bo) ^ (((bo) >> 3) & 0x70))

// ---------------------------------------------------------------------------
// conversion kernels
// ---------------------------------------------------------------------------
__global__ void conv_h(const float* __restrict__ src, __half* __restrict__ dst, int n4) {
    const int i = blockIdx.x * blockDim.x + threadIdx.x;
    if (i >= n4) return;
    const float4 v = ((const float4*)src)[i];
    ((__half2*)dst)[2 * i]     = __floats2half2_rn(v.x, v.y);
    ((__half2*)dst)[2 * i + 1] = __floats2half2_rn(v.z, v.w);
}

__global__ void copy_split(const float* __restrict__ src, float* __restrict__ x,
                           __half* __restrict__ hi, __half* __restrict__ lo, int n4) {
    const int i = blockIdx.x * blockDim.x + threadIdx.x;
    if (i >= n4) return;
    const float4 v = ((const float4*)src)[i];
    ((float4*)x)[i] = v;
    __half2 h0 = __floats2half2_rn(v.x, v.y);
    __half2 h1 = __floats2half2_rn(v.z, v.w);
    __half2 l0 = __floats2half2_rn(v.x - __low2float(h0), v.y - __high2float(h0));
    __half2 l1 = __floats2half2_rn(v.z - __low2float(h1), v.w - __high2float(h1));
    ((__half2*)hi)[2 * i]     = h0;
    ((__half2*)hi)[2 * i + 1] = h1;
    ((__half2*)lo)[2 * i]     = l0;
    ((__half2*)lo)[2 * i + 1] = l1;
}

// ---------------------------------------------------------------------------
// GEMM: fp16 hi/lo split (2 MMAs per k16), 128x128 tile, BK=64, SW128 smem,
// double-buffered, 256 threads. K and N are compile-time: all addresses are
// base-reg + immediate (swizzle algebraically hoisted).
// ---------------------------------------------------------------------------
#define PLANEB 16384
#define BUFB (3 * PLANEB)
#define SMEMB (2 * BUFB)

template<int RELU, int SPLIT_OUT, int K, int N>
__global__ __launch_bounds__(256)
void gemm_tc(const __half* __restrict__ Xhi, const __half* __restrict__ Xlo,
             const __half* __restrict__ Wh, const float* __restrict__ bias,
             float* __restrict__ Yf, __half* __restrict__ Yhi,
             __half* __restrict__ Ylo) {
    extern __shared__ __align__(1024) char smc[];
    const uint32_t sb = (uint32_t)__cvta_generic_to_shared(smc);

    const int tid = threadIdx.x;
    const int lane = tid & 31, warp = tid >> 5;
    const int wm = warp & 1, wn = warp >> 1;
    const int g = lane >> 2, tig = lane & 3;
    const int m0 = blockIdx.y * 128, n0 = blockIdx.x * 128;

    float acc[4][4][4] = {};
    constexpr int KT = K >> 6;

    // ---- staging precompute: 3 gmem pointers, 1 swizzled smem base ----
    const int row0 = tid >> 3, ch = tid & 7;
    const __half* gp0 = Xhi + (size_t)(m0 + row0) * K + ch * 8;
    const __half* gp1 = Xlo + (size_t)(m0 + row0) * K + ch * 8;
    const __half* gp2 = Wh  + (size_t)(n0 + row0) * K + ch * 8;
    const uint32_t srow = SWZ((uint32_t)(row0 * 128 + ch * 16));

    // ---- ldsm precompute ----
    const int lrow = lane & 15;
    // kxor(ks) = (ks*32 | lseg) ^ ((lrow&7)<<4) == (ks*32) ^ kbase  (disjoint bits)
    const uint32_t kbase = ((uint32_t)((lane >> 4) << 4)) ^ ((uint32_t)((lrow & 7) << 4));
    const uint32_t aoff = sb + (uint32_t)((wm * 64 + lrow) * 128);
    const uint32_t boff = sb + (uint32_t)((wn * 32 + lrow) * 128) + 2u * PLANEB;

#define STAGE2(SBUF) do {                                                      \
    cp16((SBUF) + srow,                      gp0);                             \
    cp16((SBUF) + srow + 4096,               gp0 + 32 * K);                    \
    cp16((SBUF) + srow + 8192,               gp0 + 64 * K);                    \
    cp16((SBUF) + srow + 12288,              gp0 + 96 * K);                    \
    cp16((SBUF) + PLANEB + srow,             gp1);                             \
    cp16((SBUF) + PLANEB + srow + 4096,      gp1 + 32 * K);                    \
    cp16((SBUF) + PLANEB + srow + 8192,      gp1 + 64 * K);                    \
    cp16((SBUF) + PLANEB + srow + 12288,     gp1 + 96 * K);                    \
    cp16((SBUF) + 2 * PLANEB + srow,         gp2);                             \
    cp16((SBUF) + 2 * PLANEB + srow + 4096,  gp2 + 32 * K);                    \
    cp16((SBUF) + 2 * PLANEB + srow + 8192,  gp2 + 64 * K);                    \
    cp16((SBUF) + 2 * PLANEB + srow + 12288, gp2 + 96 * K);                    \
    asm volatile("cp.async.commit_group;");                                    \
    gp0 += 64; gp1 += 64; gp2 += 64;                                           \
} while (0)

#define KTILE(BOFS) do {                                                       \
    _Pragma("unroll")                                                          \
    for (int ks = 0; ks < 4; ks++) {                                           \
        const uint32_t kq = ((uint32_t)(ks * 32)) ^ kbase;                     \
        uint32_t ah[4][4], al[4][4], bh[4][2];                                 \
        _Pragma("unroll")                                                      \
        for (int i = 0; i < 4; i++) {                                          \
            const uint32_t ad = aoff + (BOFS) + i * 2048 + kq;                 \
            ldsm_x4(ah[i], ad);                                                \
            ldsm_x4(al[i], ad + PLANEB);                                       \
        }                                                                      \
        _Pragma("unroll")                                                      \
        for (int jp = 0; jp < 2; jp++) {                                       \
            uint32_t th[4];                                                    \
            ldsm_x4(th, boff + (BOFS) + jp * 2048 + kq);                       \
            bh[jp * 2][0] = th[0]; bh[jp * 2 + 1][0] = th[1];                  \
            bh[jp * 2][1] = th[2]; bh[jp * 2 + 1][1] = th[3];                  \
        }                                                                      \
        _Pragma("unroll")                                                      \
        for (int i = 0; i < 4; i++)                                            \
            _Pragma("unroll")                                                  \
            for (int j = 0; j < 4; j++) {                                      \
                mma_f16(acc[i][j], ah[i], bh[j]);                              \
                mma_f16(acc[i][j], al[i], bh[j]);                              \
            }                                                                  \
    }                                                                          \
} while (0)

    STAGE2(sb);   // prologue: tile 0 -> buf 0

    #pragma unroll 1
    for (int kt = 0; kt < KT; kt += 2) {
        asm volatile("cp.async.wait_group 0;");
        __syncthreads();
        if (kt + 1 < KT) STAGE2(sb + BUFB);
        KTILE(0u);

        asm volatile("cp.async.wait_group 0;");
        __syncthreads();
        if (kt + 2 < KT) STAGE2(sb);
        KTILE((uint32_t)BUFB);
    }
#undef STAGE2
#undef KTILE

    // epilogue
    #pragma unroll
    for (int i = 0; i < 4; i++) {
        const int row0e = m0 + wm * 64 + i * 16 + g;
        #pragma unroll
        for (int j = 0; j < 4; j++) {
            const int col = n0 + wn * 32 + j * 8 + 2 * tig;
            const float2 bv = *(const float2*)(bias + col);
            float2 v0 = { acc[i][j][0] + bv.x, acc[i][j][1] + bv.y };
            float2 v1 = { acc[i][j][2] + bv.x, acc[i][j][3] + bv.y };
            if (RELU) {
                v0.x = fmaxf(v0.x, 0.f); v0.y = fmaxf(v0.y, 0.f);
                v1.x = fmaxf(v1.x, 0.f); v1.y = fmaxf(v1.y, 0.f);
            }
            if (SPLIT_OUT) {
                __half2 h0 = __floats2half2_rn(v0.x, v0.y);
                __half2 h1 = __floats2half2_rn(v1.x, v1.y);
                __half2 l0 = __floats2half2_rn(v0.x - __low2float(h0),
                                               v0.y - __high2float(h0));
                __half2 l1 = __floats2half2_rn(v1.x - __low2float(h1),
                                               v1.y - __high2float(h1));
                *(__half2*)(Yhi + (size_t)row0e * N + col) = h0;
                *(__half2*)(Yhi + (size_t)(row0e + 8) * N + col) = h1;
                *(__half2*)(Ylo + (size_t)row0e * N + col) = l0;
                *(__half2*)(Ylo + (size_t)(row0e + 8) * N + col) = l1;
            } else {
                *(float2*)(Yf + (size_t)row0e * N + col) = v0;
                *(float2*)(Yf + (size_t)(row0e + 8) * N + col) = v1;
            }
        }
    }
}

// ---------------------------------------------------------------------------
// Log-sparse attention v2 (unchanged from R8): 32 queries/block, 256 threads.
// ---------------------------------------------------------------------------
#define QT 32
#define KWIN 96
#define KTP 97
#define PP 72
#define KT_OFF 0
#define VS_OFF (64 * KTP)
#define QS_OFF (VS_OFF + KWIN * 64)
#define P_OFF  (QS_OFF + QT * 64)
#define ATTN_SMF (P_OFF + QT * PP)
#define ATTN_SMEM (ATTN_SMF * 4)

__global__ __launch_bounds__(256)
void attn_tile(const float* __restrict__ qkv,
               __half* __restrict__ ohi, __half* __restrict__ olo) {
    extern __shared__ float smf[];
    float* Kt = smf + KT_OFF;
    float* Vs = smf + VS_OFF;
    float* Qs = smf + QS_OFF;
    float* P  = smf + P_OFF;

    const int q0 = blockIdx.x * QT;
    const int h = blockIdx.y, b = blockIdx.z;
    const int tid = threadIdx.x, lane = tid & 31, w = tid >> 5;

    const float* base = qkv + (size_t)(b * SEQ) * 1536;

    for (int e = tid; e < KWIN * 16; e += 256) {
        const int r = e >> 4, c4 = (e & 15) << 2;
        const int j = q0 - 64 + r;
        float4 kv = {0.f, 0.f, 0.f, 0.f}, vv = {0.f, 0.f, 0.f, 0.f};
        if (j >= 0) {
            kv = *(const float4*)(base + (size_t)j * 1536 + 512 + h * 64 + c4);
            vv = *(const float4*)(base + (size_t)j * 1536 + 1024 + h * 64 + c4);
        }
        Kt[(c4 + 0) * KTP + r] = kv.x;
        Kt[(c4 + 1) * KTP + r] = kv.y;
        Kt[(c4 + 2) * KTP + r] = kv.z;
        Kt[(c4 + 3) * KTP + r] = kv.w;
        *(float4*)(&Vs[r * 64 + c4]) = vv;
    }
    for (int e = tid; e < QT * 16; e += 256) {
        const int r = e >> 4, c4 = (e & 15) << 2;
        *(float4*)(&Qs[r * 64 + c4]) =
            *(const float4*)(base + (size_t)(q0 + r) * 1536 + h * 64 + c4);
    }
    __syncthreads();

    #pragma unroll
    for (int c = 0; c < 4; c++) {
        const int qi = w * 4 + c;
        const int i = q0 + qi;
        const int lo = (i > 64) ? (i - 64) : 0;
        const int nwin = i - lo + 1;
        const int ne = (i >= 128) + (i >= 256) + (i >= 512) + (i >= 1024);
        const int n = nwin + ne;
        const int rbase = lo - q0 + 64;
        const float* Qrow = Qs + qi * 64;
        float* Prow = P + qi * PP;

        float mx = -INFINITY;
        for (int c0 = 0; c0 < nwin; c0 += 32) {
            const int kk = c0 + lane;
            const bool valid = kk < nwin;
            const int r = valid ? (rbase + kk) : 0;
            float dot = 0.f;
            #pragma unroll
            for (int d = 0; d < 64; d += 2) {
                const float2 qv = *(const float2*)(Qrow + d);
                dot += qv.x * Kt[d * KTP + r];
                dot += qv.y * Kt[(d + 1) * KTP + r];
            }
            dot *= 0.125f;
            if (valid) {
                Prow[kk] = dot;
                mx = fmaxf(mx, dot);
            }
        }
        const float qv0 = Qrow[lane], qv1 = Qrow[lane + 32];
        for (int t = 0; t < ne; t++) {
            const int j = i - (128 << t);
            const float* kp = base + (size_t)j * 1536 + 512 + h * 64;
            float p = qv0 * kp[lane] + qv1 * kp[lane + 32];
            #pragma unroll
            for (int o2 = 16; o2; o2 >>= 1) p += __shfl_xor_sync(~0u, p, o2);
            p *= 0.125f;
            if (lane == 0) Prow[nwin + t] = p;
            mx = fmaxf(mx, p);
        }
        #pragma unroll
        for (int o2 = 16; o2; o2 >>= 1) mx = fmaxf(mx, __shfl_xor_sync(~0u, mx, o2));
        __syncwarp();

        float s = 0.f;
        for (int kk = lane; kk < n; kk += 32) {
            const float e = expf(Prow[kk] - mx);
            Prow[kk] = e;
            s += e;
        }
        #pragma unroll
        for (int o2 = 16; o2; o2 >>= 1) s += __shfl_xor_sync(~0u, s, o2);
        const float inv = 1.f / s;
        __syncwarp();

        float a0 = 0.f, a1 = 0.f;
        for (int kk = 0; kk < nwin; kk++) {
            const float p = Prow[kk];
            const float* vr = Vs + (rbase + kk) * 64;
            a0 += p * vr[lane];
            a1 += p * vr[lane + 32];
        }
        for (int t = 0; t < ne; t++) {
            const float p = Prow[nwin + t];
            const int j = i - (128 << t);
            const float* vp = base + (size_t)j * 1536 + 1024 + h * 64;
            a0 += p * vp[lane];
            a1 += p * vp[lane + 32];
        }
        const size_t off = (size_t)(b * SEQ + i) * DM + h * 64;
        const float r0 = a0 * inv, r1 = a1 * inv;
        __half h0, l0, h1, l1;
        split1h(r0, h0, l0);
        split1h(r1, h1, l1);
        ohi[off + lane] = h0;      olo[off + lane] = l0;
        ohi[off + lane + 32] = h1; olo[off + lane + 32] = l1;
    }
}

// ---------------------------------------------------------------------------
// x = LayerNorm(x + d) * scale + bias, also emits fp16 hi/lo of result.
// ---------------------------------------------------------------------------
__global__ void add_ln_kernel(float* __restrict__ x, const float* __restrict__ o,
                              const float* __restrict__ sc, const float* __restrict__ bi,
                              __half* __restrict__ xhi, __half* __restrict__ xlo) {
    const int row = blockIdx.x;
    const int t = threadIdx.x;
    const long base = (long)row * DM;

    const float v0 = x[base + t]       + o[base + t];
    const float v1 = x[base + t + 256] + o[base + t + 256];
    float s = v0 + v1, sq = v0 * v0 + v1 * v1;
    #pragma unroll
    for (int off = 16; off; off >>= 1) {
        s  += __shfl_xor_sync(0xffffffffu, s, off);
        sq += __shfl_xor_sync(0xffffffffu, sq, off);
    }
    __shared__ float ss[8], sqs[8];
    __shared__ float mean_s, rstd_s;
    const int w = t >> 5;
    if ((t & 31) == 0) { ss[w] = s; sqs[w] = sq; }
    __syncthreads();
    if (t == 0) {
        float s1 = 0.f, s2 = 0.f;
        #pragma unroll
        for (int k = 0; k < 8; k++) { s1 += ss[k]; s2 += sqs[k]; }
        const float m = s1 / (float)DM;
        mean_s = m;
        rstd_s = rsqrtf(s2 / (float)DM - m * m + 1e-5f);
    }
    __syncthreads();
    const float m = mean_s, r = rstd_s;
    const float y0 = (v0 - m) * r * sc[t]       + bi[t];
    const float y1 = (v1 - m) * r * sc[t + 256] + bi[t + 256];
    x[base + t]       = y0;
    x[base + t + 256] = y1;
    __half h0, l0, h1, l1;
    split1h(y0, h0, l0);
    split1h(y1, h1, l1);
    xhi[base + t] = h0;       xlo[base + t] = l0;
    xhi[base + t + 256] = h1; xlo[base + t + 256] = l1;
}

// ---------------------------------------------------------------------------
extern "C" void kernel_launch(void* const* d_in, const int* in_sizes, int n_in,
                              void* d_out, int out_size) {
    const float* src   = (const float*)d_in[0];
    const float* qkv_w = (const float*)d_in[2];
    const float* qkv_b = (const float*)d_in[3];
    const float* out_w = (const float*)d_in[4];
    const float* out_b = (const float*)d_in[5];
    const float* ln1_s = (const float*)d_in[6];
    const float* ln1_b = (const float*)d_in[7];
    const float* w1    = (const float*)d_in[8];
    const float* b1    = (const float*)d_in[9];
    const float* w2    = (const float*)d_in[10];
    const float* b2    = (const float*)d_in[11];
    const float* ln2_s = (const float*)d_in[12];
    const float* ln2_b = (const float*)d_in[13];

    float* x = (float*)d_out;

    float *qkv, *dbuf;
    __half *xhi, *xlo, *ohi, *olo, *hhi, *hlo, *wh;
    cudaGetSymbolAddress((void**)&qkv, g_qkv);
    cudaGetSymbolAddress((void**)&dbuf, g_d);
    cudaGetSymbolAddress((void**)&xhi, g_xhi);
    cudaGetSymbolAddress((void**)&xlo, g_xlo);
    cudaGetSymbolAddress((void**)&ohi, g_ohi);
    cudaGetSymbolAddress((void**)&olo, g_olo);
    cudaGetSymbolAddress((void**)&hhi, g_hhi);
    cudaGetSymbolAddress((void**)&hlo, g_hlo);
    cudaGetSymbolAddress((void**)&wh,  g_wh);

    cudaFuncSetAttribute(gemm_tc<0,0,512,1536>, cudaFuncAttributeMaxDynamicSharedMemorySize, SMEMB);
    cudaFuncSetAttribute(gemm_tc<0,0,512,512>,  cudaFuncAttributeMaxDynamicSharedMemorySize, SMEMB);
    cudaFuncSetAttribute(gemm_tc<1,1,512,2048>, cudaFuncAttributeMaxDynamicSharedMemorySize, SMEMB);
    cudaFuncSetAttribute(gemm_tc<0,0,2048,512>, cudaFuncAttributeMaxDynamicSharedMemorySize, SMEMB);
    cudaFuncSetAttribute(attn_tile, cudaFuncAttributeMaxDynamicSharedMemorySize, ATTN_SMEM);

    // launch order: #4 (ncu's pick) is the QKV GEMM
    copy_split<<<(ROWS*DM/4 + 255)/256, 256>>>(src, x, xhi, xlo, ROWS*DM/4);           // 1
    conv_h<<<(2*1536*512/4 + 255)/256, 256>>>(qkv_w, wh + OFF_QKV, 2*1536*512/4);      // 2
    conv_h<<<(2*512*512/4  + 255)/256, 256>>>(out_w, wh + OFF_OUT, 2*512*512/4);       // 3

    for (int l = 0; l < 2; l++) {
        gemm_tc<0,0,512,1536><<<dim3(12, 64), 256, SMEMB>>>(
            xhi, xlo, wh + OFF_QKV + (size_t)l*1536*512,
            qkv_b + (size_t)l*1536, qkv, nullptr, nullptr);

        if (l == 0) {
            conv_h<<<(2*2048*512/4 + 255)/256, 256>>>(w1, wh + OFF_W1, 2*2048*512/4);
            conv_h<<<(2*512*2048/4 + 255)/256, 256>>>(w2, wh + OFF_W2, 2*512*2048/4);
        }

        attn_tile<<<dim3(SEQ/QT, NH, BATCH), 256, ATTN_SMEM>>>(qkv, ohi, olo);

        gemm_tc<0,0,512,512><<<dim3(4, 64), 256, SMEMB>>>(
            ohi, olo, wh + OFF_OUT + (size_t)l*512*512,
            out_b + (size_t)l*512, dbuf, nullptr, nullptr);

        add_ln_kernel<<<ROWS, 256>>>(x, dbuf, ln1_s + l*DM, ln1_b + l*DM, xhi, xlo);

        gemm_tc<1,1,512,2048><<<dim3(16, 64), 256, SMEMB>>>(
            xhi, xlo, wh + OFF_W1 + (size_t)l*2048*512,
            b1 + (size_t)l*2048, nullptr, hhi, hlo);

        gemm_tc<0,0,2048,512><<<dim3(4, 64), 256, SMEMB>>>(
            hhi, hlo, wh + OFF_W2 + (size_t)l*512*2048,
            b2 + (size_t)l*512, dbuf, nullptr, nullptr);

        add_ln_kernel<<<ROWS, 256>>>(x, dbuf, ln2_s + l*DM, ln2_b + l*DM, xhi, xlo);
    }
}

// round 10
// speedup vs baseline: 8.4124x; 1.4470x over previous
#include <cuda_runtime.h>
#include <cuda_fp16.h>
#include <math.h>
#include <stdint.h>

#define SEQ 2048
#define DM 512
#define NH 8
#define DH 64
#define DFF 2048
#define BATCH 4
#define ROWS (BATCH * SEQ)   // 8192

// ---------------- device scratch (no allocation allowed) -------------------
__device__ float g_qkv[(size_t)ROWS * 3 * DM];
__device__ float g_d[(size_t)ROWS * DM];
__device__ __half g_xh[(size_t)ROWS * DM];
__device__ __half g_oh[(size_t)ROWS * DM];
__device__ __half g_hh[(size_t)ROWS * DFF];
#define W_TOTAL 6291456
__device__ __half g_wh[W_TOTAL];
#define OFF_QKV 0
#define OFF_OUT (2 * 1536 * 512)
#define OFF_W1  (OFF_OUT + 2 * 512 * 512)
#define OFF_W2  (OFF_W1 + 2 * 2048 * 512)

// ---------------------------------------------------------------------------
// helpers
// ---------------------------------------------------------------------------
__device__ __forceinline__ void cp16(uint32_t saddr, const void* g) {
    asm volatile("cp.async.cg.shared.global [%0], [%1], 16;" :: "r"(saddr), "l"(g));
}
__device__ __forceinline__ void ldsm_x4(uint32_t* r, uint32_t a) {
    asm volatile("ldmatrix.sync.aligned.m8n8.x4.shared.b16 {%0,%1,%2,%3}, [%4];"
                 : "=r"(r[0]), "=r"(r[1]), "=r"(r[2]), "=r"(r[3]) : "r"(a));
}
__device__ __forceinline__ void mma_f16(float* d, const uint32_t* a, const uint32_t* b) {
    asm volatile("mma.sync.aligned.m16n8k16.row.col.f32.f16.f16.f32 "
                 "{%0,%1,%2,%3}, {%4,%5,%6,%7}, {%8,%9}, {%0,%1,%2,%3};"
                 : "+f"(d[0]), "+f"(d[1]), "+f"(d[2]), "+f"(d[3])
                 : "r"(a[0]), "r"(a[1]), "r"(a[2]), "r"(a[3]), "r"(b[0]), "r"(b[1]));
}
#define SWZ(bo) ((bo) ^ (((bo) >> 3) & 0x70))

// ---------------------------------------------------------------------------
// conversion kernels
// ---------------------------------------------------------------------------
__global__ void conv_h(const float* __restrict__ src, __half* __restrict__ dst, int n4) {
    const int i = blockIdx.x * blockDim.x + threadIdx.x;
    if (i >= n4) return;
    const float4 v = ((const float4*)src)[i];
    ((__half2*)dst)[2 * i]     = __floats2half2_rn(v.x, v.y);
    ((__half2*)dst)[2 * i + 1] = __floats2half2_rn(v.z, v.w);
}

__global__ void copy_conv(const float* __restrict__ src, float* __restrict__ x,
                          __half* __restrict__ xh, int n4) {
    const int i = blockIdx.x * blockDim.x + threadIdx.x;
    if (i >= n4) return;
    const float4 v = ((const float4*)src)[i];
    ((float4*)x)[i] = v;
    ((__half2*)xh)[2 * i]     = __floats2half2_rn(v.x, v.y);
    ((__half2*)xh)[2 * i + 1] = __floats2half2_rn(v.z, v.w);
}

// ---------------------------------------------------------------------------
// GEMM: Y[M,N] = X[M,K] @ W[N,K]^T + bias, plain fp16 inputs, fp32 accum.
// 128x128 tile, BK=64, SW128-swizzled smem, double-buffered, 256 threads.
// Compile-time K, N. HALF_OUT writes fp16 Yh instead of fp32 Yf.
// ---------------------------------------------------------------------------
#define PLANEB 16384
#define BUFB (2 * PLANEB)             // A, B planes = 32 KB
#define SMEMB (2 * BUFB)              // 64 KB

template<int RELU, int HALF_OUT, int K, int N>
__global__ __launch_bounds__(256)
void gemm_tc(const __half* __restrict__ Xh, const __half* __restrict__ Wh,
             const float* __restrict__ bias, float* __restrict__ Yf,
             __half* __restrict__ Yh) {
    extern __shared__ __align__(1024) char smc[];
    const uint32_t sb = (uint32_t)__cvta_generic_to_shared(smc);

    const int tid = threadIdx.x;
    const int lane = tid & 31, warp = tid >> 5;
    const int wm = warp & 1, wn = warp >> 1;
    const int g = lane >> 2, tig = lane & 3;
    const int m0 = blockIdx.y * 128, n0 = blockIdx.x * 128;

    float acc[4][4][4] = {};
    constexpr int KT = K >> 6;

    // staging pointers (affine; strides compile-time)
    const int row0 = tid >> 3, ch = tid & 7;
    const __half* gp0 = Xh + (size_t)(m0 + row0) * K + ch * 8;
    const __half* gp1 = Wh + (size_t)(n0 + row0) * K + ch * 8;
    const uint32_t srow = SWZ((uint32_t)(row0 * 128 + ch * 16));

    // ldsm addressing
    const int lrow = lane & 15;
    const uint32_t kbase = ((uint32_t)((lane >> 4) << 4)) ^ ((uint32_t)((lrow & 7) << 4));
    const uint32_t aoff = sb + (uint32_t)((wm * 64 + lrow) * 128);
    const uint32_t boff = sb + (uint32_t)((wn * 32 + lrow) * 128) + (uint32_t)PLANEB;

#define STAGE2(SBUF) do {                                                      \
    cp16((SBUF) + srow,                  gp0);                                 \
    cp16((SBUF) + srow + 4096,           gp0 + 32 * K);                        \
    cp16((SBUF) + srow + 8192,           gp0 + 64 * K);                        \
    cp16((SBUF) + srow + 12288,          gp0 + 96 * K);                        \
    cp16((SBUF) + PLANEB + srow,         gp1);                                 \
    cp16((SBUF) + PLANEB + srow + 4096,  gp1 + 32 * K);                        \
    cp16((SBUF) + PLANEB + srow + 8192,  gp1 + 64 * K);                        \
    cp16((SBUF) + PLANEB + srow + 12288, gp1 + 96 * K);                        \
    asm volatile("cp.async.commit_group;");                                    \
    gp0 += 64; gp1 += 64;                                                      \
} while (0)

#define KTILE(BOFS) do {                                                       \
    _Pragma("unroll")                                                          \
    for (int ks = 0; ks < 4; ks++) {                                           \
        const uint32_t kq = ((uint32_t)(ks * 32)) ^ kbase;                     \
        uint32_t ah[4][4], bh[4][2];                                           \
        _Pragma("unroll")                                                      \
        for (int i = 0; i < 4; i++)                                            \
            ldsm_x4(ah[i], aoff + (BOFS) + i * 2048 + kq);                     \
        _Pragma("unroll")                                                      \
        for (int jp = 0; jp < 2; jp++) {                                       \
            uint32_t th[4];                                                    \
            ldsm_x4(th, boff + (BOFS) + jp * 2048 + kq);                       \
            bh[jp * 2][0] = th[0]; bh[jp * 2 + 1][0] = th[1];                  \
            bh[jp * 2][1] = th[2]; bh[jp * 2 + 1][1] = th[3];                  \
        }                                                                      \
        _Pragma("unroll")                                                      \
        for (int i = 0; i < 4; i++)                                            \
            _Pragma("unroll")                                                  \
            for (int j = 0; j < 4; j++)                                        \
                mma_f16(acc[i][j], ah[i], bh[j]);                              \
    }                                                                          \
} while (0)

    STAGE2(sb);   // prologue: tile 0 -> buf 0

    #pragma unroll 1
    for (int kt = 0; kt < KT; kt += 2) {
        asm volatile("cp.async.wait_group 0;");
        __syncthreads();
        if (kt + 1 < KT) STAGE2(sb + BUFB);
        KTILE(0u);

        asm volatile("cp.async.wait_group 0;");
        __syncthreads();
        if (kt + 2 < KT) STAGE2(sb);
        KTILE((uint32_t)BUFB);
    }
#undef STAGE2
#undef KTILE

    // epilogue
    #pragma unroll
    for (int i = 0; i < 4; i++) {
        const int row0e = m0 + wm * 64 + i * 16 + g;
        #pragma unroll
        for (int j = 0; j < 4; j++) {
            const int col = n0 + wn * 32 + j * 8 + 2 * tig;
            const float2 bv = *(const float2*)(bias + col);
            float2 v0 = { acc[i][j][0] + bv.x, acc[i][j][1] + bv.y };
            float2 v1 = { acc[i][j][2] + bv.x, acc[i][j][3] + bv.y };
            if (RELU) {
                v0.x = fmaxf(v0.x, 0.f); v0.y = fmaxf(v0.y, 0.f);
                v1.x = fmaxf(v1.x, 0.f); v1.y = fmaxf(v1.y, 0.f);
            }
            if (HALF_OUT) {
                *(__half2*)(Yh + (size_t)row0e * N + col) = __floats2half2_rn(v0.x, v0.y);
                *(__half2*)(Yh + (size_t)(row0e + 8) * N + col) = __floats2half2_rn(v1.x, v1.y);
            } else {
                *(float2*)(Yf + (size_t)row0e * N + col) = v0;
                *(float2*)(Yf + (size_t)(row0e + 8) * N + col) = v1;
            }
        }
    }
}

// ---------------------------------------------------------------------------
// Log-sparse attention: 32 queries/block, 256 threads (8 warps, 4 q each).
// K transposed in smem; fp16 output (single plane).
// ---------------------------------------------------------------------------
#define QT 32
#define KWIN 96
#define KTP 97
#define PP 72
#define KT_OFF 0
#define VS_OFF (64 * KTP)
#define QS_OFF (VS_OFF + KWIN * 64)
#define P_OFF  (QS_OFF + QT * 64)
#define ATTN_SMF (P_OFF + QT * PP)
#define ATTN_SMEM (ATTN_SMF * 4)

__global__ __launch_bounds__(256)
void attn_tile(const float* __restrict__ qkv, __half* __restrict__ oh) {
    extern __shared__ float smf[];
    float* Kt = smf + KT_OFF;
    float* Vs = smf + VS_OFF;
    float* Qs = smf + QS_OFF;
    float* P  = smf + P_OFF;

    const int q0 = blockIdx.x * QT;
    const int h = blockIdx.y, b = blockIdx.z;
    const int tid = threadIdx.x, lane = tid & 31, w = tid >> 5;

    const float* base = qkv + (size_t)(b * SEQ) * 1536;

    for (int e = tid; e < KWIN * 16; e += 256) {
        const int r = e >> 4, c4 = (e & 15) << 2;
        const int j = q0 - 64 + r;
        float4 kv = {0.f, 0.f, 0.f, 0.f}, vv = {0.f, 0.f, 0.f, 0.f};
        if (j >= 0) {
            kv = *(const float4*)(base + (size_t)j * 1536 + 512 + h * 64 + c4);
            vv = *(const float4*)(base + (size_t)j * 1536 + 1024 + h * 64 + c4);
        }
        Kt[(c4 + 0) * KTP + r] = kv.x;
        Kt[(c4 + 1) * KTP + r] = kv.y;
        Kt[(c4 + 2) * KTP + r] = kv.z;
        Kt[(c4 + 3) * KTP + r] = kv.w;
        *(float4*)(&Vs[r * 64 + c4]) = vv;
    }
    for (int e = tid; e < QT * 16; e += 256) {
        const int r = e >> 4, c4 = (e & 15) << 2;
        *(float4*)(&Qs[r * 64 + c4]) =
            *(const float4*)(base + (size_t)(q0 + r) * 1536 + h * 64 + c4);
    }
    __syncthreads();

    #pragma unroll
    for (int c = 0; c < 4; c++) {
        const int qi = w * 4 + c;
        const int i = q0 + qi;
        const int lo = (i > 64) ? (i - 64) : 0;
        const int nwin = i - lo + 1;
        const int ne = (i >= 128) + (i >= 256) + (i >= 512) + (i >= 1024);
        const int n = nwin + ne;
        const int rbase = lo - q0 + 64;
        const float* Qrow = Qs + qi * 64;
        float* Prow = P + qi * PP;

        float mx = -INFINITY;
        for (int c0 = 0; c0 < nwin; c0 += 32) {
            const int kk = c0 + lane;
            const bool valid = kk < nwin;
            const int r = valid ? (rbase + kk) : 0;
            float dot = 0.f;
            #pragma unroll
            for (int d = 0; d < 64; d += 2) {
                const float2 qv = *(const float2*)(Qrow + d);
                dot += qv.x * Kt[d * KTP + r];
                dot += qv.y * Kt[(d + 1) * KTP + r];
            }
            dot *= 0.125f;
            if (valid) {
                Prow[kk] = dot;
                mx = fmaxf(mx, dot);
            }
        }
        const float qv0 = Qrow[lane], qv1 = Qrow[lane + 32];
        for (int t = 0; t < ne; t++) {
            const int j = i - (128 << t);
            const float* kp = base + (size_t)j * 1536 + 512 + h * 64;
            float p = qv0 * kp[lane] + qv1 * kp[lane + 32];
            #pragma unroll
            for (int o2 = 16; o2; o2 >>= 1) p += __shfl_xor_sync(~0u, p, o2);
            p *= 0.125f;
            if (lane == 0) Prow[nwin + t] = p;
            mx = fmaxf(mx, p);
        }
        #pragma unroll
        for (int o2 = 16; o2; o2 >>= 1) mx = fmaxf(mx, __shfl_xor_sync(~0u, mx, o2));
        __syncwarp();

        float s = 0.f;
        for (int kk = lane; kk < n; kk += 32) {
            const float e = expf(Prow[kk] - mx);
            Prow[kk] = e;
            s += e;
        }
        #pragma unroll
        for (int o2 = 16; o2; o2 >>= 1) s += __shfl_xor_sync(~0u, s, o2);
        const float inv = 1.f / s;
        __syncwarp();

        float a0 = 0.f, a1 = 0.f;
        for (int kk = 0; kk < nwin; kk++) {
            const float p = Prow[kk];
            const float* vr = Vs + (rbase + kk) * 64;
            a0 += p * vr[lane];
            a1 += p * vr[lane + 32];
        }
        for (int t = 0; t < ne; t++) {
            const float p = Prow[nwin + t];
            const int j = i - (128 << t);
            const float* vp = base + (size_t)j * 1536 + 1024 + h * 64;
            a0 += p * vp[lane];
            a1 += p * vp[lane + 32];
        }
        const size_t off = (size_t)(b * SEQ + i) * DM + h * 64;
        oh[off + lane]      = __float2half_rn(a0 * inv);
        oh[off + lane + 32] = __float2half_rn(a1 * inv);
    }
}

// ---------------------------------------------------------------------------
// x = LayerNorm(x + d) * scale + bias; also emits fp16 copy of result.
// ---------------------------------------------------------------------------
__global__ void add_ln_kernel(float* __restrict__ x, const float* __restrict__ o,
                              const float* __restrict__ sc, const float* __restrict__ bi,
                              __half* __restrict__ xh) {
    const int row = blockIdx.x;
    const int t = threadIdx.x;
    const long base = (long)row * DM;

    const float v0 = x[base + t]       + o[base + t];
    const float v1 = x[base + t + 256] + o[base + t + 256];
    float s = v0 + v1, sq = v0 * v0 + v1 * v1;
    #pragma unroll
    for (int off = 16; off; off >>= 1) {
        s  += __shfl_xor_sync(0xffffffffu, s, off);
        sq += __shfl_xor_sync(0xffffffffu, sq, off);
    }
    __shared__ float ss[8], sqs[8];
    __shared__ float mean_s, rstd_s;
    const int w = t >> 5;
    if ((t & 31) == 0) { ss[w] = s; sqs[w] = sq; }
    __syncthreads();
    if (t == 0) {
        float s1 = 0.f, s2 = 0.f;
        #pragma unroll
        for (int k = 0; k < 8; k++) { s1 += ss[k]; s2 += sqs[k]; }
        const float m = s1 / (float)DM;
        mean_s = m;
        rstd_s = rsqrtf(s2 / (float)DM - m * m + 1e-5f);
    }
    __syncthreads();
    const float m = mean_s, r = rstd_s;
    const float y0 = (v0 - m) * r * sc[t]       + bi[t];
    const float y1 = (v1 - m) * r * sc[t + 256] + bi[t + 256];
    x[base + t]       = y0;
    x[base + t + 256] = y1;
    xh[base + t]       = __float2half_rn(y0);
    xh[base + t + 256] = __float2half_rn(y1);
}

// ---------------------------------------------------------------------------
extern "C" void kernel_launch(void* const* d_in, const int* in_sizes, int n_in,
                              void* d_out, int out_size) {
    const float* src   = (const float*)d_in[0];
    const float* qkv_w = (const float*)d_in[2];
    const float* qkv_b = (const float*)d_in[3];
    const float* out_w = (const float*)d_in[4];
    const float* out_b = (const float*)d_in[5];
    const float* ln1_s = (const float*)d_in[6];
    const float* ln1_b = (const float*)d_in[7];
    const float* w1    = (const float*)d_in[8];
    const float* b1    = (const float*)d_in[9];
    const float* w2    = (const float*)d_in[10];
    const float* b2    = (const float*)d_in[11];
    const float* ln2_s = (const float*)d_in[12];
    const float* ln2_b = (const float*)d_in[13];

    float* x = (float*)d_out;

    float *qkv, *dbuf;
    __half *xh, *oh, *hh, *wh;
    cudaGetSymbolAddress((void**)&qkv, g_qkv);
    cudaGetSymbolAddress((void**)&dbuf, g_d);
    cudaGetSymbolAddress((void**)&xh, g_xh);
    cudaGetSymbolAddress((void**)&oh, g_oh);
    cudaGetSymbolAddress((void**)&hh, g_hh);
    cudaGetSymbolAddress((void**)&wh, g_wh);

    cudaFuncSetAttribute(gemm_tc<0,0,512,1536>, cudaFuncAttributeMaxDynamicSharedMemorySize, SMEMB);
    cudaFuncSetAttribute(gemm_tc<0,0,512,512>,  cudaFuncAttributeMaxDynamicSharedMemorySize, SMEMB);
    cudaFuncSetAttribute(gemm_tc<1,1,512,2048>, cudaFuncAttributeMaxDynamicSharedMemorySize, SMEMB);
    cudaFuncSetAttribute(gemm_tc<0,0,2048,512>, cudaFuncAttributeMaxDynamicSharedMemorySize, SMEMB);
    cudaFuncSetAttribute(attn_tile, cudaFuncAttributeMaxDynamicSharedMemorySize, ATTN_SMEM);

    // launch order: #4 (ncu's pick) is the QKV GEMM
    copy_conv<<<(ROWS*DM/4 + 255)/256, 256>>>(src, x, xh, ROWS*DM/4);                  // 1
    conv_h<<<(2*1536*512/4 + 255)/256, 256>>>(qkv_w, wh + OFF_QKV, 2*1536*512/4);      // 2
    conv_h<<<(2*512*512/4  + 255)/256, 256>>>(out_w, wh + OFF_OUT, 2*512*512/4);       // 3

    for (int l = 0; l < 2; l++) {
        gemm_tc<0,0,512,1536><<<dim3(12, 64), 256, SMEMB>>>(
            xh, wh + OFF_QKV + (size_t)l*1536*512,
            qkv_b + (size_t)l*1536, qkv, nullptr);

        if (l == 0) {
            conv_h<<<(2*2048*512/4 + 255)/256, 256>>>(w1, wh + OFF_W1, 2*2048*512/4);
            conv_h<<<(2*512*2048/4 + 255)/256, 256>>>(w2, wh + OFF_W2, 2*512*2048/4);
        }

        attn_tile<<<dim3(SEQ/QT, NH, BATCH), 256, ATTN_SMEM>>>(qkv, oh);

        gemm_tc<0,0,512,512><<<dim3(4, 64), 256, SMEMB>>>(
            oh, wh + OFF_OUT + (size_t)l*512*512,
            out_b + (size_t)l*512, dbuf, nullptr);

        add_ln_kernel<<<ROWS, 256>>>(x, dbuf, ln1_s + l*DM, ln1_b + l*DM, xh);

        gemm_tc<1,1,512,2048><<<dim3(16, 64), 256, SMEMB>>>(
            xh, wh + OFF_W1 + (size_t)l*2048*512,
            b1 + (size_t)l*2048, nullptr, hh);

        gemm_tc<0,0,2048,512><<<dim3(4, 64), 256, SMEMB>>>(
            hh, wh + OFF_W2 + (size_t)l*512*2048,
            b2 + (size_t)l*512, dbuf, nullptr);

        add_ln_kernel<<<ROWS, 256>>>(x, dbuf, ln2_s + l*DM, ln2_b + l*DM, xh);
    }
}

// round 11
// speedup vs baseline: 8.9608x; 1.0652x over previous
#include <cuda_runtime.h>
#include <cuda_fp16.h>
#include <math.h>
#include <stdint.h>

#define SEQ 2048
#define DM 512
#define NH 8
#define DH 64
#define DFF 2048
#define BATCH 4
#define ROWS (BATCH * SEQ)   // 8192

// ---------------- device scratch (no allocation allowed) -------------------
__device__ float g_qkv[(size_t)ROWS * 3 * DM];
__device__ float g_d[(size_t)ROWS * DM];
__device__ __half g_xh[(size_t)ROWS * DM];
__device__ __half g_oh[(size_t)ROWS * DM];
__device__ __half g_hh[(size_t)ROWS * DFF];
#define W_TOTAL 6291456
__device__ __half g_wh[W_TOTAL];
#define OFF_QKV 0
#define OFF_OUT (2 * 1536 * 512)
#define OFF_W1  (OFF_OUT + 2 * 512 * 512)
#define OFF_W2  (OFF_W1 + 2 * 2048 * 512)

// ---------------------------------------------------------------------------
// helpers
// ---------------------------------------------------------------------------
__device__ __forceinline__ void cp16(uint32_t saddr, const void* g) {
    asm volatile("cp.async.cg.shared.global [%0], [%1], 16;" :: "r"(saddr), "l"(g));
}
__device__ __forceinline__ void ldsm_x4(uint32_t* r, uint32_t a) {
    asm volatile("ldmatrix.sync.aligned.m8n8.x4.shared.b16 {%0,%1,%2,%3}, [%4];"
                 : "=r"(r[0]), "=r"(r[1]), "=r"(r[2]), "=r"(r[3]) : "r"(a));
}
__device__ __forceinline__ void mma_f16(float* d, const uint32_t* a, const uint32_t* b) {
    asm volatile("mma.sync.aligned.m16n8k16.row.col.f32.f16.f16.f32 "
                 "{%0,%1,%2,%3}, {%4,%5,%6,%7}, {%8,%9}, {%0,%1,%2,%3};"
                 : "+f"(d[0]), "+f"(d[1]), "+f"(d[2]), "+f"(d[3])
                 : "r"(a[0]), "r"(a[1]), "r"(a[2]), "r"(a[3]), "r"(b[0]), "r"(b[1]));
}
#define SWZ(bo) ((bo) ^ (((bo) >> 3) & 0x70))

// ---------------------------------------------------------------------------
// conversion kernels
// ---------------------------------------------------------------------------
__global__ void conv_all(const float* __restrict__ qkv_w, const float* __restrict__ out_w,
                         const float* __restrict__ w1, const float* __restrict__ w2,
                         __half* __restrict__ dst) {
    const int i = blockIdx.x * blockDim.x + threadIdx.x;   // float4 index
    if (i >= W_TOTAL / 4) return;
    const int e = i * 4;
    const float* src;
    int local;
    if (e < OFF_OUT)      { src = qkv_w; local = e; }
    else if (e < OFF_W1)  { src = out_w; local = e - OFF_OUT; }
    else if (e < OFF_W2)  { src = w1;    local = e - OFF_W1; }
    else                  { src = w2;    local = e - OFF_W2; }
    const float4 v = *(const float4*)(src + local);
    ((__half2*)dst)[2 * i]     = __floats2half2_rn(v.x, v.y);
    ((__half2*)dst)[2 * i + 1] = __floats2half2_rn(v.z, v.w);
}

__global__ void copy_conv(const float* __restrict__ src, float* __restrict__ x,
                          __half* __restrict__ xh, int n4) {
    const int i = blockIdx.x * blockDim.x + threadIdx.x;
    if (i >= n4) return;
    const float4 v = ((const float4*)src)[i];
    ((float4*)x)[i] = v;
    ((__half2*)xh)[2 * i]     = __floats2half2_rn(v.x, v.y);
    ((__half2*)xh)[2 * i + 1] = __floats2half2_rn(v.z, v.w);
}

// ---------------------------------------------------------------------------
// GEMM (unchanged from R10): plain fp16, 128x128 tile, BK=64, SW128 smem,
// double-buffered, 256 threads, compile-time K/N.
// ---------------------------------------------------------------------------
#define PLANEB 16384
#define BUFB (2 * PLANEB)
#define SMEMB (2 * BUFB)

template<int RELU, int HALF_OUT, int K, int N>
__global__ __launch_bounds__(256)
void gemm_tc(const __half* __restrict__ Xh, const __half* __restrict__ Wh,
             const float* __restrict__ bias, float* __restrict__ Yf,
             __half* __restrict__ Yh) {
    extern __shared__ __align__(1024) char smc[];
    const uint32_t sb = (uint32_t)__cvta_generic_to_shared(smc);

    const int tid = threadIdx.x;
    const int lane = tid & 31, warp = tid >> 5;
    const int wm = warp & 1, wn = warp >> 1;
    const int g = lane >> 2, tig = lane & 3;
    const int m0 = blockIdx.y * 128, n0 = blockIdx.x * 128;

    float acc[4][4][4] = {};
    constexpr int KT = K >> 6;

    const int row0 = tid >> 3, ch = tid & 7;
    const __half* gp0 = Xh + (size_t)(m0 + row0) * K + ch * 8;
    const __half* gp1 = Wh + (size_t)(n0 + row0) * K + ch * 8;
    const uint32_t srow = SWZ((uint32_t)(row0 * 128 + ch * 16));

    const int lrow = lane & 15;
    const uint32_t kbase = ((uint32_t)((lane >> 4) << 4)) ^ ((uint32_t)((lrow & 7) << 4));
    const uint32_t aoff = sb + (uint32_t)((wm * 64 + lrow) * 128);
    const uint32_t boff = sb + (uint32_t)((wn * 32 + lrow) * 128) + (uint32_t)PLANEB;

#define STAGE2(SBUF) do {                                                      \
    cp16((SBUF) + srow,                  gp0);                                 \
    cp16((SBUF) + srow + 4096,           gp0 + 32 * K);                        \
    cp16((SBUF) + srow + 8192,           gp0 + 64 * K);                        \
    cp16((SBUF) + srow + 12288,          gp0 + 96 * K);                        \
    cp16((SBUF) + PLANEB + srow,         gp1);                                 \
    cp16((SBUF) + PLANEB + srow + 4096,  gp1 + 32 * K);                        \
    cp16((SBUF) + PLANEB + srow + 8192,  gp1 + 64 * K);                        \
    cp16((SBUF) + PLANEB + srow + 12288, gp1 + 96 * K);                        \
    asm volatile("cp.async.commit_group;");                                    \
    gp0 += 64; gp1 += 64;                                                      \
} while (0)

#define KTILE(BOFS) do {                                                       \
    _Pragma("unroll")                                                          \
    for (int ks = 0; ks < 4; ks++) {                                           \
        const uint32_t kq = ((uint32_t)(ks * 32)) ^ kbase;                     \
        uint32_t ah[4][4], bh[4][2];                                           \
        _Pragma("unroll")                                                      \
        for (int i = 0; i < 4; i++)                                            \
            ldsm_x4(ah[i], aoff + (BOFS) + i * 2048 + kq);                     \
        _Pragma("unroll")                                                      \
        for (int jp = 0; jp < 2; jp++) {                                       \
            uint32_t th[4];                                                    \
            ldsm_x4(th, boff + (BOFS) + jp * 2048 + kq);                       \
            bh[jp * 2][0] = th[0]; bh[jp * 2 + 1][0] = th[1];                  \
            bh[jp * 2][1] = th[2]; bh[jp * 2 + 1][1] = th[3];                  \
        }                                                                      \
        _Pragma("unroll")                                                      \
        for (int i = 0; i < 4; i++)                                            \
            _Pragma("unroll")                                                  \
            for (int j = 0; j < 4; j++)                                        \
                mma_f16(acc[i][j], ah[i], bh[j]);                              \
    }                                                                          \
} while (0)

    STAGE2(sb);

    #pragma unroll 1
    for (int kt = 0; kt < KT; kt += 2) {
        asm volatile("cp.async.wait_group 0;");
        __syncthreads();
        if (kt + 1 < KT) STAGE2(sb + BUFB);
        KTILE(0u);

        asm volatile("cp.async.wait_group 0;");
        __syncthreads();
        if (kt + 2 < KT) STAGE2(sb);
        KTILE((uint32_t)BUFB);
    }
#undef STAGE2
#undef KTILE

    #pragma unroll
    for (int i = 0; i < 4; i++) {
        const int row0e = m0 + wm * 64 + i * 16 + g;
        #pragma unroll
        for (int j = 0; j < 4; j++) {
            const int col = n0 + wn * 32 + j * 8 + 2 * tig;
            const float2 bv = *(const float2*)(bias + col);
            float2 v0 = { acc[i][j][0] + bv.x, acc[i][j][1] + bv.y };
            float2 v1 = { acc[i][j][2] + bv.x, acc[i][j][3] + bv.y };
            if (RELU) {
                v0.x = fmaxf(v0.x, 0.f); v0.y = fmaxf(v0.y, 0.f);
                v1.x = fmaxf(v1.x, 0.f); v1.y = fmaxf(v1.y, 0.f);
            }
            if (HALF_OUT) {
                *(__half2*)(Yh + (size_t)row0e * N + col) = __floats2half2_rn(v0.x, v0.y);
                *(__half2*)(Yh + (size_t)(row0e + 8) * N + col) = __floats2half2_rn(v1.x, v1.y);
            } else {
                *(float2*)(Yf + (size_t)row0e * N + col) = v0;
                *(float2*)(Yf + (size_t)(row0e + 8) * N + col) = v1;
            }
        }
    }
}

// ---------------------------------------------------------------------------
// Log-sparse attention v3: 32 q/block, 256 threads. K/V staged as half2
// (K transposed [d/2][r], V [r][d/2]); scores/softmax/accum in fp32.
// ---------------------------------------------------------------------------
#define QT 32
#define KWIN 96
#define KTP2 97
#define PP 72
#define VS2_OFF (32 * KTP2)                 // 3104 (4B units)
#define QS_OFF (VS2_OFF + KWIN * 32)        // 6176
#define P_OFF  (QS_OFF + QT * 64)           // 8224
#define ATTN_SMF (P_OFF + QT * PP)          // 10528 floats
#define ATTN_SMEM (ATTN_SMF * 4)            // 42112 bytes

__global__ __launch_bounds__(256)
void attn_tile(const float* __restrict__ qkv, __half* __restrict__ oh) {
    extern __shared__ float smf[];
    __half2* Kt2 = (__half2*)smf;                 // [32][KTP2]
    __half2* Vs2 = (__half2*)(smf + VS2_OFF);     // [KWIN][32]
    float*   Qs  = smf + QS_OFF;                  // [QT][64]
    float*   P   = smf + P_OFF;                   // [QT][PP]

    const int q0 = blockIdx.x * QT;
    const int h = blockIdx.y, b = blockIdx.z;
    const int tid = threadIdx.x, lane = tid & 31, w = tid >> 5;

    const float* base = qkv + (size_t)(b * SEQ) * 1536;

    for (int e = tid; e < KWIN * 16; e += 256) {
        const int r = e >> 4, c4 = (e & 15) << 2;
        const int j = q0 - 64 + r;
        float4 kv = {0.f, 0.f, 0.f, 0.f}, vv = {0.f, 0.f, 0.f, 0.f};
        if (j >= 0) {
            kv = *(const float4*)(base + (size_t)j * 1536 + 512 + h * 64 + c4);
            vv = *(const float4*)(base + (size_t)j * 1536 + 1024 + h * 64 + c4);
        }
        const int d2 = c4 >> 1;
        Kt2[d2 * KTP2 + r]       = __floats2half2_rn(kv.x, kv.y);
        Kt2[(d2 + 1) * KTP2 + r] = __floats2half2_rn(kv.z, kv.w);
        Vs2[r * 32 + d2]     = __floats2half2_rn(vv.x, vv.y);
        Vs2[r * 32 + d2 + 1] = __floats2half2_rn(vv.z, vv.w);
    }
    for (int e = tid; e < QT * 16; e += 256) {
        const int r = e >> 4, c4 = (e & 15) << 2;
        *(float4*)(&Qs[r * 64 + c4]) =
            *(const float4*)(base + (size_t)(q0 + r) * 1536 + h * 64 + c4);
    }
    __syncthreads();

    #pragma unroll
    for (int c = 0; c < 4; c++) {
        const int qi = w * 4 + c;
        const int i = q0 + qi;
        const int lo = (i > 64) ? (i - 64) : 0;
        const int nwin = i - lo + 1;
        const int ne = (i >= 128) + (i >= 256) + (i >= 512) + (i >= 1024);
        const int n = nwin + ne;
        const int rbase = lo - q0 + 64;
        const float* Qrow = Qs + qi * 64;
        float* Prow = P + qi * PP;

        // scores: lanes own keys; 32x (LDS.32 + cvt + 2 FFMA)
        float mx = -INFINITY;
        for (int c0 = 0; c0 < nwin; c0 += 32) {
            const int kk = c0 + lane;
            const bool valid = kk < nwin;
            const int r = valid ? (rbase + kk) : 0;
            float dot = 0.f;
            #pragma unroll
            for (int d2 = 0; d2 < 32; d2++) {
                const float2 qv = *(const float2*)(Qrow + 2 * d2);
                const float2 kf = __half22float2(Kt2[d2 * KTP2 + r]);
                dot += qv.x * kf.x + qv.y * kf.y;
            }
            dot *= 0.125f;
            if (valid) {
                Prow[kk] = dot;
                mx = fmaxf(mx, dot);
            }
        }
        // extras (<=4 log-strided keys): lanes own dim-pairs, shfl reduce
        const float2 qv2 = *(const float2*)(Qrow + 2 * lane);
        for (int t = 0; t < ne; t++) {
            const int j = i - (128 << t);
            const float2 kf = *(const float2*)(base + (size_t)j * 1536 + 512 + h * 64 + 2 * lane);
            float p = qv2.x * kf.x + qv2.y * kf.y;
            #pragma unroll
            for (int o2 = 16; o2; o2 >>= 1) p += __shfl_xor_sync(~0u, p, o2);
            p *= 0.125f;
            if (lane == 0) Prow[nwin + t] = p;
            mx = fmaxf(mx, p);
        }
        #pragma unroll
        for (int o2 = 16; o2; o2 >>= 1) mx = fmaxf(mx, __shfl_xor_sync(~0u, mx, o2));
        __syncwarp();

        // softmax weights
        float s = 0.f;
        for (int kk = lane; kk < n; kk += 32) {
            const float e = expf(Prow[kk] - mx);
            Prow[kk] = e;
            s += e;
        }
        #pragma unroll
        for (int o2 = 16; o2; o2 >>= 1) s += __shfl_xor_sync(~0u, s, o2);
        const float inv = 1.f / s;
        __syncwarp();

        // weighted V: lanes own dim-pairs
        float a0 = 0.f, a1 = 0.f;
        for (int kk = 0; kk < nwin; kk++) {
            const float p = Prow[kk];
            const float2 vf = __half22float2(Vs2[(rbase + kk) * 32 + lane]);
            a0 += p * vf.x;
            a1 += p * vf.y;
        }
        for (int t = 0; t < ne; t++) {
            const float p = Prow[nwin + t];
            const int j = i - (128 << t);
            const float2 vf = *(const float2*)(base + (size_t)j * 1536 + 1024 + h * 64 + 2 * lane);
            a0 += p * vf.x;
            a1 += p * vf.y;
        }
        const size_t off = (size_t)(b * SEQ + i) * DM + h * 64;
        *(__half2*)(oh + off + 2 * lane) = __floats2half2_rn(a0 * inv, a1 * inv);
    }
}

// ---------------------------------------------------------------------------
// x = LayerNorm(x + d) * scale + bias; emits fp16 copy. 128 thr, float4.
// ---------------------------------------------------------------------------
__global__ __launch_bounds__(128)
void add_ln_kernel(float* __restrict__ x, const float* __restrict__ o,
                   const float* __restrict__ sc, const float* __restrict__ bi,
                   __half* __restrict__ xh) {
    const int row = blockIdx.x;
    const int t = threadIdx.x;                 // 0..127
    const long base = (long)row * DM + 4 * t;

    const float4 xv = *(const float4*)(x + base);
    const float4 ov = *(const float4*)(o + base);
    const float v0 = xv.x + ov.x, v1 = xv.y + ov.y;
    const float v2 = xv.z + ov.z, v3 = xv.w + ov.w;
    float s = v0 + v1 + v2 + v3;
    float sq = v0 * v0 + v1 * v1 + v2 * v2 + v3 * v3;
    #pragma unroll
    for (int off = 16; off; off >>= 1) {
        s  += __shfl_xor_sync(0xffffffffu, s, off);
        sq += __shfl_xor_sync(0xffffffffu, sq, off);
    }
    __shared__ float ss[4], sqs[4];
    __shared__ float mean_s, rstd_s;
    const int w = t >> 5;
    if ((t & 31) == 0) { ss[w] = s; sqs[w] = sq; }
    __syncthreads();
    if (t == 0) {
        const float s1 = ss[0] + ss[1] + ss[2] + ss[3];
        const float s2 = sqs[0] + sqs[1] + sqs[2] + sqs[3];
        const float m = s1 / (float)DM;
        mean_s = m;
        rstd_s = rsqrtf(s2 / (float)DM - m * m + 1e-5f);
    }
    __syncthreads();
    const float m = mean_s, r = rstd_s;
    const float4 scv = *(const float4*)(sc + 4 * t);
    const float4 biv = *(const float4*)(bi + 4 * t);
    float4 y;
    y.x = (v0 - m) * r * scv.x + biv.x;
    y.y = (v1 - m) * r * scv.y + biv.y;
    y.z = (v2 - m) * r * scv.z + biv.z;
    y.w = (v3 - m) * r * scv.w + biv.w;
    *(float4*)(x + base) = y;
    *(__half2*)(xh + base)     = __floats2half2_rn(y.x, y.y);
    *(__half2*)(xh + base + 2) = __floats2half2_rn(y.z, y.w);
}

// ---------------------------------------------------------------------------
extern "C" void kernel_launch(void* const* d_in, const int* in_sizes, int n_in,
                              void* d_out, int out_size) {
    const float* src   = (const float*)d_in[0];
    const float* qkv_w = (const float*)d_in[2];
    const float* qkv_b = (const float*)d_in[3];
    const float* out_w = (const float*)d_in[4];
    const float* out_b = (const float*)d_in[5];
    const float* ln1_s = (const float*)d_in[6];
    const float* ln1_b = (const float*)d_in[7];
    const float* w1    = (const float*)d_in[8];
    const float* b1    = (const float*)d_in[9];
    const float* w2    = (const float*)d_in[10];
    const float* b2    = (const float*)d_in[11];
    const float* ln2_s = (const float*)d_in[12];
    const float* ln2_b = (const float*)d_in[13];

    float* x = (float*)d_out;

    float *qkv, *dbuf;
    __half *xh, *oh, *hh, *wh;
    cudaGetSymbolAddress((void**)&qkv, g_qkv);
    cudaGetSymbolAddress((void**)&dbuf, g_d);
    cudaGetSymbolAddress((void**)&xh, g_xh);
    cudaGetSymbolAddress((void**)&oh, g_oh);
    cudaGetSymbolAddress((void**)&hh, g_hh);
    cudaGetSymbolAddress((void**)&wh, g_wh);

    cudaFuncSetAttribute(gemm_tc<0,0,512,1536>, cudaFuncAttributeMaxDynamicSharedMemorySize, SMEMB);
    cudaFuncSetAttribute(gemm_tc<0,0,512,512>,  cudaFuncAttributeMaxDynamicSharedMemorySize, SMEMB);
    cudaFuncSetAttribute(gemm_tc<1,1,512,2048>, cudaFuncAttributeMaxDynamicSharedMemorySize, SMEMB);
    cudaFuncSetAttribute(gemm_tc<0,0,2048,512>, cudaFuncAttributeMaxDynamicSharedMemorySize, SMEMB);
    cudaFuncSetAttribute(attn_tile, cudaFuncAttributeMaxDynamicSharedMemorySize, ATTN_SMEM);

    // launch order: #4 (ncu's pick) is attn_tile
    copy_conv<<<(ROWS*DM/4 + 255)/256, 256>>>(src, x, xh, ROWS*DM/4);                  // 1
    conv_all<<<(W_TOTAL/4 + 255)/256, 256>>>(qkv_w, out_w, w1, w2, wh);                // 2

    for (int l = 0; l < 2; l++) {
        gemm_tc<0,0,512,1536><<<dim3(12, 64), 256, SMEMB>>>(                           // 3
            xh, wh + OFF_QKV + (size_t)l*1536*512,
            qkv_b + (size_t)l*1536, qkv, nullptr);

        attn_tile<<<dim3(SEQ/QT, NH, BATCH), 256, ATTN_SMEM>>>(qkv, oh);               // 4

        gemm_tc<0,0,512,512><<<dim3(4, 64), 256, SMEMB>>>(
            oh, wh + OFF_OUT + (size_t)l*512*512,
            out_b + (size_t)l*512, dbuf, nullptr);

        add_ln_kernel<<<ROWS, 128>>>(x, dbuf, ln1_s + l*DM, ln1_b + l*DM, xh);

        gemm_tc<1,1,512,2048><<<dim3(16, 64), 256, SMEMB>>>(
            xh, wh + OFF_W1 + (size_t)l*2048*512,
            b1 + (size_t)l*2048, nullptr, hh);

        gemm_tc<0,0,2048,512><<<dim3(4, 64), 256, SMEMB>>>(
            hh, wh + OFF_W2 + (size_t)l*512*2048,
            b2 + (size_t)l*512, dbuf, nullptr);

        add_ln_kernel<<<ROWS, 128>>>(x, dbuf, ln2_s + l*DM, ln2_b + l*DM, xh);
    }
}

// round 12
// speedup vs baseline: 10.1716x; 1.1351x over previous
#include <cuda_runtime.h>
#include <cuda_fp16.h>
#include <math.h>
#include <stdint.h>

#define SEQ 2048
#define DM 512
#define NH 8
#define DH 64
#define DFF 2048
#define BATCH 4
#define ROWS (BATCH * SEQ)   // 8192

// ---------------- device scratch (no allocation allowed) -------------------
__device__ float g_qkv[(size_t)ROWS * 3 * DM];
__device__ float g_d[(size_t)ROWS * DM];
__device__ __half g_xh[(size_t)ROWS * DM];
__device__ __half g_oh[(size_t)ROWS * DM];
__device__ __half g_hh[(size_t)ROWS * DFF];
#define W_TOTAL 6291456
__device__ __half g_wh[W_TOTAL];
#define OFF_QKV 0
#define OFF_OUT (2 * 1536 * 512)
#define OFF_W1  (OFF_OUT + 2 * 512 * 512)
#define OFF_W2  (OFF_W1 + 2 * 2048 * 512)

// ---------------------------------------------------------------------------
// helpers
// ---------------------------------------------------------------------------
__device__ __forceinline__ void cp16(uint32_t saddr, const void* g) {
    asm volatile("cp.async.cg.shared.global [%0], [%1], 16;" :: "r"(saddr), "l"(g));
}
__device__ __forceinline__ void ldsm_x4(uint32_t* r, uint32_t a) {
    asm volatile("ldmatrix.sync.aligned.m8n8.x4.shared.b16 {%0,%1,%2,%3}, [%4];"
                 : "=r"(r[0]), "=r"(r[1]), "=r"(r[2]), "=r"(r[3]) : "r"(a));
}
__device__ __forceinline__ void mma_f16(float* d, const uint32_t* a, const uint32_t* b) {
    asm volatile("mma.sync.aligned.m16n8k16.row.col.f32.f16.f16.f32 "
                 "{%0,%1,%2,%3}, {%4,%5,%6,%7}, {%8,%9}, {%0,%1,%2,%3};"
                 : "+f"(d[0]), "+f"(d[1]), "+f"(d[2]), "+f"(d[3])
                 : "r"(a[0]), "r"(a[1]), "r"(a[2]), "r"(a[3]), "r"(b[0]), "r"(b[1]));
}
#define SWZ(bo) ((bo) ^ (((bo) >> 3) & 0x70))

// ---------------------------------------------------------------------------
// conversion kernels
// ---------------------------------------------------------------------------
__global__ void conv_all(const float* __restrict__ qkv_w, const float* __restrict__ out_w,
                         const float* __restrict__ w1, const float* __restrict__ w2,
                         __half* __restrict__ dst) {
    const int i = blockIdx.x * blockDim.x + threadIdx.x;
    if (i >= W_TOTAL / 4) return;
    const int e = i * 4;
    const float* src;
    int local;
    if (e < OFF_OUT)      { src = qkv_w; local = e; }
    else if (e < OFF_W1)  { src = out_w; local = e - OFF_OUT; }
    else if (e < OFF_W2)  { src = w1;    local = e - OFF_W1; }
    else                  { src = w2;    local = e - OFF_W2; }
    const float4 v = *(const float4*)(src + local);
    ((__half2*)dst)[2 * i]     = __floats2half2_rn(v.x, v.y);
    ((__half2*)dst)[2 * i + 1] = __floats2half2_rn(v.z, v.w);
}

__global__ void copy_conv(const float* __restrict__ src, float* __restrict__ x,
                          __half* __restrict__ xh, int n4) {
    const int i = blockIdx.x * blockDim.x + threadIdx.x;
    if (i >= n4) return;
    const float4 v = ((const float4*)src)[i];
    ((float4*)x)[i] = v;
    ((__half2*)xh)[2 * i]     = __floats2half2_rn(v.x, v.y);
    ((__half2*)xh)[2 * i + 1] = __floats2half2_rn(v.z, v.w);
}

// ---------------------------------------------------------------------------
// GEMM (unchanged): plain fp16, 128x128 tile, BK=64, SW128 smem, 256 threads.
// ---------------------------------------------------------------------------
#define PLANEB 16384
#define BUFB (2 * PLANEB)
#define SMEMB (2 * BUFB)

template<int RELU, int HALF_OUT, int K, int N>
__global__ __launch_bounds__(256)
void gemm_tc(const __half* __restrict__ Xh, const __half* __restrict__ Wh,
             const float* __restrict__ bias, float* __restrict__ Yf,
             __half* __restrict__ Yh) {
    extern __shared__ __align__(1024) char smc[];
    const uint32_t sb = (uint32_t)__cvta_generic_to_shared(smc);

    const int tid = threadIdx.x;
    const int lane = tid & 31, warp = tid >> 5;
    const int wm = warp & 1, wn = warp >> 1;
    const int g = lane >> 2, tig = lane & 3;
    const int m0 = blockIdx.y * 128, n0 = blockIdx.x * 128;

    float acc[4][4][4] = {};
    constexpr int KT = K >> 6;

    const int row0 = tid >> 3, ch = tid & 7;
    const __half* gp0 = Xh + (size_t)(m0 + row0) * K + ch * 8;
    const __half* gp1 = Wh + (size_t)(n0 + row0) * K + ch * 8;
    const uint32_t srow = SWZ((uint32_t)(row0 * 128 + ch * 16));

    const int lrow = lane & 15;
    const uint32_t kbase = ((uint32_t)((lane >> 4) << 4)) ^ ((uint32_t)((lrow & 7) << 4));
    const uint32_t aoff = sb + (uint32_t)((wm * 64 + lrow) * 128);
    const uint32_t boff = sb + (uint32_t)((wn * 32 + lrow) * 128) + (uint32_t)PLANEB;

#define STAGE2(SBUF) do {                                                      \
    cp16((SBUF) + srow,                  gp0);                                 \
    cp16((SBUF) + srow + 4096,           gp0 + 32 * K);                        \
    cp16((SBUF) + srow + 8192,           gp0 + 64 * K);                        \
    cp16((SBUF) + srow + 12288,          gp0 + 96 * K);                        \
    cp16((SBUF) + PLANEB + srow,         gp1);                                 \
    cp16((SBUF) + PLANEB + srow + 4096,  gp1 + 32 * K);                        \
    cp16((SBUF) + PLANEB + srow + 8192,  gp1 + 64 * K);                        \
    cp16((SBUF) + PLANEB + srow + 12288, gp1 + 96 * K);                        \
    asm volatile("cp.async.commit_group;");                                    \
    gp0 += 64; gp1 += 64;                                                      \
} while (0)

#define KTILE(BOFS) do {                                                       \
    _Pragma("unroll")                                                          \
    for (int ks = 0; ks < 4; ks++) {                                           \
        const uint32_t kq = ((uint32_t)(ks * 32)) ^ kbase;                     \
        uint32_t ah[4][4], bh[4][2];                                           \
        _Pragma("unroll")                                                      \
        for (int i = 0; i < 4; i++)                                            \
            ldsm_x4(ah[i], aoff + (BOFS) + i * 2048 + kq);                     \
        _Pragma("unroll")                                                      \
        for (int jp = 0; jp < 2; jp++) {                                       \
            uint32_t th[4];                                                    \
            ldsm_x4(th, boff + (BOFS) + jp * 2048 + kq);                       \
            bh[jp * 2][0] = th[0]; bh[jp * 2 + 1][0] = th[1];                  \
            bh[jp * 2][1] = th[2]; bh[jp * 2 + 1][1] = th[3];                  \
        }                                                                      \
        _Pragma("unroll")                                                      \
        for (int i = 0; i < 4; i++)                                            \
            _Pragma("unroll")                                                  \
            for (int j = 0; j < 4; j++)                                        \
                mma_f16(acc[i][j], ah[i], bh[j]);                              \
    }                                                                          \
} while (0)

    STAGE2(sb);

    #pragma unroll 1
    for (int kt = 0; kt < KT; kt += 2) {
        asm volatile("cp.async.wait_group 0;");
        __syncthreads();
        if (kt + 1 < KT) STAGE2(sb + BUFB);
        KTILE(0u);

        asm volatile("cp.async.wait_group 0;");
        __syncthreads();
        if (kt + 2 < KT) STAGE2(sb);
        KTILE((uint32_t)BUFB);
    }
#undef STAGE2
#undef KTILE

    #pragma unroll
    for (int i = 0; i < 4; i++) {
        const int row0e = m0 + wm * 64 + i * 16 + g;
        #pragma unroll
        for (int j = 0; j < 4; j++) {
            const int col = n0 + wn * 32 + j * 8 + 2 * tig;
            const float2 bv = *(const float2*)(bias + col);
            float2 v0 = { acc[i][j][0] + bv.x, acc[i][j][1] + bv.y };
            float2 v1 = { acc[i][j][2] + bv.x, acc[i][j][3] + bv.y };
            if (RELU) {
                v0.x = fmaxf(v0.x, 0.f); v0.y = fmaxf(v0.y, 0.f);
                v1.x = fmaxf(v1.x, 0.f); v1.y = fmaxf(v1.y, 0.f);
            }
            if (HALF_OUT) {
                *(__half2*)(Yh + (size_t)row0e * N + col) = __floats2half2_rn(v0.x, v0.y);
                *(__half2*)(Yh + (size_t)(row0e + 8) * N + col) = __floats2half2_rn(v1.x, v1.y);
            } else {
                *(float2*)(Yf + (size_t)row0e * N + col) = v0;
                *(float2*)(Yf + (size_t)(row0e + 8) * N + col) = v1;
            }
        }
    }
}

// ---------------------------------------------------------------------------
// Tensor-core log-sparse attention: 32 queries/block, 256 threads (8 warps).
// S = Q@K^T (window, band-masked), softmax, O = P@V via mma.m16n8k16.
// Log-strided extras (<=4/query) via scalar side-path (Pex/Oex).
// ---------------------------------------------------------------------------
#define ATT_QS  0            // [32][64] half, SW128 (4 KB)
#define ATT_KS  4096         // [128][64] half, SW128 (16 KB)
#define ATT_VT  20480        // 2 chunks x [64][64] half, SW128 (16 KB)
#define ATT_PS  36864        // 2 chunks x [32][64] half, SW128 (8 KB)
#define ATT_OEX 45056        // float[32][64] (8 KB)
#define ATT_MX4 53248        // float[32][4]
#define ATT_SM4 53760        // float[32][4]
#define ATT_EXM 54272        // float[32]
#define ATT_EXS 54400        // float[32]
#define ATT_SMEM 54528

__global__ __launch_bounds__(256)
void attn_mma(const float* __restrict__ qkv, __half* __restrict__ oh) {
    extern __shared__ __align__(1024) char smc[];
    const uint32_t sb = (uint32_t)__cvta_generic_to_shared(smc);

    const int q0 = blockIdx.x * 32;
    const int h = blockIdx.y, b = blockIdx.z;
    const int tid = threadIdx.x, lane = tid & 31, warp = tid >> 5;
    const int wq = warp & 1, wk = warp >> 1;
    const int g = lane >> 2, tig = lane & 3, lrow = lane & 15;

    const float* base = qkv + (size_t)(b * SEQ) * 1536;

    // ---- stage Q [32][64] fp16 SW128 ----
    for (int e = tid; e < 512; e += 256) {
        const int row = e >> 4, c4 = (e & 15) << 2;
        const float4 v = *(const float4*)(base + (size_t)(q0 + row) * 1536 + h * 64 + c4);
        char* p = smc + ATT_QS + SWZ((uint32_t)(row * 128 + c4 * 2));
        *(__half2*)p       = __floats2half2_rn(v.x, v.y);
        *(__half2*)(p + 4) = __floats2half2_rn(v.z, v.w);
    }
    // ---- stage K [128][64] fp16 SW128 (rows 96..127 and j<0 -> zero) ----
    for (int e = tid; e < 2048; e += 256) {
        const int r = e >> 4, c4 = (e & 15) << 2;
        const int j = q0 - 64 + r;
        float4 v = {0.f, 0.f, 0.f, 0.f};
        if (j >= 0 && r < 96)
            v = *(const float4*)(base + (size_t)j * 1536 + 512 + h * 64 + c4);
        char* p = smc + ATT_KS + SWZ((uint32_t)(r * 128 + c4 * 2));
        *(__half2*)p       = __floats2half2_rn(v.x, v.y);
        *(__half2*)(p + 4) = __floats2half2_rn(v.z, v.w);
    }
    // ---- stage V^T: 2 chunks of [64 dims][64 keys] fp16 SW128 ----
    for (int e = tid; e < 2048; e += 256) {
        const int key = e & 127;
        const int dg = (e >> 7) << 2;        // dim group 0,4,...,60
        const int j = q0 - 64 + key;
        float4 v = {0.f, 0.f, 0.f, 0.f};
        if (j >= 0 && key < 96)
            v = *(const float4*)(base + (size_t)j * 1536 + 1024 + h * 64 + dg);
        char* vt = smc + ATT_VT + (key >> 6) * 8192;
        const int kc2 = (key & 63) * 2;
        *(__half*)(vt + SWZ((uint32_t)((dg + 0) * 128 + kc2))) = __float2half_rn(v.x);
        *(__half*)(vt + SWZ((uint32_t)((dg + 1) * 128 + kc2))) = __float2half_rn(v.y);
        *(__half*)(vt + SWZ((uint32_t)((dg + 2) * 128 + kc2))) = __float2half_rn(v.z);
        *(__half*)(vt + SWZ((uint32_t)((dg + 3) * 128 + kc2))) = __float2half_rn(v.w);
    }
    __syncthreads();

    // ---- extras scores (each warp owns 4 queries) ----
    float exs[4][4];
    int nes[4];
    {
        float* EXM = (float*)(smc + ATT_EXM);
        #pragma unroll
        for (int c = 0; c < 4; c++) {
            const int qi = warp * 4 + c;
            const int i = q0 + qi;
            const int ne = (i >= 128) + (i >= 256) + (i >= 512) + (i >= 1024);
            nes[c] = ne;
            const __half2 qh = *(__half2*)(smc + ATT_QS + SWZ((uint32_t)(qi * 128 + lane * 4)));
            const float2 qf = __half22float2(qh);
            float mex = -INFINITY;
            #pragma unroll
            for (int t = 0; t < 4; t++) {
                if (t < ne) {
                    const int j = i - (128 << t);
                    const float2 kf = *(const float2*)(base + (size_t)j * 1536 + 512 + h * 64 + 2 * lane);
                    float p = qf.x * kf.x + qf.y * kf.y;
                    #pragma unroll
                    for (int o2 = 16; o2; o2 >>= 1) p += __shfl_xor_sync(~0u, p, o2);
                    p *= 0.125f;
                    exs[c][t] = p;
                    mex = fmaxf(mex, p);
                }
            }
            if (lane == 0) EXM[qi] = mex;
        }
    }

    // ---- S = Q @ K^T (window) ----
    float S[4][4] = {};
    const uint32_t kbase = ((uint32_t)((lane >> 4) << 4)) ^ ((uint32_t)((lrow & 7) << 4));
    {
        const uint32_t qa = sb + ATT_QS + (uint32_t)((wq * 16 + lrow) * 128);
        const uint32_t kb = sb + ATT_KS + (uint32_t)((wk * 32 + lrow) * 128);
        #pragma unroll
        for (int ks = 0; ks < 4; ks++) {
            const uint32_t kq = ((uint32_t)(ks * 32)) ^ kbase;
            uint32_t A[4], th[4], B[4][2];
            ldsm_x4(A, qa + kq);
            ldsm_x4(th, kb + kq);
            B[0][0] = th[0]; B[1][0] = th[1]; B[0][1] = th[2]; B[1][1] = th[3];
            ldsm_x4(th, kb + 2048 + kq);
            B[2][0] = th[0]; B[3][0] = th[1]; B[2][1] = th[2]; B[3][1] = th[3];
            #pragma unroll
            for (int j = 0; j < 4; j++) mma_f16(S[j], A, B[j]);
        }
    }

    // ---- mask + scale + partial row max ----
    const int r0 = wq * 16 + g, r1 = r0 + 8;
    const int cmin = 64 - q0;          // j >= 0 constraint
    float m0 = -INFINITY, m1 = -INFINITY;
    #pragma unroll
    for (int j = 0; j < 4; j++) {
        const int col0 = wk * 32 + j * 8 + 2 * tig;
        const int col1 = col0 + 1;
        S[j][0] = (col0 >= r0 && col0 <= r0 + 64 && col0 >= cmin) ? S[j][0] * 0.125f : -INFINITY;
        S[j][1] = (col1 >= r0 && col1 <= r0 + 64 && col1 >= cmin) ? S[j][1] * 0.125f : -INFINITY;
        S[j][2] = (col0 >= r1 && col0 <= r1 + 64 && col0 >= cmin) ? S[j][2] * 0.125f : -INFINITY;
        S[j][3] = (col1 >= r1 && col1 <= r1 + 64 && col1 >= cmin) ? S[j][3] * 0.125f : -INFINITY;
        m0 = fmaxf(m0, fmaxf(S[j][0], S[j][1]));
        m1 = fmaxf(m1, fmaxf(S[j][2], S[j][3]));
    }
    m0 = fmaxf(m0, __shfl_xor_sync(~0u, m0, 1)); m0 = fmaxf(m0, __shfl_xor_sync(~0u, m0, 2));
    m1 = fmaxf(m1, __shfl_xor_sync(~0u, m1, 1)); m1 = fmaxf(m1, __shfl_xor_sync(~0u, m1, 2));
    {
        float* MX4 = (float*)(smc + ATT_MX4);
        if (tig == 0) { MX4[r0 * 4 + wk] = m0; MX4[r1 * 4 + wk] = m1; }
    }
    __syncthreads();

    // ---- final row max, exp, partial sums, store P (fp16) ----
    {
        float* MX4 = (float*)(smc + ATT_MX4);
        float* SM4 = (float*)(smc + ATT_SM4);
        float* EXM = (float*)(smc + ATT_EXM);
        const float mxf0 = fmaxf(fmaxf(fmaxf(MX4[r0 * 4], MX4[r0 * 4 + 1]),
                                       fmaxf(MX4[r0 * 4 + 2], MX4[r0 * 4 + 3])), EXM[r0]);
        const float mxf1 = fmaxf(fmaxf(fmaxf(MX4[r1 * 4], MX4[r1 * 4 + 1]),
                                       fmaxf(MX4[r1 * 4 + 2], MX4[r1 * 4 + 3])), EXM[r1]);
        float s0 = 0.f, s1 = 0.f;
        #pragma unroll
        for (int j = 0; j < 4; j++) {
            const float e0 = __expf(S[j][0] - mxf0), e1 = __expf(S[j][1] - mxf0);
            const float e2 = __expf(S[j][2] - mxf1), e3 = __expf(S[j][3] - mxf1);
            s0 += e0 + e1; s1 += e2 + e3;
            const int col0 = wk * 32 + j * 8 + 2 * tig;
            char* ps = smc + ATT_PS + (col0 >> 6) * 4096;
            const int kc2 = (col0 & 63) * 2;
            *(__half2*)(ps + SWZ((uint32_t)(r0 * 128 + kc2))) = __floats2half2_rn(e0, e1);
            *(__half2*)(ps + SWZ((uint32_t)(r1 * 128 + kc2))) = __floats2half2_rn(e2, e3);
        }
        s0 += __shfl_xor_sync(~0u, s0, 1); s0 += __shfl_xor_sync(~0u, s0, 2);
        s1 += __shfl_xor_sync(~0u, s1, 1); s1 += __shfl_xor_sync(~0u, s1, 2);
        if (tig == 0) { SM4[r0 * 4 + wk] = s0; SM4[r1 * 4 + wk] = s1; }

        // extras exp + sums (per-warp queries)
        float* EXS = (float*)(smc + ATT_EXS);
        #pragma unroll
        for (int c = 0; c < 4; c++) {
            const int qi = warp * 4 + c;
            const float mxfq = fmaxf(fmaxf(fmaxf(MX4[qi * 4], MX4[qi * 4 + 1]),
                                           fmaxf(MX4[qi * 4 + 2], MX4[qi * 4 + 3])), EXM[qi]);
            float es = 0.f;
            #pragma unroll
            for (int t = 0; t < 4; t++) {
                if (t < nes[c]) {
                    exs[c][t] = __expf(exs[c][t] - mxfq);
                    es += exs[c][t];
                }
            }
            if (lane == 0) EXS[qi] = es;
        }
    }
    __syncthreads();

    // ---- extras output Oex + PV MMA ----
    {
        float* OEX = (float*)(smc + ATT_OEX);
        #pragma unroll
        for (int c = 0; c < 4; c++) {
            const int qi = warp * 4 + c;
            const int i = q0 + qi;
            float2 a = {0.f, 0.f};
            #pragma unroll
            for (int t = 0; t < 4; t++) {
                if (t < nes[c]) {
                    const int j = i - (128 << t);
                    const float2 vf = *(const float2*)(base + (size_t)j * 1536 + 1024 + h * 64 + 2 * lane);
                    a.x += exs[c][t] * vf.x;
                    a.y += exs[c][t] * vf.y;
                }
            }
            *(float2*)(OEX + qi * 64 + 2 * lane) = a;
        }
    }
    float O[2][4] = {};
    {
        const uint32_t pa = sb + ATT_PS + (uint32_t)((wq * 16 + lrow) * 128);
        const uint32_t vb = sb + ATT_VT + (uint32_t)((wk * 16 + lrow) * 128);
        #pragma unroll
        for (int ch = 0; ch < 2; ch++) {
            #pragma unroll
            for (int ks = 0; ks < 4; ks++) {
                const uint32_t kq = ((uint32_t)(ks * 32)) ^ kbase;
                uint32_t A[4], th[4], B0[2], B1[2];
                ldsm_x4(A, pa + ch * 4096 + kq);
                ldsm_x4(th, vb + ch * 8192 + kq);
                B0[0] = th[0]; B1[0] = th[1]; B0[1] = th[2]; B1[1] = th[3];
                mma_f16(O[0], A, B0);
                mma_f16(O[1], A, B1);
            }
        }
    }
    __syncthreads();

    // ---- epilogue: O = (PV + Oex) / rowsum ----
    {
        float* SM4 = (float*)(smc + ATT_SM4);
        float* EXS = (float*)(smc + ATT_EXS);
        float* OEX = (float*)(smc + ATT_OEX);
        const float inv0 = 1.f / (SM4[r0 * 4] + SM4[r0 * 4 + 1] + SM4[r0 * 4 + 2] +
                                  SM4[r0 * 4 + 3] + EXS[r0]);
        const float inv1 = 1.f / (SM4[r1 * 4] + SM4[r1 * 4 + 1] + SM4[r1 * 4 + 2] +
                                  SM4[r1 * 4 + 3] + EXS[r1]);
        #pragma unroll
        for (int j = 0; j < 2; j++) {
            const int col0 = wk * 16 + j * 8 + 2 * tig;
            const float2 ex0 = *(const float2*)(OEX + r0 * 64 + col0);
            const float2 ex1 = *(const float2*)(OEX + r1 * 64 + col0);
            const __half2 h0 = __floats2half2_rn((O[j][0] + ex0.x) * inv0,
                                                 (O[j][1] + ex0.y) * inv0);
            const __half2 h1 = __floats2half2_rn((O[j][2] + ex1.x) * inv1,
                                                 (O[j][3] + ex1.y) * inv1);
            *(__half2*)(oh + (size_t)(b * SEQ + q0 + r0) * DM + h * 64 + col0) = h0;
            *(__half2*)(oh + (size_t)(b * SEQ + q0 + r1) * DM + h * 64 + col0) = h1;
        }
    }
}

// ---------------------------------------------------------------------------
// x = LayerNorm(x + d) * scale + bias; emits fp16 copy. 128 thr, float4.
// ---------------------------------------------------------------------------
__global__ __launch_bounds__(128)
void add_ln_kernel(float* __restrict__ x, const float* __restrict__ o,
                   const float* __restrict__ sc, const float* __restrict__ bi,
                   __half* __restrict__ xh) {
    const int row = blockIdx.x;
    const int t = threadIdx.x;
    const long base = (long)row * DM + 4 * t;

    const float4 xv = *(const float4*)(x + base);
    const float4 ov = *(const float4*)(o + base);
    const float v0 = xv.x + ov.x, v1 = xv.y + ov.y;
    const float v2 = xv.z + ov.z, v3 = xv.w + ov.w;
    float s = v0 + v1 + v2 + v3;
    float sq = v0 * v0 + v1 * v1 + v2 * v2 + v3 * v3;
    #pragma unroll
    for (int off = 16; off; off >>= 1) {
        s  += __shfl_xor_sync(0xffffffffu, s, off);
        sq += __shfl_xor_sync(0xffffffffu, sq, off);
    }
    __shared__ float ss[4], sqs[4];
    __shared__ float mean_s, rstd_s;
    const int w = t >> 5;
    if ((t & 31) == 0) { ss[w] = s; sqs[w] = sq; }
    __syncthreads();
    if (t == 0) {
        const float s1 = ss[0] + ss[1] + ss[2] + ss[3];
        const float s2 = sqs[0] + sqs[1] + sqs[2] + sqs[3];
        const float m = s1 / (float)DM;
        mean_s = m;
        rstd_s = rsqrtf(s2 / (float)DM - m * m + 1e-5f);
    }
    __syncthreads();
    const float m = mean_s, r = rstd_s;
    const float4 scv = *(const float4*)(sc + 4 * t);
    const float4 biv = *(const float4*)(bi + 4 * t);
    float4 y;
    y.x = (v0 - m) * r * scv.x + biv.x;
    y.y = (v1 - m) * r * scv.y + biv.y;
    y.z = (v2 - m) * r * scv.z + biv.z;
    y.w = (v3 - m) * r * scv.w + biv.w;
    *(float4*)(x + base) = y;
    *(__half2*)(xh + base)     = __floats2half2_rn(y.x, y.y);
    *(__half2*)(xh + base + 2) = __floats2half2_rn(y.z, y.w);
}

// ---------------------------------------------------------------------------
extern "C" void kernel_launch(void* const* d_in, const int* in_sizes, int n_in,
                              void* d_out, int out_size) {
    const float* src   = (const float*)d_in[0];
    const float* qkv_w = (const float*)d_in[2];
    const float* qkv_b = (const float*)d_in[3];
    const float* out_w = (const float*)d_in[4];
    const float* out_b = (const float*)d_in[5];
    const float* ln1_s = (const float*)d_in[6];
    const float* ln1_b = (const float*)d_in[7];
    const float* w1    = (const float*)d_in[8];
    const float* b1    = (const float*)d_in[9];
    const float* w2    = (const float*)d_in[10];
    const float* b2    = (const float*)d_in[11];
    const float* ln2_s = (const float*)d_in[12];
    const float* ln2_b = (const float*)d_in[13];

    float* x = (float*)d_out;

    float *qkv, *dbuf;
    __half *xh, *oh, *hh, *wh;
    cudaGetSymbolAddress((void**)&qkv, g_qkv);
    cudaGetSymbolAddress((void**)&dbuf, g_d);
    cudaGetSymbolAddress((void**)&xh, g_xh);
    cudaGetSymbolAddress((void**)&oh, g_oh);
    cudaGetSymbolAddress((void**)&hh, g_hh);
    cudaGetSymbolAddress((void**)&wh, g_wh);

    cudaFuncSetAttribute(gemm_tc<0,0,512,1536>, cudaFuncAttributeMaxDynamicSharedMemorySize, SMEMB);
    cudaFuncSetAttribute(gemm_tc<0,0,512,512>,  cudaFuncAttributeMaxDynamicSharedMemorySize, SMEMB);
    cudaFuncSetAttribute(gemm_tc<1,1,512,2048>, cudaFuncAttributeMaxDynamicSharedMemorySize, SMEMB);
    cudaFuncSetAttribute(gemm_tc<0,0,2048,512>, cudaFuncAttributeMaxDynamicSharedMemorySize, SMEMB);
    cudaFuncSetAttribute(attn_mma, cudaFuncAttributeMaxDynamicSharedMemorySize, ATT_SMEM);

    // launch order: #4 (ncu's pick) is attn_mma
    copy_conv<<<(ROWS*DM/4 + 255)/256, 256>>>(src, x, xh, ROWS*DM/4);                  // 1
    conv_all<<<(W_TOTAL/4 + 255)/256, 256>>>(qkv_w, out_w, w1, w2, wh);                // 2

    for (int l = 0; l < 2; l++) {
        gemm_tc<0,0,512,1536><<<dim3(12, 64), 256, SMEMB>>>(                           // 3
            xh, wh + OFF_QKV + (size_t)l*1536*512,
            qkv_b + (size_t)l*1536, qkv, nullptr);

        attn_mma<<<dim3(SEQ/32, NH, BATCH), 256, ATT_SMEM>>>(qkv, oh);                 // 4

        gemm_tc<0,0,512,512><<<dim3(4, 64), 256, SMEMB>>>(
            oh, wh + OFF_OUT + (size_t)l*512*512,
            out_b + (size_t)l*512, dbuf, nullptr);

        add_ln_kernel<<<ROWS, 128>>>(x, dbuf, ln1_s + l*DM, ln1_b + l*DM, xh);

        gemm_tc<1,1,512,2048><<<dim3(16, 64), 256, SMEMB>>>(
            xh, wh + OFF_W1 + (size_t)l*2048*512,
            b1 + (size_t)l*2048, nullptr, hh);

        gemm_tc<0,0,2048,512><<<dim3(4, 64), 256, SMEMB>>>(
            hh, wh + OFF_W2 + (size_t)l*512*2048,
            b2 + (size_t)l*512, dbuf, nullptr);

        add_ln_kernel<<<ROWS, 128>>>(x, dbuf, ln2_s + l*DM, ln2_b + l*DM, xh);
    }
}

// round 13
// speedup vs baseline: 12.0178x; 1.1815x over previous
#include <cuda_runtime.h>
#include <cuda_fp16.h>
#include <math.h>
#include <stdint.h>

#define SEQ 2048
#define DM 512
#define NH 8
#define DH 64
#define DFF 2048
#define BATCH 4
#define ROWS (BATCH * SEQ)   // 8192

// ---------------- device scratch (no allocation allowed) -------------------
__device__ float g_qkv[(size_t)ROWS * 3 * DM];
__device__ float g_d[(size_t)ROWS * DM];
__device__ __half g_xh[(size_t)ROWS * DM];
__device__ __half g_oh[(size_t)ROWS * DM];
__device__ __half g_hh[(size_t)ROWS * DFF];
#define W_TOTAL 6291456
__device__ __half g_wh[W_TOTAL];
#define OFF_QKV 0
#define OFF_OUT (2 * 1536 * 512)
#define OFF_W1  (OFF_OUT + 2 * 512 * 512)
#define OFF_W2  (OFF_W1 + 2 * 2048 * 512)

// ---------------------------------------------------------------------------
// helpers
// ---------------------------------------------------------------------------
__device__ __forceinline__ void cp16(uint32_t saddr, const void* g) {
    asm volatile("cp.async.cg.shared.global [%0], [%1], 16;" :: "r"(saddr), "l"(g));
}
__device__ __forceinline__ void ldsm_x4(uint32_t* r, uint32_t a) {
    asm volatile("ldmatrix.sync.aligned.m8n8.x4.shared.b16 {%0,%1,%2,%3}, [%4];"
                 : "=r"(r[0]), "=r"(r[1]), "=r"(r[2]), "=r"(r[3]) : "r"(a));
}
__device__ __forceinline__ void ldsm_x4_t(uint32_t* r, uint32_t a) {
    asm volatile("ldmatrix.sync.aligned.m8n8.x4.trans.shared.b16 {%0,%1,%2,%3}, [%4];"
                 : "=r"(r[0]), "=r"(r[1]), "=r"(r[2]), "=r"(r[3]) : "r"(a));
}
__device__ __forceinline__ void mma_f16(float* d, const uint32_t* a, const uint32_t* b) {
    asm volatile("mma.sync.aligned.m16n8k16.row.col.f32.f16.f16.f32 "
                 "{%0,%1,%2,%3}, {%4,%5,%6,%7}, {%8,%9}, {%0,%1,%2,%3};"
                 : "+f"(d[0]), "+f"(d[1]), "+f"(d[2]), "+f"(d[3])
                 : "r"(a[0]), "r"(a[1]), "r"(a[2]), "r"(a[3]), "r"(b[0]), "r"(b[1]));
}
#define SWZ(bo) ((bo) ^ (((bo) >> 3) & 0x70))

// ---------------------------------------------------------------------------
// conversion kernels
// ---------------------------------------------------------------------------
__global__ void conv_all(const float* __restrict__ qkv_w, const float* __restrict__ out_w,
                         const float* __restrict__ w1, const float* __restrict__ w2,
                         __half* __restrict__ dst) {
    const int i = blockIdx.x * blockDim.x + threadIdx.x;
    if (i >= W_TOTAL / 4) return;
    const int e = i * 4;
    const float* src;
    int local;
    if (e < OFF_OUT)      { src = qkv_w; local = e; }
    else if (e < OFF_W1)  { src = out_w; local = e - OFF_OUT; }
    else if (e < OFF_W2)  { src = w1;    local = e - OFF_W1; }
    else                  { src = w2;    local = e - OFF_W2; }
    const float4 v = *(const float4*)(src + local);
    ((__half2*)dst)[2 * i]     = __floats2half2_rn(v.x, v.y);
    ((__half2*)dst)[2 * i + 1] = __floats2half2_rn(v.z, v.w);
}

__global__ void copy_conv(const float* __restrict__ src, float* __restrict__ x,
                          __half* __restrict__ xh, int n4) {
    const int i = blockIdx.x * blockDim.x + threadIdx.x;
    if (i >= n4) return;
    const float4 v = ((const float4*)src)[i];
    ((float4*)x)[i] = v;
    ((__half2*)xh)[2 * i]     = __floats2half2_rn(v.x, v.y);
    ((__half2*)xh)[2 * i + 1] = __floats2half2_rn(v.z, v.w);
}

// ---------------------------------------------------------------------------
// GEMM (unchanged): plain fp16, 128x128 tile, BK=64, SW128 smem, 256 threads.
// ---------------------------------------------------------------------------
#define PLANEB 16384
#define BUFB (2 * PLANEB)
#define SMEMB (2 * BUFB)

template<int RELU, int HALF_OUT, int K, int N>
__global__ __launch_bounds__(256)
void gemm_tc(const __half* __restrict__ Xh, const __half* __restrict__ Wh,
             const float* __restrict__ bias, float* __restrict__ Yf,
             __half* __restrict__ Yh) {
    extern __shared__ __align__(1024) char smc[];
    const uint32_t sb = (uint32_t)__cvta_generic_to_shared(smc);

    const int tid = threadIdx.x;
    const int lane = tid & 31, warp = tid >> 5;
    const int wm = warp & 1, wn = warp >> 1;
    const int g = lane >> 2, tig = lane & 3;
    const int m0 = blockIdx.y * 128, n0 = blockIdx.x * 128;

    float acc[4][4][4] = {};
    constexpr int KT = K >> 6;

    const int row0 = tid >> 3, ch = tid & 7;
    const __half* gp0 = Xh + (size_t)(m0 + row0) * K + ch * 8;
    const __half* gp1 = Wh + (size_t)(n0 + row0) * K + ch * 8;
    const uint32_t srow = SWZ((uint32_t)(row0 * 128 + ch * 16));

    const int lrow = lane & 15;
    const uint32_t kbase = ((uint32_t)((lane >> 4) << 4)) ^ ((uint32_t)((lrow & 7) << 4));
    const uint32_t aoff = sb + (uint32_t)((wm * 64 + lrow) * 128);
    const uint32_t boff = sb + (uint32_t)((wn * 32 + lrow) * 128) + (uint32_t)PLANEB;

#define STAGE2(SBUF) do {                                                      \
    cp16((SBUF) + srow,                  gp0);                                 \
    cp16((SBUF) + srow + 4096,           gp0 + 32 * K);                        \
    cp16((SBUF) + srow + 8192,           gp0 + 64 * K);                        \
    cp16((SBUF) + srow + 12288,          gp0 + 96 * K);                        \
    cp16((SBUF) + PLANEB + srow,         gp1);                                 \
    cp16((SBUF) + PLANEB + srow + 4096,  gp1 + 32 * K);                        \
    cp16((SBUF) + PLANEB + srow + 8192,  gp1 + 64 * K);                        \
    cp16((SBUF) + PLANEB + srow + 12288, gp1 + 96 * K);                        \
    asm volatile("cp.async.commit_group;");                                    \
    gp0 += 64; gp1 += 64;                                                      \
} while (0)

#define KTILE(BOFS) do {                                                       \
    _Pragma("unroll")                                                          \
    for (int ks = 0; ks < 4; ks++) {                                           \
        const uint32_t kq = ((uint32_t)(ks * 32)) ^ kbase;                     \
        uint32_t ah[4][4], bh[4][2];                                           \
        _Pragma("unroll")                                                      \
        for (int i = 0; i < 4; i++)                                            \
            ldsm_x4(ah[i], aoff + (BOFS) + i * 2048 + kq);                     \
        _Pragma("unroll")                                                      \
        for (int jp = 0; jp < 2; jp++) {                                       \
            uint32_t th[4];                                                    \
            ldsm_x4(th, boff + (BOFS) + jp * 2048 + kq);                       \
            bh[jp * 2][0] = th[0]; bh[jp * 2 + 1][0] = th[1];                  \
            bh[jp * 2][1] = th[2]; bh[jp * 2 + 1][1] = th[3];                  \
        }                                                                      \
        _Pragma("unroll")                                                      \
        for (int i = 0; i < 4; i++)                                            \
            _Pragma("unroll")                                                  \
            for (int j = 0; j < 4; j++)                                        \
                mma_f16(acc[i][j], ah[i], bh[j]);                              \
    }                                                                          \
} while (0)

    STAGE2(sb);

    #pragma unroll 1
    for (int kt = 0; kt < KT; kt += 2) {
        asm volatile("cp.async.wait_group 0;");
        __syncthreads();
        if (kt + 1 < KT) STAGE2(sb + BUFB);
        KTILE(0u);

        asm volatile("cp.async.wait_group 0;");
        __syncthreads();
        if (kt + 2 < KT) STAGE2(sb);
        KTILE((uint32_t)BUFB);
    }
#undef STAGE2
#undef KTILE

    #pragma unroll
    for (int i = 0; i < 4; i++) {
        const int row0e = m0 + wm * 64 + i * 16 + g;
        #pragma unroll
        for (int j = 0; j < 4; j++) {
            const int col = n0 + wn * 32 + j * 8 + 2 * tig;
            const float2 bv = *(const float2*)(bias + col);
            float2 v0 = { acc[i][j][0] + bv.x, acc[i][j][1] + bv.y };
            float2 v1 = { acc[i][j][2] + bv.x, acc[i][j][3] + bv.y };
            if (RELU) {
                v0.x = fmaxf(v0.x, 0.f); v0.y = fmaxf(v0.y, 0.f);
                v1.x = fmaxf(v1.x, 0.f); v1.y = fmaxf(v1.y, 0.f);
            }
            if (HALF_OUT) {
                *(__half2*)(Yh + (size_t)row0e * N + col) = __floats2half2_rn(v0.x, v0.y);
                *(__half2*)(Yh + (size_t)(row0e + 8) * N + col) = __floats2half2_rn(v1.x, v1.y);
            } else {
                *(float2*)(Yf + (size_t)row0e * N + col) = v0;
                *(float2*)(Yf + (size_t)(row0e + 8) * N + col) = v1;
            }
        }
    }
}

// ---------------------------------------------------------------------------
// Tensor-core log-sparse attention v2: V staged [key][dim] (like K) and
// loaded with ldmatrix.trans; extras parallel across lanes; 3 CTAs/SM.
// ---------------------------------------------------------------------------
#define ATT_QS  0            // [32][64] half SW128 (4 KB)
#define ATT_KS  4096         // [128][64] half SW128 (16 KB)
#define ATT_VS  20480        // [128][64] half SW128 (16 KB)
#define ATT_PS  36864        // 2 chunks x [32][64] half SW128 (8 KB)
#define ATT_OEX 45056        // float[32][64] (8 KB)
#define ATT_MX4 53248        // float[32][4]
#define ATT_SM4 53760        // float[32][4]
#define ATT_EXM 54272        // float[32]
#define ATT_EXS 54400        // float[32]
#define ATT_EXP 54528        // float[32][4]
#define ATT_SMEM 55040

__global__ __launch_bounds__(256, 3)
void attn_mma(const float* __restrict__ qkv, __half* __restrict__ oh) {
    extern __shared__ __align__(1024) char smc[];
    const uint32_t sb = (uint32_t)__cvta_generic_to_shared(smc);

    const int q0 = blockIdx.x * 32;
    const int h = blockIdx.y, b = blockIdx.z;
    const int tid = threadIdx.x, lane = tid & 31, warp = tid >> 5;
    const int wq = warp & 1, wk = warp >> 1;
    const int g = lane >> 2, tig = lane & 3, lrow = lane & 15;

    const float* base = qkv + (size_t)(b * SEQ) * 1536;

    // ---- stage Q [32][64] fp16 SW128 ----
    for (int e = tid; e < 512; e += 256) {
        const int row = e >> 4, c4 = (e & 15) << 2;
        const float4 v = *(const float4*)(base + (size_t)(q0 + row) * 1536 + h * 64 + c4);
        char* p = smc + ATT_QS + SWZ((uint32_t)(row * 128 + c4 * 2));
        *(__half2*)p       = __floats2half2_rn(v.x, v.y);
        *(__half2*)(p + 4) = __floats2half2_rn(v.z, v.w);
    }
    // ---- stage K and V [128][64] fp16 SW128 (rows 96..127 / j<0 -> zero) ----
    for (int e = tid; e < 2048; e += 256) {
        const int r = e >> 4, c4 = (e & 15) << 2;
        const int j = q0 - 64 + r;
        float4 kv = {0.f, 0.f, 0.f, 0.f}, vv = {0.f, 0.f, 0.f, 0.f};
        if (j >= 0 && r < 96) {
            kv = *(const float4*)(base + (size_t)j * 1536 + 512 + h * 64 + c4);
            vv = *(const float4*)(base + (size_t)j * 1536 + 1024 + h * 64 + c4);
        }
        const uint32_t so = SWZ((uint32_t)(r * 128 + c4 * 2));
        char* pk = smc + ATT_KS + so;
        *(__half2*)pk       = __floats2half2_rn(kv.x, kv.y);
        *(__half2*)(pk + 4) = __floats2half2_rn(kv.z, kv.w);
        char* pv = smc + ATT_VS + so;
        *(__half2*)pv       = __floats2half2_rn(vv.x, vv.y);
        *(__half2*)(pv + 4) = __floats2half2_rn(vv.z, vv.w);
    }

    // ---- extras raw scores (lanes: t = lane>>3, 8 lanes per t) ----
    {
        float* EXM = (float*)(smc + ATT_EXM);
        float* EXPS = (float*)(smc + ATT_EXP);
        const int te = lane >> 3, g8 = lane & 7;
        #pragma unroll
        for (int c = 0; c < 4; c++) {
            const int qi = warp * 4 + c;
            const int i = q0 + qi;
            const int ne = (i >= 128) + (i >= 256) + (i >= 512) + (i >= 1024);
            float pt = 0.f;
            if (te < ne) {
                const int j = i - (128 << te);
                const float* kp = base + (size_t)j * 1536 + 512 + h * 64 + g8 * 8;
                const float* qp = base + (size_t)i * 1536 + h * 64 + g8 * 8;
                const float4 ka = *(const float4*)kp;
                const float4 kb = *(const float4*)(kp + 4);
                const float4 qa = *(const float4*)qp;
                const float4 qb = *(const float4*)(qp + 4);
                pt = qa.x * ka.x + qa.y * ka.y + qa.z * ka.z + qa.w * ka.w
                   + qb.x * kb.x + qb.y * kb.y + qb.z * kb.z + qb.w * kb.w;
            }
            pt += __shfl_xor_sync(~0u, pt, 1);
            pt += __shfl_xor_sync(~0u, pt, 2);
            pt += __shfl_xor_sync(~0u, pt, 4);
            pt *= 0.125f;
            const float p0 = __shfl_sync(~0u, pt, 0);
            const float p1 = __shfl_sync(~0u, pt, 8);
            const float p2 = __shfl_sync(~0u, pt, 16);
            const float p3 = __shfl_sync(~0u, pt, 24);
            float mex = -INFINITY;
            if (ne > 0) mex = p0;
            if (ne > 1) mex = fmaxf(mex, p1);
            if (ne > 2) mex = fmaxf(mex, p2);
            if (ne > 3) mex = fmaxf(mex, p3);
            if (lane == 0) {
                EXM[qi] = mex;
                EXPS[qi * 4 + 0] = p0; EXPS[qi * 4 + 1] = p1;
                EXPS[qi * 4 + 2] = p2; EXPS[qi * 4 + 3] = p3;
            }
        }
    }
    __syncthreads();

    // ---- S = Q @ K^T (window) ----
    float S[4][4] = {};
    const uint32_t kbase = ((uint32_t)((lane >> 4) << 4)) ^ ((uint32_t)((lrow & 7) << 4));
    {
        const uint32_t qa = sb + ATT_QS + (uint32_t)((wq * 16 + lrow) * 128);
        const uint32_t kb = sb + ATT_KS + (uint32_t)((wk * 32 + lrow) * 128);
        #pragma unroll
        for (int ks = 0; ks < 4; ks++) {
            const uint32_t kq = ((uint32_t)(ks * 32)) ^ kbase;
            uint32_t A[4], th[4], B[4][2];
            ldsm_x4(A, qa + kq);
            ldsm_x4(th, kb + kq);
            B[0][0] = th[0]; B[1][0] = th[1]; B[0][1] = th[2]; B[1][1] = th[3];
            ldsm_x4(th, kb + 2048 + kq);
            B[2][0] = th[0]; B[3][0] = th[1]; B[2][1] = th[2]; B[3][1] = th[3];
            #pragma unroll
            for (int j = 0; j < 4; j++) mma_f16(S[j], A, B[j]);
        }
    }

    // ---- mask + scale + partial row max ----
    const int r0 = wq * 16 + g, r1 = r0 + 8;
    const int cmin = 64 - q0;
    float m0 = -INFINITY, m1 = -INFINITY;
    #pragma unroll
    for (int j = 0; j < 4; j++) {
        const int col0 = wk * 32 + j * 8 + 2 * tig;
        const int col1 = col0 + 1;
        S[j][0] = (col0 >= r0 && col0 <= r0 + 64 && col0 >= cmin) ? S[j][0] * 0.125f : -INFINITY;
        S[j][1] = (col1 >= r0 && col1 <= r0 + 64 && col1 >= cmin) ? S[j][1] * 0.125f : -INFINITY;
        S[j][2] = (col0 >= r1 && col0 <= r1 + 64 && col0 >= cmin) ? S[j][2] * 0.125f : -INFINITY;
        S[j][3] = (col1 >= r1 && col1 <= r1 + 64 && col1 >= cmin) ? S[j][3] * 0.125f : -INFINITY;
        m0 = fmaxf(m0, fmaxf(S[j][0], S[j][1]));
        m1 = fmaxf(m1, fmaxf(S[j][2], S[j][3]));
    }
    m0 = fmaxf(m0, __shfl_xor_sync(~0u, m0, 1)); m0 = fmaxf(m0, __shfl_xor_sync(~0u, m0, 2));
    m1 = fmaxf(m1, __shfl_xor_sync(~0u, m1, 1)); m1 = fmaxf(m1, __shfl_xor_sync(~0u, m1, 2));
    {
        float* MX4 = (float*)(smc + ATT_MX4);
        if (tig == 0) { MX4[r0 * 4 + wk] = m0; MX4[r1 * 4 + wk] = m1; }
    }
    __syncthreads();

    // ---- final row max, exp, partial sums, store P; extras exp ----
    {
        float* MX4 = (float*)(smc + ATT_MX4);
        float* SM4 = (float*)(smc + ATT_SM4);
        float* EXM = (float*)(smc + ATT_EXM);
        const float mxf0 = fmaxf(fmaxf(fmaxf(MX4[r0 * 4], MX4[r0 * 4 + 1]),
                                       fmaxf(MX4[r0 * 4 + 2], MX4[r0 * 4 + 3])), EXM[r0]);
        const float mxf1 = fmaxf(fmaxf(fmaxf(MX4[r1 * 4], MX4[r1 * 4 + 1]),
                                       fmaxf(MX4[r1 * 4 + 2], MX4[r1 * 4 + 3])), EXM[r1]);
        float s0 = 0.f, s1 = 0.f;
        #pragma unroll
        for (int j = 0; j < 4; j++) {
            const float e0 = __expf(S[j][0] - mxf0), e1 = __expf(S[j][1] - mxf0);
            const float e2 = __expf(S[j][2] - mxf1), e3 = __expf(S[j][3] - mxf1);
            s0 += e0 + e1; s1 += e2 + e3;
            const int col0 = wk * 32 + j * 8 + 2 * tig;
            char* ps = smc + ATT_PS + (col0 >> 6) * 4096;
            const int kc2 = (col0 & 63) * 2;
            *(__half2*)(ps + SWZ((uint32_t)(r0 * 128 + kc2))) = __floats2half2_rn(e0, e1);
            *(__half2*)(ps + SWZ((uint32_t)(r1 * 128 + kc2))) = __floats2half2_rn(e2, e3);
        }
        s0 += __shfl_xor_sync(~0u, s0, 1); s0 += __shfl_xor_sync(~0u, s0, 2);
        s1 += __shfl_xor_sync(~0u, s1, 1); s1 += __shfl_xor_sync(~0u, s1, 2);
        if (tig == 0) { SM4[r0 * 4 + wk] = s0; SM4[r1 * 4 + wk] = s1; }

        float* EXS = (float*)(smc + ATT_EXS);
        float* EXPS = (float*)(smc + ATT_EXP);
        #pragma unroll
        for (int c = 0; c < 4; c++) {
            const int qi = warp * 4 + c;
            const int i = q0 + qi;
            const int ne = (i >= 128) + (i >= 256) + (i >= 512) + (i >= 1024);
            const float mxfq = fmaxf(fmaxf(fmaxf(MX4[qi * 4], MX4[qi * 4 + 1]),
                                           fmaxf(MX4[qi * 4 + 2], MX4[qi * 4 + 3])), EXM[qi]);
            float e = 0.f;
            if (lane < 4) {
                e = (lane < ne) ? __expf(EXPS[qi * 4 + lane] - mxfq) : 0.f;
                EXPS[qi * 4 + lane] = e;
            }
            e += __shfl_xor_sync(~0u, e, 1);
            e += __shfl_xor_sync(~0u, e, 2);
            if (lane == 0) EXS[qi] = e;
        }
    }
    __syncthreads();

    // ---- extras output Oex ----
    {
        float* OEX = (float*)(smc + ATT_OEX);
        float* EXPS = (float*)(smc + ATT_EXP);
        #pragma unroll
        for (int c = 0; c < 4; c++) {
            const int qi = warp * 4 + c;
            const int i = q0 + qi;
            const int ne = (i >= 128) + (i >= 256) + (i >= 512) + (i >= 1024);
            float2 a = {0.f, 0.f};
            #pragma unroll
            for (int t = 0; t < 4; t++) {
                if (t < ne) {
                    const int j = i - (128 << t);
                    const float2 vf = *(const float2*)(base + (size_t)j * 1536 + 1024 + h * 64 + 2 * lane);
                    const float wgt = EXPS[qi * 4 + t];
                    a.x += wgt * vf.x;
                    a.y += wgt * vf.y;
                }
            }
            *(float2*)(OEX + qi * 64 + 2 * lane) = a;
        }
    }
    // ---- O = P @ V (ldmatrix.trans on V[key][dim]) ----
    float O[2][4] = {};
    {
        const uint32_t pa = sb + ATT_PS + (uint32_t)((wq * 16 + lrow) * 128);
        const uint32_t vb = sb + ATT_VS + (uint32_t)(lrow * 128);
        const uint32_t vdim = ((uint32_t)(wk * 32 + ((lane >> 4) << 4)))
                            ^ ((uint32_t)((lrow & 7) << 4));
        #pragma unroll
        for (int ks = 0; ks < 8; ks++) {
            uint32_t A[4], th[4];
            const uint32_t kq = ((uint32_t)((ks & 3) * 32)) ^ kbase;
            ldsm_x4(A, pa + (ks >> 2) * 4096 + kq);
            ldsm_x4_t(th, vb + ks * 2048 + vdim);
            uint32_t B0[2] = { th[0], th[1] };
            uint32_t B1[2] = { th[2], th[3] };
            mma_f16(O[0], A, B0);
            mma_f16(O[1], A, B1);
        }
    }
    __syncthreads();

    // ---- epilogue: O = (PV + Oex) / rowsum ----
    {
        float* SM4 = (float*)(smc + ATT_SM4);
        float* EXS = (float*)(smc + ATT_EXS);
        float* OEX = (float*)(smc + ATT_OEX);
        const float inv0 = 1.f / (SM4[r0 * 4] + SM4[r0 * 4 + 1] + SM4[r0 * 4 + 2] +
                                  SM4[r0 * 4 + 3] + EXS[r0]);
        const float inv1 = 1.f / (SM4[r1 * 4] + SM4[r1 * 4 + 1] + SM4[r1 * 4 + 2] +
                                  SM4[r1 * 4 + 3] + EXS[r1]);
        #pragma unroll
        for (int j = 0; j < 2; j++) {
            const int col0 = wk * 16 + j * 8 + 2 * tig;
            const float2 ex0 = *(const float2*)(OEX + r0 * 64 + col0);
            const float2 ex1 = *(const float2*)(OEX + r1 * 64 + col0);
            const __half2 h0 = __floats2half2_rn((O[j][0] + ex0.x) * inv0,
                                                 (O[j][1] + ex0.y) * inv0);
            const __half2 h1 = __floats2half2_rn((O[j][2] + ex1.x) * inv1,
                                                 (O[j][3] + ex1.y) * inv1);
            *(__half2*)(oh + (size_t)(b * SEQ + q0 + r0) * DM + h * 64 + col0) = h0;
            *(__half2*)(oh + (size_t)(b * SEQ + q0 + r1) * DM + h * 64 + col0) = h1;
        }
    }
}

// ---------------------------------------------------------------------------
// x = LayerNorm(x + d) * scale + bias; emits fp16 copy. 128 thr, float4.
// ---------------------------------------------------------------------------
__global__ __launch_bounds__(128)
void add_ln_kernel(float* __restrict__ x, const float* __restrict__ o,
                   const float* __restrict__ sc, const float* __restrict__ bi,
                   __half* __restrict__ xh) {
    const int row = blockIdx.x;
    const int t = threadIdx.x;
    const long base = (long)row * DM + 4 * t;

    const float4 xv = *(const float4*)(x + base);
    const float4 ov = *(const float4*)(o + base);
    const float v0 = xv.x + ov.x, v1 = xv.y + ov.y;
    const float v2 = xv.z + ov.z, v3 = xv.w + ov.w;
    float s = v0 + v1 + v2 + v3;
    float sq = v0 * v0 + v1 * v1 + v2 * v2 + v3 * v3;
    #pragma unroll
    for (int off = 16; off; off >>= 1) {
        s  += __shfl_xor_sync(0xffffffffu, s, off);
        sq += __shfl_xor_sync(0xffffffffu, sq, off);
    }
    __shared__ float ss[4], sqs[4];
    __shared__ float mean_s, rstd_s;
    const int w = t >> 5;
    if ((t & 31) == 0) { ss[w] = s; sqs[w] = sq; }
    __syncthreads();
    if (t == 0) {
        const float s1 = ss[0] + ss[1] + ss[2] + ss[3];
        const float s2 = sqs[0] + sqs[1] + sqs[2] + sqs[3];
        const float m = s1 / (float)DM;
        mean_s = m;
        rstd_s = rsqrtf(s2 / (float)DM - m * m + 1e-5f);
    }
    __syncthreads();
    const float m = mean_s, r = rstd_s;
    const float4 scv = *(const float4*)(sc + 4 * t);
    const float4 biv = *(const float4*)(bi + 4 * t);
    float4 y;
    y.x = (v0 - m) * r * scv.x + biv.x;
    y.y = (v1 - m) * r * scv.y + biv.y;
    y.z = (v2 - m) * r * scv.z + biv.z;
    y.w = (v3 - m) * r * scv.w + biv.w;
    *(float4*)(x + base) = y;
    *(__half2*)(xh + base)     = __floats2half2_rn(y.x, y.y);
    *(__half2*)(xh + base + 2) = __floats2half2_rn(y.z, y.w);
}

// ---------------------------------------------------------------------------
extern "C" void kernel_launch(void* const* d_in, const int* in_sizes, int n_in,
                              void* d_out, int out_size) {
    const float* src   = (const float*)d_in[0];
    const float* qkv_w = (const float*)d_in[2];
    const float* qkv_b = (const float*)d_in[3];
    const float* out_w = (const float*)d_in[4];
    const float* out_b = (const float*)d_in[5];
    const float* ln1_s = (const float*)d_in[6];
    const float* ln1_b = (const float*)d_in[7];
    const float* w1    = (const float*)d_in[8];
    const float* b1    = (const float*)d_in[9];
    const float* w2    = (const float*)d_in[10];
    const float* b2    = (const float*)d_in[11];
    const float* ln2_s = (const float*)d_in[12];
    const float* ln2_b = (const float*)d_in[13];

    float* x = (float*)d_out;

    float *qkv, *dbuf;
    __half *xh, *oh, *hh, *wh;
    cudaGetSymbolAddress((void**)&qkv, g_qkv);
    cudaGetSymbolAddress((void**)&dbuf, g_d);
    cudaGetSymbolAddress((void**)&xh, g_xh);
    cudaGetSymbolAddress((void**)&oh, g_oh);
    cudaGetSymbolAddress((void**)&hh, g_hh);
    cudaGetSymbolAddress((void**)&wh, g_wh);

    cudaFuncSetAttribute(gemm_tc<0,0,512,1536>, cudaFuncAttributeMaxDynamicSharedMemorySize, SMEMB);
    cudaFuncSetAttribute(gemm_tc<0,0,512,512>,  cudaFuncAttributeMaxDynamicSharedMemorySize, SMEMB);
    cudaFuncSetAttribute(gemm_tc<1,1,512,2048>, cudaFuncAttributeMaxDynamicSharedMemorySize, SMEMB);
    cudaFuncSetAttribute(gemm_tc<0,0,2048,512>, cudaFuncAttributeMaxDynamicSharedMemorySize, SMEMB);
    cudaFuncSetAttribute(attn_mma, cudaFuncAttributeMaxDynamicSharedMemorySize, ATT_SMEM);

    // launch order: #4 (ncu's pick) is attn_mma
    copy_conv<<<(ROWS*DM/4 + 255)/256, 256>>>(src, x, xh, ROWS*DM/4);                  // 1
    conv_all<<<(W_TOTAL/4 + 255)/256, 256>>>(qkv_w, out_w, w1, w2, wh);                // 2

    for (int l = 0; l < 2; l++) {
        gemm_tc<0,0,512,1536><<<dim3(12, 64), 256, SMEMB>>>(                           // 3
            xh, wh + OFF_QKV + (size_t)l*1536*512,
            qkv_b + (size_t)l*1536, qkv, nullptr);

        attn_mma<<<dim3(SEQ/32, NH, BATCH), 256, ATT_SMEM>>>(qkv, oh);                 // 4

        gemm_tc<0,0,512,512><<<dim3(4, 64), 256, SMEMB>>>(
            oh, wh + OFF_OUT + (size_t)l*512*512,
            out_b + (size_t)l*512, dbuf, nullptr);

        add_ln_kernel<<<ROWS, 128>>>(x, dbuf, ln1_s + l*DM, ln1_b + l*DM, xh);

        gemm_tc<1,1,512,2048><<<dim3(16, 64), 256, SMEMB>>>(
            xh, wh + OFF_W1 + (size_t)l*2048*512,
            b1 + (size_t)l*2048, nullptr, hh);

        gemm_tc<0,0,2048,512><<<dim3(4, 64), 256, SMEMB>>>(
            hh, wh + OFF_W2 + (size_t)l*512*2048,
            b2 + (size_t)l*512, dbuf, nullptr);

        add_ln_kernel<<<ROWS, 128>>>(x, dbuf, ln2_s + l*DM, ln2_b + l*DM, xh);
    }
}

// round 14
// speedup vs baseline: 12.2781x; 1.0217x over previous
#include <cuda_runtime.h>
#include <cuda_fp16.h>
#include <math.h>
#include <stdint.h>

#define SEQ 2048
#define DM 512
#define NH 8
#define DH 64
#define DFF 2048
#define BATCH 4
#define ROWS (BATCH * SEQ)   // 8192

// ---------------- device scratch (no allocation allowed) -------------------
__device__ float g_qkv[(size_t)ROWS * 3 * DM];
__device__ float g_d[(size_t)ROWS * DM];
__device__ __half g_xh[(size_t)ROWS * DM];
__device__ __half g_oh[(size_t)ROWS * DM];
__device__ __half g_hh[(size_t)ROWS * DFF];
#define W_TOTAL 6291456
__device__ __half g_wh[W_TOTAL];
#define OFF_QKV 0
#define OFF_OUT (2 * 1536 * 512)
#define OFF_W1  (OFF_OUT + 2 * 512 * 512)
#define OFF_W2  (OFF_W1 + 2 * 2048 * 512)

// ---------------------------------------------------------------------------
// helpers
// ---------------------------------------------------------------------------
__device__ __forceinline__ void cp16(uint32_t saddr, const void* g) {
    asm volatile("cp.async.cg.shared.global [%0], [%1], 16;" :: "r"(saddr), "l"(g));
}
__device__ __forceinline__ void ldsm_x4(uint32_t* r, uint32_t a) {
    asm volatile("ldmatrix.sync.aligned.m8n8.x4.shared.b16 {%0,%1,%2,%3}, [%4];"
                 : "=r"(r[0]), "=r"(r[1]), "=r"(r[2]), "=r"(r[3]) : "r"(a));
}
__device__ __forceinline__ void ldsm_x4_t(uint32_t* r, uint32_t a) {
    asm volatile("ldmatrix.sync.aligned.m8n8.x4.trans.shared.b16 {%0,%1,%2,%3}, [%4];"
                 : "=r"(r[0]), "=r"(r[1]), "=r"(r[2]), "=r"(r[3]) : "r"(a));
}
__device__ __forceinline__ void mma_f16(float* d, const uint32_t* a, const uint32_t* b) {
    asm volatile("mma.sync.aligned.m16n8k16.row.col.f32.f16.f16.f32 "
                 "{%0,%1,%2,%3}, {%4,%5,%6,%7}, {%8,%9}, {%0,%1,%2,%3};"
                 : "+f"(d[0]), "+f"(d[1]), "+f"(d[2]), "+f"(d[3])
                 : "r"(a[0]), "r"(a[1]), "r"(a[2]), "r"(a[3]), "r"(b[0]), "r"(b[1]));
}
#define SWZ(bo) ((bo) ^ (((bo) >> 3) & 0x70))

// ---------------------------------------------------------------------------
// conversion kernels
// ---------------------------------------------------------------------------
__global__ void conv_all(const float* __restrict__ qkv_w, const float* __restrict__ out_w,
                         const float* __restrict__ w1, const float* __restrict__ w2,
                         __half* __restrict__ dst) {
    const int i = blockIdx.x * blockDim.x + threadIdx.x;
    if (i >= W_TOTAL / 4) return;
    const int e = i * 4;
    const float* src;
    int local;
    if (e < OFF_OUT)      { src = qkv_w; local = e; }
    else if (e < OFF_W1)  { src = out_w; local = e - OFF_OUT; }
    else if (e < OFF_W2)  { src = w1;    local = e - OFF_W1; }
    else                  { src = w2;    local = e - OFF_W2; }
    const float4 v = *(const float4*)(src + local);
    ((__half2*)dst)[2 * i]     = __floats2half2_rn(v.x, v.y);
    ((__half2*)dst)[2 * i + 1] = __floats2half2_rn(v.z, v.w);
}

__global__ void copy_conv(const float* __restrict__ src, float* __restrict__ x,
                          __half* __restrict__ xh, int n4) {
    const int i = blockIdx.x * blockDim.x + threadIdx.x;
    if (i >= n4) return;
    const float4 v = ((const float4*)src)[i];
    ((float4*)x)[i] = v;
    ((__half2*)xh)[2 * i]     = __floats2half2_rn(v.x, v.y);
    ((__half2*)xh)[2 * i + 1] = __floats2half2_rn(v.z, v.w);
}

// ---------------------------------------------------------------------------
// GEMM v2: plain fp16, 128x128 block tile, BK=64, SW128 smem, double-buffered.
// 128 threads / 4 warps; each warp owns 64x64 (4 MMA per LDSM.x4).
// ---------------------------------------------------------------------------
#define PLANEB 16384
#define BUFB (2 * PLANEB)
#define SMEMB (2 * BUFB)

template<int RELU, int HALF_OUT, int K, int N>
__global__ __launch_bounds__(128)
void gemm_tc(const __half* __restrict__ Xh, const __half* __restrict__ Wh,
             const float* __restrict__ bias, float* __restrict__ Yf,
             __half* __restrict__ Yh) {
    extern __shared__ __align__(1024) char smc[];
    const uint32_t sb = (uint32_t)__cvta_generic_to_shared(smc);

    const int tid = threadIdx.x;
    const int lane = tid & 31, warp = tid >> 5;
    const int wm = warp & 1, wn = warp >> 1;
    const int g = lane >> 2, tig = lane & 3;
    const int m0 = blockIdx.y * 128, n0 = blockIdx.x * 128;

    float acc[4][8][4] = {};
    constexpr int KT = K >> 6;

    // staging: 128 threads, 16 rows x 8 chunks; each thread does 8 rows/plane
    const int row0 = tid >> 3, ch = tid & 7;          // row0 0..15, ch 0..7
    const __half* gp0 = Xh + (size_t)(m0 + row0) * K + ch * 8;
    const __half* gp1 = Wh + (size_t)(n0 + row0) * K + ch * 8;
    const uint32_t srow = SWZ((uint32_t)(row0 * 128 + ch * 16));

    const int lrow = lane & 15;
    const uint32_t kbase = ((uint32_t)((lane >> 4) << 4)) ^ ((uint32_t)((lrow & 7) << 4));
    const uint32_t aoff = sb + (uint32_t)((wm * 64 + lrow) * 128);
    const uint32_t boff = sb + (uint32_t)((wn * 64 + lrow) * 128) + (uint32_t)PLANEB;

#define STAGE2(SBUF) do {                                                      \
    _Pragma("unroll")                                                          \
    for (int r_ = 0; r_ < 8; r_++) {                                           \
        cp16((SBUF) + srow + r_ * 2048,          gp0 + r_ * 16 * K);           \
        cp16((SBUF) + PLANEB + srow + r_ * 2048, gp1 + r_ * 16 * K);           \
    }                                                                          \
    asm volatile("cp.async.commit_group;");                                    \
    gp0 += 64; gp1 += 64;                                                      \
} while (0)

#define KTILE(BOFS) do {                                                       \
    _Pragma("unroll")                                                          \
    for (int ks = 0; ks < 4; ks++) {                                           \
        const uint32_t kq = ((uint32_t)(ks * 32)) ^ kbase;                     \
        uint32_t ah[4][4], bh[8][2];                                           \
        _Pragma("unroll")                                                      \
        for (int i = 0; i < 4; i++)                                            \
            ldsm_x4(ah[i], aoff + (BOFS) + i * 2048 + kq);                     \
        _Pragma("unroll")                                                      \
        for (int jp = 0; jp < 4; jp++) {                                       \
            uint32_t th[4];                                                    \
            ldsm_x4(th, boff + (BOFS) + jp * 2048 + kq);                       \
            bh[jp * 2][0] = th[0]; bh[jp * 2 + 1][0] = th[1];                  \
            bh[jp * 2][1] = th[2]; bh[jp * 2 + 1][1] = th[3];                  \
        }                                                                      \
        _Pragma("unroll")                                                      \
        for (int i = 0; i < 4; i++)                                            \
            _Pragma("unroll")                                                  \
            for (int j = 0; j < 8; j++)                                        \
                mma_f16(acc[i][j], ah[i], bh[j]);                              \
    }                                                                          \
} while (0)

    STAGE2(sb);

    #pragma unroll 1
    for (int kt = 0; kt < KT; kt += 2) {
        asm volatile("cp.async.wait_group 0;");
        __syncthreads();
        if (kt + 1 < KT) STAGE2(sb + BUFB);
        KTILE(0u);

        asm volatile("cp.async.wait_group 0;");
        __syncthreads();
        if (kt + 2 < KT) STAGE2(sb);
        KTILE((uint32_t)BUFB);
    }
#undef STAGE2
#undef KTILE

    // epilogue
    #pragma unroll
    for (int i = 0; i < 4; i++) {
        const int row0e = m0 + wm * 64 + i * 16 + g;
        #pragma unroll
        for (int j = 0; j < 8; j++) {
            const int col = n0 + wn * 64 + j * 8 + 2 * tig;
            const float2 bv = *(const float2*)(bias + col);
            float2 v0 = { acc[i][j][0] + bv.x, acc[i][j][1] + bv.y };
            float2 v1 = { acc[i][j][2] + bv.x, acc[i][j][3] + bv.y };
            if (RELU) {
                v0.x = fmaxf(v0.x, 0.f); v0.y = fmaxf(v0.y, 0.f);
                v1.x = fmaxf(v1.x, 0.f); v1.y = fmaxf(v1.y, 0.f);
            }
            if (HALF_OUT) {
                *(__half2*)(Yh + (size_t)row0e * N + col) = __floats2half2_rn(v0.x, v0.y);
                *(__half2*)(Yh + (size_t)(row0e + 8) * N + col) = __floats2half2_rn(v1.x, v1.y);
            } else {
                *(float2*)(Yf + (size_t)row0e * N + col) = v0;
                *(float2*)(Yf + (size_t)(row0e + 8) * N + col) = v1;
            }
        }
    }
}

// ---------------------------------------------------------------------------
// Tensor-core log-sparse attention (unchanged from R13).
// ---------------------------------------------------------------------------
#define ATT_QS  0
#define ATT_KS  4096
#define ATT_VS  20480
#define ATT_PS  36864
#define ATT_OEX 45056
#define ATT_MX4 53248
#define ATT_SM4 53760
#define ATT_EXM 54272
#define ATT_EXS 54400
#define ATT_EXP 54528
#define ATT_SMEM 55040

__global__ __launch_bounds__(256, 3)
void attn_mma(const float* __restrict__ qkv, __half* __restrict__ oh) {
    extern __shared__ __align__(1024) char smc[];
    const uint32_t sb = (uint32_t)__cvta_generic_to_shared(smc);

    const int q0 = blockIdx.x * 32;
    const int h = blockIdx.y, b = blockIdx.z;
    const int tid = threadIdx.x, lane = tid & 31, warp = tid >> 5;
    const int wq = warp & 1, wk = warp >> 1;
    const int g = lane >> 2, tig = lane & 3, lrow = lane & 15;

    const float* base = qkv + (size_t)(b * SEQ) * 1536;

    for (int e = tid; e < 512; e += 256) {
        const int row = e >> 4, c4 = (e & 15) << 2;
        const float4 v = *(const float4*)(base + (size_t)(q0 + row) * 1536 + h * 64 + c4);
        char* p = smc + ATT_QS + SWZ((uint32_t)(row * 128 + c4 * 2));
        *(__half2*)p       = __floats2half2_rn(v.x, v.y);
        *(__half2*)(p + 4) = __floats2half2_rn(v.z, v.w);
    }
    for (int e = tid; e < 2048; e += 256) {
        const int r = e >> 4, c4 = (e & 15) << 2;
        const int j = q0 - 64 + r;
        float4 kv = {0.f, 0.f, 0.f, 0.f}, vv = {0.f, 0.f, 0.f, 0.f};
        if (j >= 0 && r < 96) {
            kv = *(const float4*)(base + (size_t)j * 1536 + 512 + h * 64 + c4);
            vv = *(const float4*)(base + (size_t)j * 1536 + 1024 + h * 64 + c4);
        }
        const uint32_t so = SWZ((uint32_t)(r * 128 + c4 * 2));
        char* pk = smc + ATT_KS + so;
        *(__half2*)pk       = __floats2half2_rn(kv.x, kv.y);
        *(__half2*)(pk + 4) = __floats2half2_rn(kv.z, kv.w);
        char* pv = smc + ATT_VS + so;
        *(__half2*)pv       = __floats2half2_rn(vv.x, vv.y);
        *(__half2*)(pv + 4) = __floats2half2_rn(vv.z, vv.w);
    }

    {
        float* EXM = (float*)(smc + ATT_EXM);
        float* EXPS = (float*)(smc + ATT_EXP);
        const int te = lane >> 3, g8 = lane & 7;
        #pragma unroll
        for (int c = 0; c < 4; c++) {
            const int qi = warp * 4 + c;
            const int i = q0 + qi;
            const int ne = (i >= 128) + (i >= 256) + (i >= 512) + (i >= 1024);
            float pt = 0.f;
            if (te < ne) {
                const int j = i - (128 << te);
                const float* kp = base + (size_t)j * 1536 + 512 + h * 64 + g8 * 8;
                const float* qp = base + (size_t)i * 1536 + h * 64 + g8 * 8;
                const float4 ka = *(const float4*)kp;
                const float4 kb = *(const float4*)(kp + 4);
                const float4 qa = *(const float4*)qp;
                const float4 qb = *(const float4*)(qp + 4);
                pt = qa.x * ka.x + qa.y * ka.y + qa.z * ka.z + qa.w * ka.w
                   + qb.x * kb.x + qb.y * kb.y + qb.z * kb.z + qb.w * kb.w;
            }
            pt += __shfl_xor_sync(~0u, pt, 1);
            pt += __shfl_xor_sync(~0u, pt, 2);
            pt += __shfl_xor_sync(~0u, pt, 4);
            pt *= 0.125f;
            const float p0 = __shfl_sync(~0u, pt, 0);
            const float p1 = __shfl_sync(~0u, pt, 8);
            const float p2 = __shfl_sync(~0u, pt, 16);
            const float p3 = __shfl_sync(~0u, pt, 24);
            float mex = -INFINITY;
            if (ne > 0) mex = p0;
            if (ne > 1) mex = fmaxf(mex, p1);
            if (ne > 2) mex = fmaxf(mex, p2);
            if (ne > 3) mex = fmaxf(mex, p3);
            if (lane == 0) {
                EXM[qi] = mex;
                EXPS[qi * 4 + 0] = p0; EXPS[qi * 4 + 1] = p1;
                EXPS[qi * 4 + 2] = p2; EXPS[qi * 4 + 3] = p3;
            }
        }
    }
    __syncthreads();

    float S[4][4] = {};
    const uint32_t kbase = ((uint32_t)((lane >> 4) << 4)) ^ ((uint32_t)((lrow & 7) << 4));
    {
        const uint32_t qa = sb + ATT_QS + (uint32_t)((wq * 16 + lrow) * 128);
        const uint32_t kb = sb + ATT_KS + (uint32_t)((wk * 32 + lrow) * 128);
        #pragma unroll
        for (int ks = 0; ks < 4; ks++) {
            const uint32_t kq = ((uint32_t)(ks * 32)) ^ kbase;
            uint32_t A[4], th[4], B[4][2];
            ldsm_x4(A, qa + kq);
            ldsm_x4(th, kb + kq);
            B[0][0] = th[0]; B[1][0] = th[1]; B[0][1] = th[2]; B[1][1] = th[3];
            ldsm_x4(th, kb + 2048 + kq);
            B[2][0] = th[0]; B[3][0] = th[1]; B[2][1] = th[2]; B[3][1] = th[3];
            #pragma unroll
            for (int j = 0; j < 4; j++) mma_f16(S[j], A, B[j]);
        }
    }

    const int r0 = wq * 16 + g, r1 = r0 + 8;
    const int cmin = 64 - q0;
    float m0 = -INFINITY, m1 = -INFINITY;
    #pragma unroll
    for (int j = 0; j < 4; j++) {
        const int col0 = wk * 32 + j * 8 + 2 * tig;
        const int col1 = col0 + 1;
        S[j][0] = (col0 >= r0 && col0 <= r0 + 64 && col0 >= cmin) ? S[j][0] * 0.125f : -INFINITY;
        S[j][1] = (col1 >= r0 && col1 <= r0 + 64 && col1 >= cmin) ? S[j][1] * 0.125f : -INFINITY;
        S[j][2] = (col0 >= r1 && col0 <= r1 + 64 && col0 >= cmin) ? S[j][2] * 0.125f : -INFINITY;
        S[j][3] = (col1 >= r1 && col1 <= r1 + 64 && col1 >= cmin) ? S[j][3] * 0.125f : -INFINITY;
        m0 = fmaxf(m0, fmaxf(S[j][0], S[j][1]));
        m1 = fmaxf(m1, fmaxf(S[j][2], S[j][3]));
    }
    m0 = fmaxf(m0, __shfl_xor_sync(~0u, m0, 1)); m0 = fmaxf(m0, __shfl_xor_sync(~0u, m0, 2));
    m1 = fmaxf(m1, __shfl_xor_sync(~0u, m1, 1)); m1 = fmaxf(m1, __shfl_xor_sync(~0u, m1, 2));
    {
        float* MX4 = (float*)(smc + ATT_MX4);
        if (tig == 0) { MX4[r0 * 4 + wk] = m0; MX4[r1 * 4 + wk] = m1; }
    }
    __syncthreads();

    {
        float* MX4 = (float*)(smc + ATT_MX4);
        float* SM4 = (float*)(smc + ATT_SM4);
        float* EXM = (float*)(smc + ATT_EXM);
        const float mxf0 = fmaxf(fmaxf(fmaxf(MX4[r0 * 4], MX4[r0 * 4 + 1]),
                                       fmaxf(MX4[r0 * 4 + 2], MX4[r0 * 4 + 3])), EXM[r0]);
        const float mxf1 = fmaxf(fmaxf(fmaxf(MX4[r1 * 4], MX4[r1 * 4 + 1]),
                                       fmaxf(MX4[r1 * 4 + 2], MX4[r1 * 4 + 3])), EXM[r1]);
        float s0 = 0.f, s1 = 0.f;
        #pragma unroll
        for (int j = 0; j < 4; j++) {
            const float e0 = __expf(S[j][0] - mxf0), e1 = __expf(S[j][1] - mxf0);
            const float e2 = __expf(S[j][2] - mxf1), e3 = __expf(S[j][3] - mxf1);
            s0 += e0 + e1; s1 += e2 + e3;
            const int col0 = wk * 32 + j * 8 + 2 * tig;
            char* ps = smc + ATT_PS + (col0 >> 6) * 4096;
            const int kc2 = (col0 & 63) * 2;
            *(__half2*)(ps + SWZ((uint32_t)(r0 * 128 + kc2))) = __floats2half2_rn(e0, e1);
            *(__half2*)(ps + SWZ((uint32_t)(r1 * 128 + kc2))) = __floats2half2_rn(e2, e3);
        }
        s0 += __shfl_xor_sync(~0u, s0, 1); s0 += __shfl_xor_sync(~0u, s0, 2);
        s1 += __shfl_xor_sync(~0u, s1, 1); s1 += __shfl_xor_sync(~0u, s1, 2);
        if (tig == 0) { SM4[r0 * 4 + wk] = s0; SM4[r1 * 4 + wk] = s1; }

        float* EXS = (float*)(smc + ATT_EXS);
        float* EXPS = (float*)(smc + ATT_EXP);
        #pragma unroll
        for (int c = 0; c < 4; c++) {
            const int qi = warp * 4 + c;
            const int i = q0 + qi;
            const int ne = (i >= 128) + (i >= 256) + (i >= 512) + (i >= 1024);
            const float mxfq = fmaxf(fmaxf(fmaxf(MX4[qi * 4], MX4[qi * 4 + 1]),
                                           fmaxf(MX4[qi * 4 + 2], MX4[qi * 4 + 3])), EXM[qi]);
            float e = 0.f;
            if (lane < 4) {
                e = (lane < ne) ? __expf(EXPS[qi * 4 + lane] - mxfq) : 0.f;
                EXPS[qi * 4 + lane] = e;
            }
            e += __shfl_xor_sync(~0u, e, 1);
            e += __shfl_xor_sync(~0u, e, 2);
            if (lane == 0) EXS[qi] = e;
        }
    }
    __syncthreads();

    {
        float* OEX = (float*)(smc + ATT_OEX);
        float* EXPS = (float*)(smc + ATT_EXP);
        #pragma unroll
        for (int c = 0; c < 4; c++) {
            const int qi = warp * 4 + c;
            const int i = q0 + qi;
            const int ne = (i >= 128) + (i >= 256) + (i >= 512) + (i >= 1024);
            float2 a = {0.f, 0.f};
            #pragma unroll
            for (int t = 0; t < 4; t++) {
                if (t < ne) {
                    const int j = i - (128 << t);
                    const float2 vf = *(const float2*)(base + (size_t)j * 1536 + 1024 + h * 64 + 2 * lane);
                    const float wgt = EXPS[qi * 4 + t];
                    a.x += wgt * vf.x;
                    a.y += wgt * vf.y;
                }
            }
            *(float2*)(OEX + qi * 64 + 2 * lane) = a;
        }
    }
    float O[2][4] = {};
    {
        const uint32_t pa = sb + ATT_PS + (uint32_t)((wq * 16 + lrow) * 128);
        const uint32_t vb = sb + ATT_VS + (uint32_t)(lrow * 128);
        const uint32_t vdim = ((uint32_t)(wk * 32 + ((lane >> 4) << 4)))
                            ^ ((uint32_t)((lrow & 7) << 4));
        #pragma unroll
        for (int ks = 0; ks < 8; ks++) {
            uint32_t A[4], th[4];
            const uint32_t kq = ((uint32_t)((ks & 3) * 32)) ^ kbase;
            ldsm_x4(A, pa + (ks >> 2) * 4096 + kq);
            ldsm_x4_t(th, vb + ks * 2048 + vdim);
            uint32_t B0[2] = { th[0], th[1] };
            uint32_t B1[2] = { th[2], th[3] };
            mma_f16(O[0], A, B0);
            mma_f16(O[1], A, B1);
        }
    }
    __syncthreads();

    {
        float* SM4 = (float*)(smc + ATT_SM4);
        float* EXS = (float*)(smc + ATT_EXS);
        float* OEX = (float*)(smc + ATT_OEX);
        const float inv0 = 1.f / (SM4[r0 * 4] + SM4[r0 * 4 + 1] + SM4[r0 * 4 + 2] +
                                  SM4[r0 * 4 + 3] + EXS[r0]);
        const float inv1 = 1.f / (SM4[r1 * 4] + SM4[r1 * 4 + 1] + SM4[r1 * 4 + 2] +
                                  SM4[r1 * 4 + 3] + EXS[r1]);
        #pragma unroll
        for (int j = 0; j < 2; j++) {
            const int col0 = wk * 16 + j * 8 + 2 * tig;
            const float2 ex0 = *(const float2*)(OEX + r0 * 64 + col0);
            const float2 ex1 = *(const float2*)(OEX + r1 * 64 + col0);
            const __half2 h0 = __floats2half2_rn((O[j][0] + ex0.x) * inv0,
                                                 (O[j][1] + ex0.y) * inv0);
            const __half2 h1 = __floats2half2_rn((O[j][2] + ex1.x) * inv1,
                                                 (O[j][3] + ex1.y) * inv1);
            *(__half2*)(oh + (size_t)(b * SEQ + q0 + r0) * DM + h * 64 + col0) = h0;
            *(__half2*)(oh + (size_t)(b * SEQ + q0 + r1) * DM + h * 64 + col0) = h1;
        }
    }
}

// ---------------------------------------------------------------------------
// x = LayerNorm(x + d) * scale + bias; emits fp16 copy. 128 thr, float4.
// ---------------------------------------------------------------------------
__global__ __launch_bounds__(128)
void add_ln_kernel(float* __restrict__ x, const float* __restrict__ o,
                   const float* __restrict__ sc, const float* __restrict__ bi,
                   __half* __restrict__ xh) {
    const int row = blockIdx.x;
    const int t = threadIdx.x;
    const long base = (long)row * DM + 4 * t;

    const float4 xv = *(const float4*)(x + base);
    const float4 ov = *(const float4*)(o + base);
    const float v0 = xv.x + ov.x, v1 = xv.y + ov.y;
    const float v2 = xv.z + ov.z, v3 = xv.w + ov.w;
    float s = v0 + v1 + v2 + v3;
    float sq = v0 * v0 + v1 * v1 + v2 * v2 + v3 * v3;
    #pragma unroll
    for (int off = 16; off; off >>= 1) {
        s  += __shfl_xor_sync(0xffffffffu, s, off);
        sq += __shfl_xor_sync(0xffffffffu, sq, off);
    }
    __shared__ float ss[4], sqs[4];
    __shared__ float mean_s, rstd_s;
    const int w = t >> 5;
    if ((t & 31) == 0) { ss[w] = s; sqs[w] = sq; }
    __syncthreads();
    if (t == 0) {
        const float s1 = ss[0] + ss[1] + ss[2] + ss[3];
        const float s2 = sqs[0] + sqs[1] + sqs[2] + sqs[3];
        const float m = s1 / (float)DM;
        mean_s = m;
        rstd_s = rsqrtf(s2 / (float)DM - m * m + 1e-5f);
    }
    __syncthreads();
    const float m = mean_s, r = rstd_s;
    const float4 scv = *(const float4*)(sc + 4 * t);
    const float4 biv = *(const float4*)(bi + 4 * t);
    float4 y;
    y.x = (v0 - m) * r * scv.x + biv.x;
    y.y = (v1 - m) * r * scv.y + biv.y;
    y.z = (v2 - m) * r * scv.z + biv.z;
    y.w = (v3 - m) * r * scv.w + biv.w;
    *(float4*)(x + base) = y;
    *(__half2*)(xh + base)     = __floats2half2_rn(y.x, y.y);
    *(__half2*)(xh + base + 2) = __floats2half2_rn(y.z, y.w);
}

// ---------------------------------------------------------------------------
extern "C" void kernel_launch(void* const* d_in, const int* in_sizes, int n_in,
                              void* d_out, int out_size) {
    const float* src   = (const float*)d_in[0];
    const float* qkv_w = (const float*)d_in[2];
    const float* qkv_b = (const float*)d_in[3];
    const float* out_w = (const float*)d_in[4];
    const float* out_b = (const float*)d_in[5];
    const float* ln1_s = (const float*)d_in[6];
    const float* ln1_b = (const float*)d_in[7];
    const float* w1    = (const float*)d_in[8];
    const float* b1    = (const float*)d_in[9];
    const float* w2    = (const float*)d_in[10];
    const float* b2    = (const float*)d_in[11];
    const float* ln2_s = (const float*)d_in[12];
    const float* ln2_b = (const float*)d_in[13];

    float* x = (float*)d_out;

    float *qkv, *dbuf;
    __half *xh, *oh, *hh, *wh;
    cudaGetSymbolAddress((void**)&qkv, g_qkv);
    cudaGetSymbolAddress((void**)&dbuf, g_d);
    cudaGetSymbolAddress((void**)&xh, g_xh);
    cudaGetSymbolAddress((void**)&oh, g_oh);
    cudaGetSymbolAddress((void**)&hh, g_hh);
    cudaGetSymbolAddress((void**)&wh, g_wh);

    cudaFuncSetAttribute(gemm_tc<0,0,512,1536>, cudaFuncAttributeMaxDynamicSharedMemorySize, SMEMB);
    cudaFuncSetAttribute(gemm_tc<0,0,512,512>,  cudaFuncAttributeMaxDynamicSharedMemorySize, SMEMB);
    cudaFuncSetAttribute(gemm_tc<1,1,512,2048>, cudaFuncAttributeMaxDynamicSharedMemorySize, SMEMB);
    cudaFuncSetAttribute(gemm_tc<0,0,2048,512>, cudaFuncAttributeMaxDynamicSharedMemorySize, SMEMB);
    cudaFuncSetAttribute(attn_mma, cudaFuncAttributeMaxDynamicSharedMemorySize, ATT_SMEM);

    // launch order: #3 is QKV GEMM, #4 (ncu's pick) is attn_mma
    copy_conv<<<(ROWS*DM/4 + 255)/256, 256>>>(src, x, xh, ROWS*DM/4);                  // 1
    conv_all<<<(W_TOTAL/4 + 255)/256, 256>>>(qkv_w, out_w, w1, w2, wh);                // 2

    for (int l = 0; l < 2; l++) {
        gemm_tc<0,0,512,1536><<<dim3(12, 64), 128, SMEMB>>>(                           // 3
            xh, wh + OFF_QKV + (size_t)l*1536*512,
            qkv_b + (size_t)l*1536, qkv, nullptr);

        attn_mma<<<dim3(SEQ/32, NH, BATCH), 256, ATT_SMEM>>>(qkv, oh);                 // 4

        gemm_tc<0,0,512,512><<<dim3(4, 64), 128, SMEMB>>>(
            oh, wh + OFF_OUT + (size_t)l*512*512,
            out_b + (size_t)l*512, dbuf, nullptr);

        add_ln_kernel<<<ROWS, 128>>>(x, dbuf, ln1_s + l*DM, ln1_b + l*DM, xh);

        gemm_tc<1,1,512,2048><<<dim3(16, 64), 128, SMEMB>>>(
            xh, wh + OFF_W1 + (size_t)l*2048*512,
            b1 + (size_t)l*2048, nullptr, hh);

        gemm_tc<0,0,2048,512><<<dim3(4, 64), 128, SMEMB>>>(
            hh, wh + OFF_W2 + (size_t)l*512*2048,
            b2 + (size_t)l*512, dbuf, nullptr);

        add_ln_kernel<<<ROWS, 128>>>(x, dbuf, ln2_s + l*DM, ln2_b + l*DM, xh);
    }
}

// round 15
// speedup vs baseline: 12.8269x; 1.0447x over previous
#include <cuda_runtime.h>
#include <cuda_fp16.h>
#include <math.h>
#include <stdint.h>

#define SEQ 2048
#define DM 512
#define NH 8
#define DH 64
#define DFF 2048
#define BATCH 4
#define ROWS (BATCH * SEQ)   // 8192

// ---------------- device scratch (no allocation allowed) -------------------
__device__ __half g_qkvh[(size_t)ROWS * 3 * DM];   // fp16 qkv (24 MB)
__device__ float g_d[(size_t)ROWS * DM];
__device__ __half g_xh[(size_t)ROWS * DM];
__device__ __half g_oh[(size_t)ROWS * DM];
__device__ __half g_hh[(size_t)ROWS * DFF];
#define W_TOTAL 6291456
__device__ __half g_wh[W_TOTAL];
#define OFF_QKV 0
#define OFF_OUT (2 * 1536 * 512)
#define OFF_W1  (OFF_OUT + 2 * 512 * 512)
#define OFF_W2  (OFF_W1 + 2 * 2048 * 512)

// ---------------------------------------------------------------------------
// helpers
// ---------------------------------------------------------------------------
__device__ __forceinline__ void cp16(uint32_t saddr, const void* g) {
    asm volatile("cp.async.cg.shared.global [%0], [%1], 16;" :: "r"(saddr), "l"(g));
}
__device__ __forceinline__ void cp16z(uint32_t saddr, const void* g, int sz) {
    asm volatile("cp.async.cg.shared.global [%0], [%1], 16, %2;"
                 :: "r"(saddr), "l"(g), "r"(sz));
}
__device__ __forceinline__ void ldsm_x4(uint32_t* r, uint32_t a) {
    asm volatile("ldmatrix.sync.aligned.m8n8.x4.shared.b16 {%0,%1,%2,%3}, [%4];"
                 : "=r"(r[0]), "=r"(r[1]), "=r"(r[2]), "=r"(r[3]) : "r"(a));
}
__device__ __forceinline__ void ldsm_x4_t(uint32_t* r, uint32_t a) {
    asm volatile("ldmatrix.sync.aligned.m8n8.x4.trans.shared.b16 {%0,%1,%2,%3}, [%4];"
                 : "=r"(r[0]), "=r"(r[1]), "=r"(r[2]), "=r"(r[3]) : "r"(a));
}
__device__ __forceinline__ void mma_f16(float* d, const uint32_t* a, const uint32_t* b) {
    asm volatile("mma.sync.aligned.m16n8k16.row.col.f32.f16.f16.f32 "
                 "{%0,%1,%2,%3}, {%4,%5,%6,%7}, {%8,%9}, {%0,%1,%2,%3};"
                 : "+f"(d[0]), "+f"(d[1]), "+f"(d[2]), "+f"(d[3])
                 : "r"(a[0]), "r"(a[1]), "r"(a[2]), "r"(a[3]), "r"(b[0]), "r"(b[1]));
}
#define SWZ(bo) ((bo) ^ (((bo) >> 3) & 0x70))

// ---------------------------------------------------------------------------
// conversion kernels
// ---------------------------------------------------------------------------
__global__ void conv_all(const float* __restrict__ qkv_w, const float* __restrict__ out_w,
                         const float* __restrict__ w1, const float* __restrict__ w2,
                         __half* __restrict__ dst) {
    const int i = blockIdx.x * blockDim.x + threadIdx.x;
    if (i >= W_TOTAL / 4) return;
    const int e = i * 4;
    const float* src;
    int local;
    if (e < OFF_OUT)      { src = qkv_w; local = e; }
    else if (e < OFF_W1)  { src = out_w; local = e - OFF_OUT; }
    else if (e < OFF_W2)  { src = w1;    local = e - OFF_W1; }
    else                  { src = w2;    local = e - OFF_W2; }
    const float4 v = *(const float4*)(src + local);
    ((__half2*)dst)[2 * i]     = __floats2half2_rn(v.x, v.y);
    ((__half2*)dst)[2 * i + 1] = __floats2half2_rn(v.z, v.w);
}

__global__ void copy_conv(const float* __restrict__ src, float* __restrict__ x,
                          __half* __restrict__ xh, int n4) {
    const int i = blockIdx.x * blockDim.x + threadIdx.x;
    if (i >= n4) return;
    const float4 v = ((const float4*)src)[i];
    ((float4*)x)[i] = v;
    ((__half2*)xh)[2 * i]     = __floats2half2_rn(v.x, v.y);
    ((__half2*)xh)[2 * i + 1] = __floats2half2_rn(v.z, v.w);
}

// ---------------------------------------------------------------------------
// GEMM (R14): plain fp16, 128x128 block tile, BK=64, SW128 smem, 128 threads.
// ---------------------------------------------------------------------------
#define PLANEB 16384
#define BUFB (2 * PLANEB)
#define SMEMB (2 * BUFB)

template<int RELU, int HALF_OUT, int K, int N>
__global__ __launch_bounds__(128)
void gemm_tc(const __half* __restrict__ Xh, const __half* __restrict__ Wh,
             const float* __restrict__ bias, float* __restrict__ Yf,
             __half* __restrict__ Yh) {
    extern __shared__ __align__(1024) char smc[];
    const uint32_t sb = (uint32_t)__cvta_generic_to_shared(smc);

    const int tid = threadIdx.x;
    const int lane = tid & 31, warp = tid >> 5;
    const int wm = warp & 1, wn = warp >> 1;
    const int g = lane >> 2, tig = lane & 3;
    const int m0 = blockIdx.y * 128, n0 = blockIdx.x * 128;

    float acc[4][8][4] = {};
    constexpr int KT = K >> 6;

    const int row0 = tid >> 3, ch = tid & 7;
    const __half* gp0 = Xh + (size_t)(m0 + row0) * K + ch * 8;
    const __half* gp1 = Wh + (size_t)(n0 + row0) * K + ch * 8;
    const uint32_t srow = SWZ((uint32_t)(row0 * 128 + ch * 16));

    const int lrow = lane & 15;
    const uint32_t kbase = ((uint32_t)((lane >> 4) << 4)) ^ ((uint32_t)((lrow & 7) << 4));
    const uint32_t aoff = sb + (uint32_t)((wm * 64 + lrow) * 128);
    const uint32_t boff = sb + (uint32_t)((wn * 64 + lrow) * 128) + (uint32_t)PLANEB;

#define STAGE2(SBUF) do {                                                      \
    _Pragma("unroll")                                                          \
    for (int r_ = 0; r_ < 8; r_++) {                                           \
        cp16((SBUF) + srow + r_ * 2048,          gp0 + r_ * 16 * K);           \
        cp16((SBUF) + PLANEB + srow + r_ * 2048, gp1 + r_ * 16 * K);           \
    }                                                                          \
    asm volatile("cp.async.commit_group;");                                    \
    gp0 += 64; gp1 += 64;                                                      \
} while (0)

#define KTILE(BOFS) do {                                                       \
    _Pragma("unroll")                                                          \
    for (int ks = 0; ks < 4; ks++) {                                           \
        const uint32_t kq = ((uint32_t)(ks * 32)) ^ kbase;                     \
        uint32_t ah[4][4], bh[8][2];                                           \
        _Pragma("unroll")                                                      \
        for (int i = 0; i < 4; i++)                                            \
            ldsm_x4(ah[i], aoff + (BOFS) + i * 2048 + kq);                     \
        _Pragma("unroll")                                                      \
        for (int jp = 0; jp < 4; jp++) {                                       \
            uint32_t th[4];                                                    \
            ldsm_x4(th, boff + (BOFS) + jp * 2048 + kq);                       \
            bh[jp * 2][0] = th[0]; bh[jp * 2 + 1][0] = th[1];                  \
            bh[jp * 2][1] = th[2]; bh[jp * 2 + 1][1] = th[3];                  \
        }                                                                      \
        _Pragma("unroll")                                                      \
        for (int i = 0; i < 4; i++)                                            \
            _Pragma("unroll")                                                  \
            for (int j = 0; j < 8; j++)                                        \
                mma_f16(acc[i][j], ah[i], bh[j]);                              \
    }                                                                          \
} while (0)

    STAGE2(sb);

    #pragma unroll 1
    for (int kt = 0; kt < KT; kt += 2) {
        asm volatile("cp.async.wait_group 0;");
        __syncthreads();
        if (kt + 1 < KT) STAGE2(sb + BUFB);
        KTILE(0u);

        asm volatile("cp.async.wait_group 0;");
        __syncthreads();
        if (kt + 2 < KT) STAGE2(sb);
        KTILE((uint32_t)BUFB);
    }
#undef STAGE2
#undef KTILE

    #pragma unroll
    for (int i = 0; i < 4; i++) {
        const int row0e = m0 + wm * 64 + i * 16 + g;
        #pragma unroll
        for (int j = 0; j < 8; j++) {
            const int col = n0 + wn * 64 + j * 8 + 2 * tig;
            const float2 bv = *(const float2*)(bias + col);
            float2 v0 = { acc[i][j][0] + bv.x, acc[i][j][1] + bv.y };
            float2 v1 = { acc[i][j][2] + bv.x, acc[i][j][3] + bv.y };
            if (RELU) {
                v0.x = fmaxf(v0.x, 0.f); v0.y = fmaxf(v0.y, 0.f);
                v1.x = fmaxf(v1.x, 0.f); v1.y = fmaxf(v1.y, 0.f);
            }
            if (HALF_OUT) {
                *(__half2*)(Yh + (size_t)row0e * N + col) = __floats2half2_rn(v0.x, v0.y);
                *(__half2*)(Yh + (size_t)(row0e + 8) * N + col) = __floats2half2_rn(v1.x, v1.y);
            } else {
                *(float2*)(Yf + (size_t)row0e * N + col) = v0;
                *(float2*)(Yf + (size_t)(row0e + 8) * N + col) = v1;
            }
        }
    }
}

// ---------------------------------------------------------------------------
// Tensor-core log-sparse attention v3: fp16 qkv input, cp.async zfill staging.
// ---------------------------------------------------------------------------
#define ATT_QS  0
#define ATT_KS  4096
#define ATT_VS  20480
#define ATT_PS  36864
#define ATT_OEX 45056
#define ATT_MX4 53248
#define ATT_SM4 53760
#define ATT_EXM 54272
#define ATT_EXS 54400
#define ATT_EXP 54528
#define ATT_SMEM 55040

__global__ __launch_bounds__(256, 3)
void attn_mma(const __half* __restrict__ qkv, __half* __restrict__ oh) {
    extern __shared__ __align__(1024) char smc[];
    const uint32_t sb = (uint32_t)__cvta_generic_to_shared(smc);

    const int q0 = blockIdx.x * 32;
    const int h = blockIdx.y, b = blockIdx.z;
    const int tid = threadIdx.x, lane = tid & 31, warp = tid >> 5;
    const int wq = warp & 1, wk = warp >> 1;
    const int g = lane >> 2, tig = lane & 3, lrow = lane & 15;

    const __half* base = qkv + (size_t)(b * SEQ) * 1536;

    // ---- async staging: Q (1 chunk), K (4), V (4) per thread ----
    {
        const int row = tid >> 3, ch = tid & 7;
        // Q [32][64]
        cp16(sb + ATT_QS + SWZ((uint32_t)(row * 128 + ch * 16)),
             base + (size_t)(q0 + row) * 1536 + h * 64 + ch * 8);
        // K and V [128][64], rows 96..127 / j<0 zero-filled
        #pragma unroll
        for (int r_ = 0; r_ < 4; r_++) {
            const int rr = row + r_ * 32;
            const int j = q0 - 64 + rr;
            const int valid = (j >= 0 && rr < 96) ? 16 : 0;
            const size_t jc = (size_t)(valid ? j : 0);
            const uint32_t so = SWZ((uint32_t)(rr * 128 + ch * 16));
            cp16z(sb + ATT_KS + so, base + jc * 1536 + 512 + h * 64 + ch * 8, valid);
            cp16z(sb + ATT_VS + so, base + jc * 1536 + 1024 + h * 64 + ch * 8, valid);
        }
        asm volatile("cp.async.commit_group;");
    }

    // ---- extras raw scores from gmem (overlaps with staging) ----
    {
        float* EXM = (float*)(smc + ATT_EXM);
        float* EXPS = (float*)(smc + ATT_EXP);
        const int te = lane >> 3, g8 = lane & 7;
        #pragma unroll
        for (int c = 0; c < 4; c++) {
            const int qi = warp * 4 + c;
            const int i = q0 + qi;
            const int ne = (i >= 128) + (i >= 256) + (i >= 512) + (i >= 1024);
            float pt = 0.f;
            if (te < ne) {
                const int j = i - (128 << te);
                const uint4 kraw = *(const uint4*)(base + (size_t)j * 1536 + 512 + h * 64 + g8 * 8);
                const uint4 qraw = *(const uint4*)(base + (size_t)i * 1536 + h * 64 + g8 * 8);
                const __half2* k2 = (const __half2*)&kraw;
                const __half2* q2 = (const __half2*)&qraw;
                #pragma unroll
                for (int u = 0; u < 4; u++) {
                    const float2 kf = __half22float2(k2[u]);
                    const float2 qf = __half22float2(q2[u]);
                    pt += qf.x * kf.x + qf.y * kf.y;
                }
            }
            pt += __shfl_xor_sync(~0u, pt, 1);
            pt += __shfl_xor_sync(~0u, pt, 2);
            pt += __shfl_xor_sync(~0u, pt, 4);
            pt *= 0.125f;
            const float p0 = __shfl_sync(~0u, pt, 0);
            const float p1 = __shfl_sync(~0u, pt, 8);
            const float p2 = __shfl_sync(~0u, pt, 16);
            const float p3 = __shfl_sync(~0u, pt, 24);
            float mex = -INFINITY;
            if (ne > 0) mex = p0;
            if (ne > 1) mex = fmaxf(mex, p1);
            if (ne > 2) mex = fmaxf(mex, p2);
            if (ne > 3) mex = fmaxf(mex, p3);
            if (lane == 0) {
                EXM[qi] = mex;
                EXPS[qi * 4 + 0] = p0; EXPS[qi * 4 + 1] = p1;
                EXPS[qi * 4 + 2] = p2; EXPS[qi * 4 + 3] = p3;
            }
        }
    }
    asm volatile("cp.async.wait_group 0;");
    __syncthreads();

    // ---- S = Q @ K^T (window) ----
    float S[4][4] = {};
    const uint32_t kbase = ((uint32_t)((lane >> 4) << 4)) ^ ((uint32_t)((lrow & 7) << 4));
    {
        const uint32_t qa = sb + ATT_QS + (uint32_t)((wq * 16 + lrow) * 128);
        const uint32_t kb = sb + ATT_KS + (uint32_t)((wk * 32 + lrow) * 128);
        #pragma unroll
        for (int ks = 0; ks < 4; ks++) {
            const uint32_t kq = ((uint32_t)(ks * 32)) ^ kbase;
            uint32_t A[4], th[4], B[4][2];
            ldsm_x4(A, qa + kq);
            ldsm_x4(th, kb + kq);
            B[0][0] = th[0]; B[1][0] = th[1]; B[0][1] = th[2]; B[1][1] = th[3];
            ldsm_x4(th, kb + 2048 + kq);
            B[2][0] = th[0]; B[3][0] = th[1]; B[2][1] = th[2]; B[3][1] = th[3];
            #pragma unroll
            for (int j = 0; j < 4; j++) mma_f16(S[j], A, B[j]);
        }
    }

    // ---- mask + scale + partial row max ----
    const int r0 = wq * 16 + g, r1 = r0 + 8;
    const int cmin = 64 - q0;
    float m0 = -INFINITY, m1 = -INFINITY;
    #pragma unroll
    for (int j = 0; j < 4; j++) {
        const int col0 = wk * 32 + j * 8 + 2 * tig;
        const int col1 = col0 + 1;
        S[j][0] = (col0 >= r0 && col0 <= r0 + 64 && col0 >= cmin) ? S[j][0] * 0.125f : -INFINITY;
        S[j][1] = (col1 >= r0 && col1 <= r0 + 64 && col1 >= cmin) ? S[j][1] * 0.125f : -INFINITY;
        S[j][2] = (col0 >= r1 && col0 <= r1 + 64 && col0 >= cmin) ? S[j][2] * 0.125f : -INFINITY;
        S[j][3] = (col1 >= r1 && col1 <= r1 + 64 && col1 >= cmin) ? S[j][3] * 0.125f : -INFINITY;
        m0 = fmaxf(m0, fmaxf(S[j][0], S[j][1]));
        m1 = fmaxf(m1, fmaxf(S[j][2], S[j][3]));
    }
    m0 = fmaxf(m0, __shfl_xor_sync(~0u, m0, 1)); m0 = fmaxf(m0, __shfl_xor_sync(~0u, m0, 2));
    m1 = fmaxf(m1, __shfl_xor_sync(~0u, m1, 1)); m1 = fmaxf(m1, __shfl_xor_sync(~0u, m1, 2));
    {
        float* MX4 = (float*)(smc + ATT_MX4);
        if (tig == 0) { MX4[r0 * 4 + wk] = m0; MX4[r1 * 4 + wk] = m1; }
    }
    __syncthreads();

    // ---- final row max, exp, partial sums, store P; extras exp ----
    {
        float* MX4 = (float*)(smc + ATT_MX4);
        float* SM4 = (float*)(smc + ATT_SM4);
        float* EXM = (float*)(smc + ATT_EXM);
        const float mxf0 = fmaxf(fmaxf(fmaxf(MX4[r0 * 4], MX4[r0 * 4 + 1]),
                                       fmaxf(MX4[r0 * 4 + 2], MX4[r0 * 4 + 3])), EXM[r0]);
        const float mxf1 = fmaxf(fmaxf(fmaxf(MX4[r1 * 4], MX4[r1 * 4 + 1]),
                                       fmaxf(MX4[r1 * 4 + 2], MX4[r1 * 4 + 3])), EXM[r1]);
        float s0 = 0.f, s1 = 0.f;
        #pragma unroll
        for (int j = 0; j < 4; j++) {
            const float e0 = __expf(S[j][0] - mxf0), e1 = __expf(S[j][1] - mxf0);
            const float e2 = __expf(S[j][2] - mxf1), e3 = __expf(S[j][3] - mxf1);
            s0 += e0 + e1; s1 += e2 + e3;
            const int col0 = wk * 32 + j * 8 + 2 * tig;
            char* ps = smc + ATT_PS + (col0 >> 6) * 4096;
            const int kc2 = (col0 & 63) * 2;
            *(__half2*)(ps + SWZ((uint32_t)(r0 * 128 + kc2))) = __floats2half2_rn(e0, e1);
            *(__half2*)(ps + SWZ((uint32_t)(r1 * 128 + kc2))) = __floats2half2_rn(e2, e3);
        }
        s0 += __shfl_xor_sync(~0u, s0, 1); s0 += __shfl_xor_sync(~0u, s0, 2);
        s1 += __shfl_xor_sync(~0u, s1, 1); s1 += __shfl_xor_sync(~0u, s1, 2);
        if (tig == 0) { SM4[r0 * 4 + wk] = s0; SM4[r1 * 4 + wk] = s1; }

        float* EXS = (float*)(smc + ATT_EXS);
        float* EXPS = (float*)(smc + ATT_EXP);
        #pragma unroll
        for (int c = 0; c < 4; c++) {
            const int qi = warp * 4 + c;
            const int i = q0 + qi;
            const int ne = (i >= 128) + (i >= 256) + (i >= 512) + (i >= 1024);
            const float mxfq = fmaxf(fmaxf(fmaxf(MX4[qi * 4], MX4[qi * 4 + 1]),
                                           fmaxf(MX4[qi * 4 + 2], MX4[qi * 4 + 3])), EXM[qi]);
            float e = 0.f;
            if (lane < 4) {
                e = (lane < ne) ? __expf(EXPS[qi * 4 + lane] - mxfq) : 0.f;
                EXPS[qi * 4 + lane] = e;
            }
            e += __shfl_xor_sync(~0u, e, 1);
            e += __shfl_xor_sync(~0u, e, 2);
            if (lane == 0) EXS[qi] = e;
        }
    }
    __syncthreads();

    // ---- extras output Oex ----
    {
        float* OEX = (float*)(smc + ATT_OEX);
        float* EXPS = (float*)(smc + ATT_EXP);
        #pragma unroll
        for (int c = 0; c < 4; c++) {
            const int qi = warp * 4 + c;
            const int i = q0 + qi;
            const int ne = (i >= 128) + (i >= 256) + (i >= 512) + (i >= 1024);
            float2 a = {0.f, 0.f};
            #pragma unroll
            for (int t = 0; t < 4; t++) {
                if (t < ne) {
                    const int j = i - (128 << t);
                    const float2 vf = __half22float2(
                        *(const __half2*)(base + (size_t)j * 1536 + 1024 + h * 64 + 2 * lane));
                    const float wgt = EXPS[qi * 4 + t];
                    a.x += wgt * vf.x;
                    a.y += wgt * vf.y;
                }
            }
            *(float2*)(OEX + qi * 64 + 2 * lane) = a;
        }
    }
    // ---- O = P @ V ----
    float O[2][4] = {};
    {
        const uint32_t pa = sb + ATT_PS + (uint32_t)((wq * 16 + lrow) * 128);
        const uint32_t vb = sb + ATT_VS + (uint32_t)(lrow * 128);
        const uint32_t vdim = ((uint32_t)(wk * 32 + ((lane >> 4) << 4)))
                            ^ ((uint32_t)((lrow & 7) << 4));
        #pragma unroll
        for (int ks = 0; ks < 8; ks++) {
            uint32_t A[4], th[4];
            const uint32_t kq = ((uint32_t)((ks & 3) * 32)) ^ kbase;
            ldsm_x4(A, pa + (ks >> 2) * 4096 + kq);
            ldsm_x4_t(th, vb + ks * 2048 + vdim);
            uint32_t B0[2] = { th[0], th[1] };
            uint32_t B1[2] = { th[2], th[3] };
            mma_f16(O[0], A, B0);
            mma_f16(O[1], A, B1);
        }
    }
    __syncthreads();

    // ---- epilogue ----
    {
        float* SM4 = (float*)(smc + ATT_SM4);
        float* EXS = (float*)(smc + ATT_EXS);
        float* OEX = (float*)(smc + ATT_OEX);
        const float inv0 = 1.f / (SM4[r0 * 4] + SM4[r0 * 4 + 1] + SM4[r0 * 4 + 2] +
                                  SM4[r0 * 4 + 3] + EXS[r0]);
        const float inv1 = 1.f / (SM4[r1 * 4] + SM4[r1 * 4 + 1] + SM4[r1 * 4 + 2] +
                                  SM4[r1 * 4 + 3] + EXS[r1]);
        #pragma unroll
        for (int j = 0; j < 2; j++) {
            const int col0 = wk * 16 + j * 8 + 2 * tig;
            const float2 ex0 = *(const float2*)(OEX + r0 * 64 + col0);
            const float2 ex1 = *(const float2*)(OEX + r1 * 64 + col0);
            const __half2 h0 = __floats2half2_rn((O[j][0] + ex0.x) * inv0,
                                                 (O[j][1] + ex0.y) * inv0);
            const __half2 h1 = __floats2half2_rn((O[j][2] + ex1.x) * inv1,
                                                 (O[j][3] + ex1.y) * inv1);
            *(__half2*)(oh + (size_t)(b * SEQ + q0 + r0) * DM + h * 64 + col0) = h0;
            *(__half2*)(oh + (size_t)(b * SEQ + q0 + r1) * DM + h * 64 + col0) = h1;
        }
    }
}

// ---------------------------------------------------------------------------
// x = LayerNorm(x + d) * scale + bias; emits fp16 copy. 128 thr, float4.
// ---------------------------------------------------------------------------
__global__ __launch_bounds__(128)
void add_ln_kernel(float* __restrict__ x, const float* __restrict__ o,
                   const float* __restrict__ sc, const float* __restrict__ bi,
                   __half* __restrict__ xh) {
    const int row = blockIdx.x;
    const int t = threadIdx.x;
    const long base = (long)row * DM + 4 * t;

    const float4 xv = *(const float4*)(x + base);
    const float4 ov = *(const float4*)(o + base);
    const float v0 = xv.x + ov.x, v1 = xv.y + ov.y;
    const float v2 = xv.z + ov.z, v3 = xv.w + ov.w;
    float s = v0 + v1 + v2 + v3;
    float sq = v0 * v0 + v1 * v1 + v2 * v2 + v3 * v3;
    #pragma unroll
    for (int off = 16; off; off >>= 1) {
        s  += __shfl_xor_sync(0xffffffffu, s, off);
        sq += __shfl_xor_sync(0xffffffffu, sq, off);
    }
    __shared__ float ss[4], sqs[4];
    __shared__ float mean_s, rstd_s;
    const int w = t >> 5;
    if ((t & 31) == 0) { ss[w] = s; sqs[w] = sq; }
    __syncthreads();
    if (t == 0) {
        const float s1 = ss[0] + ss[1] + ss[2] + ss[3];
        const float s2 = sqs[0] + sqs[1] + sqs[2] + sqs[3];
        const float m = s1 / (float)DM;
        mean_s = m;
        rstd_s = rsqrtf(s2 / (float)DM - m * m + 1e-5f);
    }
    __syncthreads();
    const float m = mean_s, r = rstd_s;
    const float4 scv = *(const float4*)(sc + 4 * t);
    const float4 biv = *(const float4*)(bi + 4 * t);
    float4 y;
    y.x = (v0 - m) * r * scv.x + biv.x;
    y.y = (v1 - m) * r * scv.y + biv.y;
    y.z = (v2 - m) * r * scv.z + biv.z;
    y.w = (v3 - m) * r * scv.w + biv.w;
    *(float4*)(x + base) = y;
    *(__half2*)(xh + base)     = __floats2half2_rn(y.x, y.y);
    *(__half2*)(xh + base + 2) = __floats2half2_rn(y.z, y.w);
}

// ---------------------------------------------------------------------------
extern "C" void kernel_launch(void* const* d_in, const int* in_sizes, int n_in,
                              void* d_out, int out_size) {
    const float* src   = (const float*)d_in[0];
    const float* qkv_w = (const float*)d_in[2];
    const float* qkv_b = (const float*)d_in[3];
    const float* out_w = (const float*)d_in[4];
    const float* out_b = (const float*)d_in[5];
    const float* ln1_s = (const float*)d_in[6];
    const float* ln1_b = (const float*)d_in[7];
    const float* w1    = (const float*)d_in[8];
    const float* b1    = (const float*)d_in[9];
    const float* w2    = (const float*)d_in[10];
    const float* b2    = (const float*)d_in[11];
    const float* ln2_s = (const float*)d_in[12];
    const float* ln2_b = (const float*)d_in[13];

    float* x = (float*)d_out;

    float *dbuf;
    __half *qkvh, *xh, *oh, *hh, *wh;
    cudaGetSymbolAddress((void**)&qkvh, g_qkvh);
    cudaGetSymbolAddress((void**)&dbuf, g_d);
    cudaGetSymbolAddress((void**)&xh, g_xh);
    cudaGetSymbolAddress((void**)&oh, g_oh);
    cudaGetSymbolAddress((void**)&hh, g_hh);
    cudaGetSymbolAddress((void**)&wh, g_wh);

    cudaFuncSetAttribute(gemm_tc<0,1,512,1536>, cudaFuncAttributeMaxDynamicSharedMemorySize, SMEMB);
    cudaFuncSetAttribute(gemm_tc<0,0,512,512>,  cudaFuncAttributeMaxDynamicSharedMemorySize, SMEMB);
    cudaFuncSetAttribute(gemm_tc<1,1,512,2048>, cudaFuncAttributeMaxDynamicSharedMemorySize, SMEMB);
    cudaFuncSetAttribute(gemm_tc<0,0,2048,512>, cudaFuncAttributeMaxDynamicSharedMemorySize, SMEMB);
    cudaFuncSetAttribute(attn_mma, cudaFuncAttributeMaxDynamicSharedMemorySize, ATT_SMEM);

    copy_conv<<<(ROWS*DM/4 + 255)/256, 256>>>(src, x, xh, ROWS*DM/4);                  // 1
    conv_all<<<(W_TOTAL/4 + 255)/256, 256>>>(qkv_w, out_w, w1, w2, wh);                // 2

    for (int l = 0; l < 2; l++) {
        // QKV projection -> fp16 qkv
        gemm_tc<0,1,512,1536><<<dim3(12, 64), 128, SMEMB>>>(                           // 3
            xh, wh + OFF_QKV + (size_t)l*1536*512,
            qkv_b + (size_t)l*1536, nullptr, qkvh);

        attn_mma<<<dim3(SEQ/32, NH, BATCH), 256, ATT_SMEM>>>(qkvh, oh);                // 4

        gemm_tc<0,0,512,512><<<dim3(4, 64), 128, SMEMB>>>(
            oh, wh + OFF_OUT + (size_t)l*512*512,
            out_b + (size_t)l*512, dbuf, nullptr);

        add_ln_kernel<<<ROWS, 128>>>(x, dbuf, ln1_s + l*DM, ln1_b + l*DM, xh);

        gemm_tc<1,1,512,2048><<<dim3(16, 64), 128, SMEMB>>>(
            xh, wh + OFF_W1 + (size_t)l*2048*512,
            b1 + (size_t)l*2048, nullptr, hh);

        gemm_tc<0,0,2048,512><<<dim3(4, 64), 128, SMEMB>>>(
            hh, wh + OFF_W2 + (size_t)l*512*2048,
            b2 + (size_t)l*512, dbuf, nullptr);

        add_ln_kernel<<<ROWS, 128>>>(x, dbuf, ln2_s + l*DM, ln2_b + l*DM, xh);
    }
}